// round 6
// baseline (speedup 1.0000x reference)
#include <cuda_runtime.h>
#include <cuda_bf16.h>
#include <cstdint>
#include <math.h>

// ===========================================================================
// BertBiAttention on GB300 (sm_103 ptxas target -> mma.sync HMMA everywhere)
//   B=16, S1=256, S2=512, V_HID=1024, T_HID=768, BI_HID=1024, H=8, D=128
// Round 4: full-HMMA pipeline. QKV GEMM writes bf16 hi/lo [B,H,S,D] directly;
//   scores = 3-pass split HMMA (+scale+mask); softmax emits bf16 hi/lo P;
//   context = 3-pass split HMMA with ldmatrix.trans V; writes fp32 output.
// ===========================================================================

#define BB   16
#define SS1  256
#define SS2  512
#define HH   8
#define DD   128
#define HD   1024
#define C1_ELEMS ((size_t)BB * SS2 * HD)

typedef __nv_bfloat16 bf16;

// ---------------- scratch ----------------
// activation / weight splits
__device__ bf16 g_x1h[4096 * 1024];
__device__ bf16 g_x1l[4096 * 1024];
__device__ bf16 g_x2h[8192 * 768];
__device__ bf16 g_x2l[8192 * 768];
__device__ bf16 g_w1h[3][1024 * 1024];  // transposed [N][K]
__device__ bf16 g_w1l[3][1024 * 1024];
__device__ bf16 g_w2h[3][1024 * 768];
__device__ bf16 g_w2l[3][1024 * 768];
// qkv in [B,H,S,D] bf16 hi/lo
#define QKV1_ELEMS (BB * HH * SS1 * DD)   // 4194304
#define QKV2_ELEMS (BB * HH * SS2 * DD)   // 8388608
__device__ bf16 g_q1h[QKV1_ELEMS]; __device__ bf16 g_q1l[QKV1_ELEMS];
__device__ bf16 g_k1h[QKV1_ELEMS]; __device__ bf16 g_k1l[QKV1_ELEMS];
__device__ bf16 g_v1h[QKV1_ELEMS]; __device__ bf16 g_v1l[QKV1_ELEMS];
__device__ bf16 g_q2h[QKV2_ELEMS]; __device__ bf16 g_q2l[QKV2_ELEMS];
__device__ bf16 g_k2h[QKV2_ELEMS]; __device__ bf16 g_k2l[QKV2_ELEMS];
__device__ bf16 g_v2h[QKV2_ELEMS]; __device__ bf16 g_v2l[QKV2_ELEMS];
// probs
#define P_ELEMS ((size_t)BB * HH * SS2 * SS1)   // 16777216 (same both ways)
__device__ float g_p1[P_ELEMS];
__device__ bf16  g_p1h[P_ELEMS]; __device__ bf16 g_p1l[P_ELEMS];
__device__ float g_p2[P_ELEMS];
__device__ bf16  g_p2h[P_ELEMS]; __device__ bf16 g_p2l[P_ELEMS];

// ---------------- helpers ----------------
__device__ __forceinline__ uint32_t smem_u32(const void* p) {
    uint32_t a;
    asm("{ .reg .u64 t; cvta.to.shared.u64 t, %1; cvt.u32.u64 %0, t; }"
        : "=r"(a) : "l"(p));
    return a;
}
__device__ __forceinline__ void cp16(uint32_t dst, const void* src) {
    asm volatile("cp.async.cg.shared.global [%0], [%1], 16;\n" :: "r"(dst), "l"(src));
}
__device__ __forceinline__ void ldsm_x4(uint32_t& r0, uint32_t& r1,
                                        uint32_t& r2, uint32_t& r3, uint32_t a) {
    asm volatile("ldmatrix.sync.aligned.m8n8.x4.shared.b16 {%0,%1,%2,%3}, [%4];"
                 : "=r"(r0), "=r"(r1), "=r"(r2), "=r"(r3) : "r"(a));
}
__device__ __forceinline__ void ldsm_x4t(uint32_t& r0, uint32_t& r1,
                                         uint32_t& r2, uint32_t& r3, uint32_t a) {
    asm volatile("ldmatrix.sync.aligned.m8n8.x4.trans.shared.b16 {%0,%1,%2,%3}, [%4];"
                 : "=r"(r0), "=r"(r1), "=r"(r2), "=r"(r3) : "r"(a));
}
__device__ __forceinline__ void mma16816(float* c, uint32_t a0, uint32_t a1,
                                         uint32_t a2, uint32_t a3,
                                         uint32_t b0, uint32_t b1) {
    asm volatile(
        "mma.sync.aligned.m16n8k16.row.col.f32.bf16.bf16.f32 "
        "{%0,%1,%2,%3}, {%4,%5,%6,%7}, {%8,%9}, {%0,%1,%2,%3};"
        : "+f"(c[0]), "+f"(c[1]), "+f"(c[2]), "+f"(c[3])
        : "r"(a0), "r"(a1), "r"(a2), "r"(a3), "r"(b0), "r"(b1));
}
__device__ __forceinline__ uint32_t packbf(bf16 a, bf16 b) {
    __nv_bfloat162 t = __halves2bfloat162(a, b);
    return *reinterpret_cast<uint32_t*>(&t);
}

// ---------------- split/convert ----------------
__global__ void xsplit(const float4* __restrict__ x,
                       uint2* __restrict__ h, uint2* __restrict__ l, int n4) {
    int i = blockIdx.x * blockDim.x + threadIdx.x;
    if (i >= n4) return;
    float4 v = x[i];
    bf16 h0 = __float2bfloat16(v.x), h1 = __float2bfloat16(v.y);
    bf16 h2 = __float2bfloat16(v.z), h3 = __float2bfloat16(v.w);
    float r0 = v.x - __bfloat162float(h0), r1 = v.y - __bfloat162float(h1);
    float r2 = v.z - __bfloat162float(h2), r3 = v.w - __bfloat162float(h3);
    uint2 hp, lp;
    hp.x = packbf(h0, h1); hp.y = packbf(h2, h3);
    lp.x = packbf(__float2bfloat16(r0), __float2bfloat16(r1));
    lp.y = packbf(__float2bfloat16(r2), __float2bfloat16(r3));
    h[i] = hp; l[i] = lp;
}

__global__ void wsplit(const float* __restrict__ W,
                       bf16* __restrict__ Wh, bf16* __restrict__ Wl,
                       int K, int N) {
    __shared__ float t[32][33];
    int k0 = blockIdx.y * 32, n0 = blockIdx.x * 32;
    int tx = threadIdx.x, ty = threadIdx.y;
#pragma unroll
    for (int i = 0; i < 4; i++)
        t[ty + i * 8][tx] = W[(size_t)(k0 + ty + i * 8) * N + n0 + tx];
    __syncthreads();
#pragma unroll
    for (int i = 0; i < 4; i++) {
        float v = t[tx][ty + i * 8];
        bf16 h = __float2bfloat16(v);
        float lo = v - __bfloat162float(h);
        size_t o = (size_t)(n0 + ty + i * 8) * K + k0 + tx;
        Wh[o] = h;
        Wl[o] = __float2bfloat16(lo);
    }
}

// ---------------------------------------------------------------------------
// QKV HMMA GEMM: 3-pass split; epilogue writes bf16 hi/lo in [B,H,S,D].
// BM=BN=128, BK=32, 256 threads, 8 warps (2m x 4n), warp tile 64x32.
// ---------------------------------------------------------------------------
struct G3 {
    const bf16* Wh[3];
    const bf16* Wl[3];
    const float* bias[3];
    bf16* outH[3];
    bf16* outL[3];
};

#define PADK 40   // smem row stride in bf16 elems (80 bytes)

__global__ __launch_bounds__(256) void hmma_qkv(
    const bf16* __restrict__ Ah, const bf16* __restrict__ Al,
    G3 g, int M, int K, int S, int sshift) {
    __shared__ __align__(128) bf16 As[2][128 * PADK];
    __shared__ __align__(128) bf16 Bs[2][128 * PADK];

    const int tid = threadIdx.x;
    const int wid = tid >> 5, lane = tid & 31;
    const int wm = wid >> 2, wn = wid & 3;
    const int z = blockIdx.z;
    const int bm = blockIdx.y * 128, bn = blockIdx.x * 128;
    const int nk = K / 32;
    const int C = 3 * nk;

    const bf16* Wh = g.Wh[z];
    const bf16* Wl = g.Wl[z];

    float acc[4][4][4];
#pragma unroll
    for (int i = 0; i < 4; i++)
#pragma unroll
        for (int j = 0; j < 4; j++)
#pragma unroll
            for (int r = 0; r < 4; r++) acc[i][j][r] = 0.f;

    const uint32_t asb = smem_u32(&As[0][0]);
    const uint32_t bsb = smem_u32(&Bs[0][0]);
    const uint32_t stageB = 128 * PADK * 2;

    const int r0 = tid >> 2, s0 = (tid & 3);
    const uint32_t a_lm = (uint32_t)((wm * 64 + (lane & 15)) * (PADK * 2) + (lane >> 4) * 16);
    const uint32_t b_lm = (uint32_t)((wn * 32 + (lane & 15)) * (PADK * 2) + (lane >> 4) * 16);

    auto load_stage = [&](int c, int buf) {
        const int p = c / nk, kc = c - p * nk;
        const bf16* Ap = (p < 2) ? Ah : Al;
        const bf16* Bp = (p == 1) ? Wl : Wh;
        const char* ab = (const char*)(Ap + (size_t)bm * K + kc * 32);
        const char* bb = (const char*)(Bp + (size_t)bn * K + kc * 32);
        const size_t rs = (size_t)K * 2;
        const uint32_t sa = asb + buf * stageB;
        const uint32_t sb2 = bsb + buf * stageB;
#pragma unroll
        for (int u = 0; u < 2; u++) {
            int row = r0 + u * 64;
            uint32_t off = (uint32_t)(row * (PADK * 2) + s0 * 16);
            cp16(sa + off, ab + (size_t)row * rs + s0 * 16);
            cp16(sb2 + off, bb + (size_t)row * rs + s0 * 16);
        }
        asm volatile("cp.async.commit_group;\n");
    };

    load_stage(0, 0);

    for (int c = 0; c < C; ++c) {
        if (c + 1 < C) {
            load_stage(c + 1, (c + 1) & 1);
            asm volatile("cp.async.wait_group 1;\n");
        } else {
            asm volatile("cp.async.wait_group 0;\n");
        }
        __syncthreads();

        const int buf = c & 1;
        const uint32_t sa = asb + buf * stageB + a_lm;
        const uint32_t sb2 = bsb + buf * stageB + b_lm;
#pragma unroll
        for (int kk = 0; kk < 2; kk++) {
            uint32_t a[4][4], bbf[2][4];
#pragma unroll
            for (int i = 0; i < 4; i++)
                ldsm_x4(a[i][0], a[i][1], a[i][2], a[i][3],
                        sa + i * 16 * (PADK * 2) + kk * 32);
#pragma unroll
            for (int j2 = 0; j2 < 2; j2++)
                ldsm_x4(bbf[j2][0], bbf[j2][1], bbf[j2][2], bbf[j2][3],
                        sb2 + j2 * 16 * (PADK * 2) + kk * 32);
#pragma unroll
            for (int i = 0; i < 4; i++)
#pragma unroll
                for (int j = 0; j < 4; j++) {
                    int j2 = j >> 1, jo = j & 1;
                    mma16816(acc[i][j], a[i][0], a[i][1], a[i][2], a[i][3],
                             bbf[j2][jo], bbf[j2][jo + 2]);
                }
        }
        __syncthreads();
    }

    // epilogue: bias add, split to bf16 hi/lo, write [B,H,S,D]
    bf16* outH = g.outH[z];
    bf16* outL = g.outL[z];
    const float* bias = g.bias[z];
#pragma unroll
    for (int i = 0; i < 4; i++) {
#pragma unroll
        for (int j = 0; j < 4; j++) {
            int m = bm + wm * 64 + i * 16 + (lane >> 2);
            int n = bn + wn * 32 + j * 8 + (lane & 3) * 2;
            float b0 = __ldg(bias + n), b1 = __ldg(bias + n + 1);
            int hq = n >> 7, d = n & 127;
#pragma unroll
            for (int r = 0; r < 2; r++) {
                int mm = m + r * 8;
                int bidx = mm >> sshift, s = mm & (S - 1);
                float p0 = acc[i][j][r * 2 + 0] + b0;
                float p1 = acc[i][j][r * 2 + 1] + b1;
                bf16 h0 = __float2bfloat16(p0);
                bf16 h1 = __float2bfloat16(p1);
                float l0 = p0 - __bfloat162float(h0);
                float l1 = p1 - __bfloat162float(h1);
                size_t idx = (((size_t)(bidx * HH + hq)) * S + s) * DD + d;
                *reinterpret_cast<uint32_t*>(outH + idx) = packbf(h0, h1);
                *reinterpret_cast<uint32_t*>(outL + idx) =
                    packbf(__float2bfloat16(l0), __float2bfloat16(l1));
            }
        }
    }
}

// ---------------------------------------------------------------------------
// scores HMMA: S[bh][m][n] = scale * (Q[bh,m,:] . K[bh,n,:]) + mask[b][n]
// 3-pass split over D=128. grid (Sk/128, Sq/128, BH).
// ---------------------------------------------------------------------------
__global__ __launch_bounds__(256) void hmma_scores(
    const bf16* __restrict__ Qh, const bf16* __restrict__ Ql,
    const bf16* __restrict__ Kh, const bf16* __restrict__ Kl,
    const float* __restrict__ mask, float* __restrict__ Sout,
    int Sq, int Sk, float scale) {
    __shared__ __align__(128) bf16 As[2][128 * PADK];
    __shared__ __align__(128) bf16 Bs[2][128 * PADK];

    const int tid = threadIdx.x;
    const int wid = tid >> 5, lane = tid & 31;
    const int wm = wid >> 2, wn = wid & 3;
    const int bh = blockIdx.z, b = bh >> 3;
    const int bm = blockIdx.y * 128, bn = blockIdx.x * 128;
    const int nk = 4;          // D=128 / 32
    const int C = 12;

    float acc[4][4][4];
#pragma unroll
    for (int i = 0; i < 4; i++)
#pragma unroll
        for (int j = 0; j < 4; j++)
#pragma unroll
            for (int r = 0; r < 4; r++) acc[i][j][r] = 0.f;

    const uint32_t asb = smem_u32(&As[0][0]);
    const uint32_t bsb = smem_u32(&Bs[0][0]);
    const uint32_t stageB = 128 * PADK * 2;

    const int r0 = tid >> 2, s0 = (tid & 3);
    const uint32_t a_lm = (uint32_t)((wm * 64 + (lane & 15)) * (PADK * 2) + (lane >> 4) * 16);
    const uint32_t b_lm = (uint32_t)((wn * 32 + (lane & 15)) * (PADK * 2) + (lane >> 4) * 16);

    auto load_stage = [&](int c, int buf) {
        const int p = c / nk, kc = c - p * nk;
        const bf16* Ap = (p < 2) ? Qh : Ql;
        const bf16* Bp = (p == 1) ? Kl : Kh;
        const char* ab = (const char*)(Ap + ((size_t)bh * Sq + bm) * DD + kc * 32);
        const char* bb = (const char*)(Bp + ((size_t)bh * Sk + bn) * DD + kc * 32);
        const size_t rs = DD * 2;
        const uint32_t sa = asb + buf * stageB;
        const uint32_t sb2 = bsb + buf * stageB;
#pragma unroll
        for (int u = 0; u < 2; u++) {
            int row = r0 + u * 64;
            uint32_t off = (uint32_t)(row * (PADK * 2) + s0 * 16);
            cp16(sa + off, ab + (size_t)row * rs + s0 * 16);
            cp16(sb2 + off, bb + (size_t)row * rs + s0 * 16);
        }
        asm volatile("cp.async.commit_group;\n");
    };

    load_stage(0, 0);

    for (int c = 0; c < C; ++c) {
        if (c + 1 < C) {
            load_stage(c + 1, (c + 1) & 1);
            asm volatile("cp.async.wait_group 1;\n");
        } else {
            asm volatile("cp.async.wait_group 0;\n");
        }
        __syncthreads();

        const int buf = c & 1;
        const uint32_t sa = asb + buf * stageB + a_lm;
        const uint32_t sb2 = bsb + buf * stageB + b_lm;
#pragma unroll
        for (int kk = 0; kk < 2; kk++) {
            uint32_t a[4][4], bbf[2][4];
#pragma unroll
            for (int i = 0; i < 4; i++)
                ldsm_x4(a[i][0], a[i][1], a[i][2], a[i][3],
                        sa + i * 16 * (PADK * 2) + kk * 32);
#pragma unroll
            for (int j2 = 0; j2 < 2; j2++)
                ldsm_x4(bbf[j2][0], bbf[j2][1], bbf[j2][2], bbf[j2][3],
                        sb2 + j2 * 16 * (PADK * 2) + kk * 32);
#pragma unroll
            for (int i = 0; i < 4; i++)
#pragma unroll
                for (int j = 0; j < 4; j++) {
                    int j2 = j >> 1, jo = j & 1;
                    mma16816(acc[i][j], a[i][0], a[i][1], a[i][2], a[i][3],
                             bbf[j2][jo], bbf[j2][jo + 2]);
                }
        }
        __syncthreads();
    }

#pragma unroll
    for (int i = 0; i < 4; i++) {
#pragma unroll
        for (int j = 0; j < 4; j++) {
            int m = bm + wm * 64 + i * 16 + (lane >> 2);
            int n = bn + wn * 32 + j * 8 + (lane & 3) * 2;
            float mk0 = __ldg(mask + b * Sk + n);
            float mk1 = __ldg(mask + b * Sk + n + 1);
#pragma unroll
            for (int r = 0; r < 2; r++) {
                int mm = m + r * 8;
                float2 v = make_float2(acc[i][j][r * 2 + 0] * scale + mk0,
                                       acc[i][j][r * 2 + 1] * scale + mk1);
                *reinterpret_cast<float2*>(
                    Sout + ((size_t)bh * Sq + mm) * Sk + n) = v;
            }
        }
    }
}

// ---------------------------------------------------------------------------
// softmax + split to bf16 hi/lo.  warp per row; n in {256,512}.
// ---------------------------------------------------------------------------
__global__ __launch_bounds__(256) void softmax_split(
    const float* __restrict__ S, bf16* __restrict__ Ph, bf16* __restrict__ Pl,
    int rows, int n) {
    int row = (blockIdx.x * blockDim.x + threadIdx.x) >> 5;
    int lane = threadIdx.x & 31;
    if (row >= rows) return;
    const float2* r2 = reinterpret_cast<const float2*>(S + (size_t)row * n);
    const int np = n >> 6;   // float2 chunks per lane (<= 8)

    float v[16];
    float mx = -INFINITY;
#pragma unroll
    for (int c = 0; c < 8; c++) {
        if (c >= np) break;
        float2 t = r2[lane + c * 32];
        v[2 * c] = t.x; v[2 * c + 1] = t.y;
        mx = fmaxf(mx, fmaxf(t.x, t.y));
    }
#pragma unroll
    for (int o = 16; o; o >>= 1) mx = fmaxf(mx, __shfl_xor_sync(0xffffffffu, mx, o));

    float sum = 0.f;
#pragma unroll
    for (int c = 0; c < 8; c++) {
        if (c >= np) break;
        float e0 = __expf(v[2 * c] - mx);
        float e1 = __expf(v[2 * c + 1] - mx);
        v[2 * c] = e0; v[2 * c + 1] = e1;
        sum += e0 + e1;
    }
#pragma unroll
    for (int o = 16; o; o >>= 1) sum += __shfl_xor_sync(0xffffffffu, sum, o);
    float inv = 1.f / sum;

    uint32_t* ph32 = reinterpret_cast<uint32_t*>(Ph + (size_t)row * n);
    uint32_t* pl32 = reinterpret_cast<uint32_t*>(Pl + (size_t)row * n);
#pragma unroll
    for (int c = 0; c < 8; c++) {
        if (c >= np) break;
        float p0 = v[2 * c] * inv, p1 = v[2 * c + 1] * inv;
        bf16 h0 = __float2bfloat16(p0), h1 = __float2bfloat16(p1);
        float l0 = p0 - __bfloat162float(h0), l1 = p1 - __bfloat162float(h1);
        ph32[lane + c * 32] = packbf(h0, h1);
        pl32[lane + c * 32] = packbf(__float2bfloat16(l0), __float2bfloat16(l1));
    }
}

// ---------------------------------------------------------------------------
// context HMMA: O[b,m,h,:] = sum_k P[bh,m,k] * V[bh,k,:]   (3-pass split)
// V consumed from [S,D] row-major via ldmatrix.trans. grid (1, Sq/128, BH).
// ---------------------------------------------------------------------------
#define PADV 136   // V smem row stride in bf16 elems (272 bytes)

__global__ __launch_bounds__(256) void hmma_ctx(
    const bf16* __restrict__ Ph, const bf16* __restrict__ Pl,
    const bf16* __restrict__ Vh, const bf16* __restrict__ Vl,
    float* __restrict__ O, int Sq, int Sk) {
    __shared__ __align__(128) bf16 As[2][128 * PADK];
    __shared__ __align__(128) bf16 Bs[2][32 * PADV];

    const int tid = threadIdx.x;
    const int wid = tid >> 5, lane = tid & 31;
    const int wm = wid >> 2, wn = wid & 3;
    const int bh = blockIdx.z, b = bh >> 3, h = bh & 7;
    const int bm = blockIdx.y * 128;
    const int nk = Sk / 32;
    const int C = 3 * nk;

    float acc[4][4][4];
#pragma unroll
    for (int i = 0; i < 4; i++)
#pragma unroll
        for (int j = 0; j < 4; j++)
#pragma unroll
            for (int r = 0; r < 4; r++) acc[i][j][r] = 0.f;

    const uint32_t asb = smem_u32(&As[0][0]);
    const uint32_t bsb = smem_u32(&Bs[0][0]);
    const uint32_t stA = 128 * PADK * 2;
    const uint32_t stB = 32 * PADV * 2;

    const int r0 = tid >> 2, s0 = (tid & 3);
    const uint32_t a_lm = (uint32_t)((wm * 64 + (lane & 15)) * (PADK * 2) + (lane >> 4) * 16);

    auto load_stage = [&](int c, int buf) {
        const int p = c / nk, kc = c - p * nk;
        const bf16* Ap = (p < 2) ? Ph : Pl;
        const bf16* Bp = (p == 1) ? Vl : Vh;
        const char* ab = (const char*)(Ap + ((size_t)bh * Sq + bm) * Sk + kc * 32);
        const char* bb = (const char*)(Bp + ((size_t)bh * Sk + kc * 32) * DD);
        const size_t rsA = (size_t)Sk * 2;
        const uint32_t sa = asb + buf * stA;
        const uint32_t sb2 = bsb + buf * stB;
#pragma unroll
        for (int u = 0; u < 2; u++) {
            int row = r0 + u * 64;
            uint32_t off = (uint32_t)(row * (PADK * 2) + s0 * 16);
            cp16(sa + off, ab + (size_t)row * rsA + s0 * 16);
        }
#pragma unroll
        for (int u = 0; u < 2; u++) {
            int seg = tid + u * 256;
            int row = seg >> 4, col = seg & 15;
            uint32_t off = (uint32_t)(row * (PADV * 2) + col * 16);
            cp16(sb2 + off, bb + (size_t)row * 256 + col * 16);
        }
        asm volatile("cp.async.commit_group;\n");
    };

    load_stage(0, 0);

    for (int c = 0; c < C; ++c) {
        if (c + 1 < C) {
            load_stage(c + 1, (c + 1) & 1);
            asm volatile("cp.async.wait_group 1;\n");
        } else {
            asm volatile("cp.async.wait_group 0;\n");
        }
        __syncthreads();

        const int buf = c & 1;
        const uint32_t sa = asb + buf * stA + a_lm;
        const uint32_t sbbase = bsb + buf * stB;
#pragma unroll
        for (int kk = 0; kk < 2; kk++) {
            uint32_t a[4][4], bbf[2][4];
#pragma unroll
            for (int i = 0; i < 4; i++)
                ldsm_x4(a[i][0], a[i][1], a[i][2], a[i][3],
                        sa + i * 16 * (PADK * 2) + kk * 32);
#pragma unroll
            for (int j2 = 0; j2 < 2; j2++) {
                uint32_t addr = sbbase
                    + (uint32_t)((kk * 16 + (lane & 15)) * (PADV * 2))
                    + (uint32_t)((wn * 32 + j2 * 16) * 2) + (lane >> 4) * 16;
                ldsm_x4t(bbf[j2][0], bbf[j2][1], bbf[j2][2], bbf[j2][3], addr);
            }
#pragma unroll
            for (int i = 0; i < 4; i++)
#pragma unroll
                for (int j = 0; j < 4; j++) {
                    int j2 = j >> 1, jo = j & 1;
                    mma16816(acc[i][j], a[i][0], a[i][1], a[i][2], a[i][3],
                             bbf[j2][jo * 2], bbf[j2][jo * 2 + 1]);
                }
        }
        __syncthreads();
    }

    // epilogue -> O[b, m, h, d] fp32
#pragma unroll
    for (int i = 0; i < 4; i++) {
#pragma unroll
        for (int j = 0; j < 4; j++) {
            int m = bm + wm * 64 + i * 16 + (lane >> 2);
            int d = wn * 32 + j * 8 + (lane & 3) * 2;
#pragma unroll
            for (int r = 0; r < 2; r++) {
                int mm = m + r * 8;
                float2 v = make_float2(acc[i][j][r * 2 + 0], acc[i][j][r * 2 + 1]);
                *reinterpret_cast<float2*>(
                    O + (((size_t)(b * Sq + mm) * HH + h)) * DD + d) = v;
            }
        }
    }
}

// ---------------------------------------------------------------------------
extern "C" void kernel_launch(void* const* d_in, const int* in_sizes, int n_in,
                              void* d_out, int out_size) {
    const float* x1    = (const float*)d_in[0];
    const float* mask1 = (const float*)d_in[1];
    const float* x2    = (const float*)d_in[2];
    const float* mask2 = (const float*)d_in[3];
    const float* W1[3] = {(const float*)d_in[4], (const float*)d_in[6], (const float*)d_in[8]};
    const float* b1[3] = {(const float*)d_in[5], (const float*)d_in[7], (const float*)d_in[9]};
    const float* W2[3] = {(const float*)d_in[10], (const float*)d_in[12], (const float*)d_in[14]};
    const float* b2[3] = {(const float*)d_in[11], (const float*)d_in[13], (const float*)d_in[15]};
    float* out = (float*)d_out;

    bf16 *x1h, *x1l, *x2h, *x2l, *w1h, *w1l, *w2h, *w2l;
    cudaGetSymbolAddress((void**)&x1h, g_x1h);
    cudaGetSymbolAddress((void**)&x1l, g_x1l);
    cudaGetSymbolAddress((void**)&x2h, g_x2h);
    cudaGetSymbolAddress((void**)&x2l, g_x2l);
    cudaGetSymbolAddress((void**)&w1h, g_w1h);
    cudaGetSymbolAddress((void**)&w1l, g_w1l);
    cudaGetSymbolAddress((void**)&w2h, g_w2h);
    cudaGetSymbolAddress((void**)&w2l, g_w2l);

    bf16 *q1h, *q1l, *k1h, *k1l, *v1h, *v1l;
    bf16 *q2h, *q2l, *k2h, *k2l, *v2h, *v2l;
    cudaGetSymbolAddress((void**)&q1h, g_q1h); cudaGetSymbolAddress((void**)&q1l, g_q1l);
    cudaGetSymbolAddress((void**)&k1h, g_k1h); cudaGetSymbolAddress((void**)&k1l, g_k1l);
    cudaGetSymbolAddress((void**)&v1h, g_v1h); cudaGetSymbolAddress((void**)&v1l, g_v1l);
    cudaGetSymbolAddress((void**)&q2h, g_q2h); cudaGetSymbolAddress((void**)&q2l, g_q2l);
    cudaGetSymbolAddress((void**)&k2h, g_k2h); cudaGetSymbolAddress((void**)&k2l, g_k2l);
    cudaGetSymbolAddress((void**)&v2h, g_v2h); cudaGetSymbolAddress((void**)&v2l, g_v2l);

    float *p1, *p2;
    bf16 *p1h, *p1l, *p2h, *p2l;
    cudaGetSymbolAddress((void**)&p1, g_p1);
    cudaGetSymbolAddress((void**)&p1h, g_p1h); cudaGetSymbolAddress((void**)&p1l, g_p1l);
    cudaGetSymbolAddress((void**)&p2, g_p2);
    cudaGetSymbolAddress((void**)&p2h, g_p2h); cudaGetSymbolAddress((void**)&p2l, g_p2l);

    const float scale = 1.0f / sqrtf((float)DD);
    dim3 blk(256);

    // --- splits ---
    {
        int n4 = 4096 * 1024 / 4;
        xsplit<<<n4 / 256, 256>>>((const float4*)x1, (uint2*)x1h, (uint2*)x1l, n4);
    }
    {
        int n4 = 8192 * 768 / 4;
        xsplit<<<n4 / 256, 256>>>((const float4*)x2, (uint2*)x2h, (uint2*)x2l, n4);
    }
    for (int i = 0; i < 3; i++) {
        wsplit<<<dim3(32, 32), dim3(32, 8)>>>(W1[i], w1h + (size_t)i * 1024 * 1024,
                                              w1l + (size_t)i * 1024 * 1024, 1024, 1024);
        wsplit<<<dim3(32, 24), dim3(32, 8)>>>(W2[i], w2h + (size_t)i * 1024 * 768,
                                              w2l + (size_t)i * 1024 * 768, 768, 1024);
    }

    // --- QKV projections -> bf16 hi/lo [B,H,S,D] ---
    {
        G3 g;
        for (int i = 0; i < 3; i++) {
            g.Wh[i] = w1h + (size_t)i * 1024 * 1024;
            g.Wl[i] = w1l + (size_t)i * 1024 * 1024;
            g.bias[i] = b1[i];
        }
        g.outH[0] = q1h; g.outL[0] = q1l;
        g.outH[1] = k1h; g.outL[1] = k1l;
        g.outH[2] = v1h; g.outL[2] = v1l;
        hmma_qkv<<<dim3(8, 32, 3), blk>>>(x1h, x1l, g, BB * SS1, 1024, SS1, 8);
    }
    {
        G3 g;
        for (int i = 0; i < 3; i++) {
            g.Wh[i] = w2h + (size_t)i * 1024 * 768;
            g.Wl[i] = w2l + (size_t)i * 1024 * 768;
            g.bias[i] = b2[i];
        }
        g.outH[0] = q2h; g.outL[0] = q2l;
        g.outH[1] = k2h; g.outL[1] = k2l;
        g.outH[2] = v2h; g.outL[2] = v2l;
        hmma_qkv<<<dim3(8, 64, 3), blk>>>(x2h, x2l, g, BB * SS2, 768, SS2, 9);
    }

    // --- attention 1: q2 over (k1, v1) -> out[0:C1] ---
    hmma_scores<<<dim3(SS1 / 128, SS2 / 128, BB * HH), blk>>>(
        q2h, q2l, k1h, k1l, mask1, p1, SS2, SS1, scale);
    softmax_split<<<(BB * HH * SS2) / 8, blk>>>(p1, p1h, p1l, BB * HH * SS2, SS1);
    hmma_ctx<<<dim3(1, SS2 / 128, BB * HH), blk>>>(p1h, p1l, v1h, v1l, out, SS2, SS1);

    // --- attention 2: q1 over (k2, v2) -> out[C1:] ---
    hmma_scores<<<dim3(SS2 / 128, SS1 / 128, BB * HH), blk>>>(
        q1h, q1l, k2h, k2l, mask2, p2, SS1, SS2, scale);
    softmax_split<<<(BB * HH * SS1) / 8, blk>>>(p2, p2h, p2l, BB * HH * SS1, SS2);
    hmma_ctx<<<dim3(1, SS1 / 128, BB * HH), blk>>>(p2h, p2l, v2h, v2l, out + C1_ELEMS, SS1, SS2);
}

// round 7
// speedup vs baseline: 1.6145x; 1.6145x over previous
#include <cuda_runtime.h>
#include <cuda_bf16.h>
#include <cstdint>
#include <math.h>

// ===========================================================================
// BertBiAttention on GB300 (sm_103 ptxas target -> mma.sync HMMA for QKV)
//   B=16, S1=256, S2=512, V_HID=1024, T_HID=768, BI_HID=1024, H=8, D=128
// Round 7: revert to R3 structure (known good), upgrade fp32 attention GEMMs
//   from 64x64/4x4 to 128x128/8x8 microtiles (proven sgemm skeleton).
//   wsplit fused to one launch; scores kernel sits at launch idx 5 for ncu.
// ===========================================================================

#define BB   16
#define SS1  256
#define SS2  512
#define HH   8
#define DD   128
#define HD   1024
#define C1_ELEMS ((size_t)BB * SS2 * HD)

typedef __nv_bfloat16 bf16;

// ---------------- scratch ----------------
__device__ float g_q1[BB * SS1 * HD];
__device__ float g_k1[BB * SS1 * HD];
__device__ float g_v1[BB * SS1 * HD];
__device__ float g_q2[BB * SS2 * HD];
__device__ float g_k2[BB * SS2 * HD];
__device__ float g_v2[BB * SS2 * HD];
__device__ float g_p1[(size_t)BB * HH * SS2 * SS1];
__device__ float g_p2[(size_t)BB * HH * SS1 * SS2];

__device__ bf16 g_x1h[4096 * 1024];
__device__ bf16 g_x1l[4096 * 1024];
__device__ bf16 g_x2h[8192 * 768];
__device__ bf16 g_x2l[8192 * 768];
__device__ bf16 g_w1h[3][1024 * 1024];  // transposed [N][K]
__device__ bf16 g_w1l[3][1024 * 1024];
__device__ bf16 g_w2h[3][1024 * 768];
__device__ bf16 g_w2l[3][1024 * 768];

// ---------------- helpers ----------------
__device__ __forceinline__ uint32_t smem_u32(const void* p) {
    uint32_t a;
    asm("{ .reg .u64 t; cvta.to.shared.u64 t, %1; cvt.u32.u64 %0, t; }"
        : "=r"(a) : "l"(p));
    return a;
}
__device__ __forceinline__ void cp16(uint32_t dst, const void* src) {
    asm volatile("cp.async.cg.shared.global [%0], [%1], 16;\n" :: "r"(dst), "l"(src));
}
__device__ __forceinline__ void ldsm_x4(uint32_t& r0, uint32_t& r1,
                                        uint32_t& r2, uint32_t& r3, uint32_t a) {
    asm volatile("ldmatrix.sync.aligned.m8n8.x4.shared.b16 {%0,%1,%2,%3}, [%4];"
                 : "=r"(r0), "=r"(r1), "=r"(r2), "=r"(r3) : "r"(a));
}
__device__ __forceinline__ void mma16816(float* c, uint32_t a0, uint32_t a1,
                                         uint32_t a2, uint32_t a3,
                                         uint32_t b0, uint32_t b1) {
    asm volatile(
        "mma.sync.aligned.m16n8k16.row.col.f32.bf16.bf16.f32 "
        "{%0,%1,%2,%3}, {%4,%5,%6,%7}, {%8,%9}, {%0,%1,%2,%3};"
        : "+f"(c[0]), "+f"(c[1]), "+f"(c[2]), "+f"(c[3])
        : "r"(a0), "r"(a1), "r"(a2), "r"(a3), "r"(b0), "r"(b1));
}
__device__ __forceinline__ uint32_t packbf(bf16 a, bf16 b) {
    __nv_bfloat162 t = __halves2bfloat162(a, b);
    return *reinterpret_cast<uint32_t*>(&t);
}

// ---------------- split/convert ----------------
__global__ void xsplit(const float4* __restrict__ x,
                       uint2* __restrict__ h, uint2* __restrict__ l, int n4) {
    int i = blockIdx.x * blockDim.x + threadIdx.x;
    if (i >= n4) return;
    float4 v = x[i];
    bf16 h0 = __float2bfloat16(v.x), h1 = __float2bfloat16(v.y);
    bf16 h2 = __float2bfloat16(v.z), h3 = __float2bfloat16(v.w);
    float r0 = v.x - __bfloat162float(h0), r1 = v.y - __bfloat162float(h1);
    float r2 = v.z - __bfloat162float(h2), r3 = v.w - __bfloat162float(h3);
    uint2 hp, lp;
    hp.x = packbf(h0, h1); hp.y = packbf(h2, h3);
    lp.x = packbf(__float2bfloat16(r0), __float2bfloat16(r1));
    lp.y = packbf(__float2bfloat16(r2), __float2bfloat16(r3));
    h[i] = hp; l[i] = lp;
}

// one launch for all 6 weights: z selects matrix; K varies (1024 or 768)
struct WS {
    const float* W[6];
    bf16* Wh[6];
    bf16* Wl[6];
    int K[6];
};

__global__ void wsplit_all(WS ws) {
    const int z = blockIdx.z;
    const int K = ws.K[z];
    const int N = 1024;
    const int k0 = blockIdx.y * 32, n0 = blockIdx.x * 32;
    if (k0 >= K) return;
    __shared__ float t[32][33];
    const float* W = ws.W[z];
    bf16* Wh = ws.Wh[z];
    bf16* Wl = ws.Wl[z];
    int tx = threadIdx.x, ty = threadIdx.y;
#pragma unroll
    for (int i = 0; i < 4; i++)
        t[ty + i * 8][tx] = W[(size_t)(k0 + ty + i * 8) * N + n0 + tx];
    __syncthreads();
#pragma unroll
    for (int i = 0; i < 4; i++) {
        float v = t[tx][ty + i * 8];
        bf16 h = __float2bfloat16(v);
        float lo = v - __bfloat162float(h);
        size_t o = (size_t)(n0 + ty + i * 8) * K + k0 + tx;
        Wh[o] = h;
        Wl[o] = __float2bfloat16(lo);
    }
}

// ---------------------------------------------------------------------------
// QKV HMMA GEMM (unchanged from round 3 — known good)
// ---------------------------------------------------------------------------
struct G3 {
    const bf16* Wh[3];
    const bf16* Wl[3];
    const float* bias[3];
    float* out[3];
};

#define PADK 40   // smem row stride in bf16 elems (80 bytes)

__global__ __launch_bounds__(256) void hmma_gemm3(
    const bf16* __restrict__ Ah, const bf16* __restrict__ Al,
    G3 g, int M, int K) {
    const int N = 1024;
    __shared__ __align__(128) bf16 As[2][128 * PADK];
    __shared__ __align__(128) bf16 Bs[2][128 * PADK];

    const int tid = threadIdx.x;
    const int wid = tid >> 5, lane = tid & 31;
    const int wm = wid >> 2, wn = wid & 3;
    const int z = blockIdx.z;
    const int bm = blockIdx.y * 128, bn = blockIdx.x * 128;
    const int nk = K / 32;
    const int C = 3 * nk;

    const bf16* Wh = g.Wh[z];
    const bf16* Wl = g.Wl[z];

    float acc[4][4][4];
#pragma unroll
    for (int i = 0; i < 4; i++)
#pragma unroll
        for (int j = 0; j < 4; j++)
#pragma unroll
            for (int r = 0; r < 4; r++) acc[i][j][r] = 0.f;

    const uint32_t asb = smem_u32(&As[0][0]);
    const uint32_t bsb = smem_u32(&Bs[0][0]);
    const uint32_t stageB = 128 * PADK * 2;

    const int r0 = tid >> 2, s0 = (tid & 3);
    const uint32_t a_lm = (uint32_t)((wm * 64 + (lane & 15)) * (PADK * 2) + (lane >> 4) * 16);
    const uint32_t b_lm = (uint32_t)((wn * 32 + (lane & 15)) * (PADK * 2) + (lane >> 4) * 16);

    auto load_stage = [&](int c, int buf) {
        const int p = c / nk, kc = c - p * nk;
        const bf16* Ap = (p < 2) ? Ah : Al;
        const bf16* Bp = (p == 1) ? Wl : Wh;
        const char* ab = (const char*)(Ap + (size_t)bm * K + kc * 32);
        const char* bb = (const char*)(Bp + (size_t)bn * K + kc * 32);
        const size_t rs = (size_t)K * 2;
        const uint32_t sa = asb + buf * stageB;
        const uint32_t sb2 = bsb + buf * stageB;
#pragma unroll
        for (int u = 0; u < 2; u++) {
            int row = r0 + u * 64;
            uint32_t off = (uint32_t)(row * (PADK * 2) + s0 * 16);
            cp16(sa + off, ab + (size_t)row * rs + s0 * 16);
            cp16(sb2 + off, bb + (size_t)row * rs + s0 * 16);
        }
        asm volatile("cp.async.commit_group;\n");
    };

    load_stage(0, 0);

    for (int c = 0; c < C; ++c) {
        if (c + 1 < C) {
            load_stage(c + 1, (c + 1) & 1);
            asm volatile("cp.async.wait_group 1;\n");
        } else {
            asm volatile("cp.async.wait_group 0;\n");
        }
        __syncthreads();

        const int buf = c & 1;
        const uint32_t sa = asb + buf * stageB + a_lm;
        const uint32_t sb2 = bsb + buf * stageB + b_lm;
#pragma unroll
        for (int kk = 0; kk < 2; kk++) {
            uint32_t a[4][4], bbf[2][4];
#pragma unroll
            for (int i = 0; i < 4; i++)
                ldsm_x4(a[i][0], a[i][1], a[i][2], a[i][3],
                        sa + i * 16 * (PADK * 2) + kk * 32);
#pragma unroll
            for (int j2 = 0; j2 < 2; j2++)
                ldsm_x4(bbf[j2][0], bbf[j2][1], bbf[j2][2], bbf[j2][3],
                        sb2 + j2 * 16 * (PADK * 2) + kk * 32);
#pragma unroll
            for (int i = 0; i < 4; i++)
#pragma unroll
                for (int j = 0; j < 4; j++) {
                    int j2 = j >> 1, jo = j & 1;
                    mma16816(acc[i][j], a[i][0], a[i][1], a[i][2], a[i][3],
                             bbf[j2][jo], bbf[j2][jo + 2]);
                }
        }
        __syncthreads();
    }

    float* outp = g.out[z];
    const float* bias = g.bias[z];
#pragma unroll
    for (int i = 0; i < 4; i++) {
#pragma unroll
        for (int j = 0; j < 4; j++) {
            int m = bm + wm * 64 + i * 16 + (lane >> 2);
            int n = bn + wn * 32 + j * 8 + (lane & 3) * 2;
            float b0 = __ldg(bias + n), b1 = __ldg(bias + n + 1);
            float2 v0 = make_float2(acc[i][j][0] + b0, acc[i][j][1] + b1);
            float2 v1 = make_float2(acc[i][j][2] + b0, acc[i][j][3] + b1);
            *reinterpret_cast<float2*>(outp + (size_t)m * N + n) = v0;
            *reinterpret_cast<float2*>(outp + (size_t)(m + 8) * N + n) = v1;
        }
    }
}

// ---------------------------------------------------------------------------
// scores fp32: S[bh][m][n] = scale*(Q[b,m,h,:].K[b,n,h,:]) + mask[b][n]
// 128x128 tile, 8x8 microtile (sgemm skeleton). grid (Sk/128, Sq/128, BH).
// Both Q and K tiles transpose-loaded into [d][row] smem.
// ---------------------------------------------------------------------------
__global__ __launch_bounds__(256, 2) void attn_scores128(
    const float* __restrict__ Q, const float* __restrict__ Km,
    const float* __restrict__ mask, float* __restrict__ S,
    int Sq, int Sk, float scale)
{
    __shared__ float Qs[16][132];
    __shared__ float Ks[16][132];
    const int tid = threadIdx.x;
    const int tx = tid & 15, ty = tid >> 4;
    const int bh = blockIdx.z, b = bh >> 3, h = bh & 7;
    const int bm = blockIdx.y * 128, bn = blockIdx.x * 128;

    const float* Qb = Q + ((size_t)(b * Sq + bm)) * HD + h * DD;
    const float* Kb = Km + ((size_t)(b * Sk + bn)) * HD + h * DD;

    float acc[8][8];
#pragma unroll
    for (int i = 0; i < 8; i++)
#pragma unroll
        for (int j = 0; j < 8; j++) acc[i][j] = 0.f;

    const int av = tid * 2;
    for (int d0 = 0; d0 < DD; d0 += 16) {
#pragma unroll
        for (int u = 0; u < 2; u++) {
            int v = av + u;
            int row = v >> 2;
            int dq = (v & 3) << 2;
            float4 q4 = *reinterpret_cast<const float4*>(Qb + (size_t)row * HD + d0 + dq);
            Qs[dq + 0][row] = q4.x; Qs[dq + 1][row] = q4.y;
            Qs[dq + 2][row] = q4.z; Qs[dq + 3][row] = q4.w;
            float4 k4 = *reinterpret_cast<const float4*>(Kb + (size_t)row * HD + d0 + dq);
            Ks[dq + 0][row] = k4.x; Ks[dq + 1][row] = k4.y;
            Ks[dq + 2][row] = k4.z; Ks[dq + 3][row] = k4.w;
        }
        __syncthreads();
#pragma unroll
        for (int kk = 0; kk < 16; kk++) {
            float a[8], bb2[8];
            float4 t;
            t = *reinterpret_cast<const float4*>(&Qs[kk][ty * 4]);
            a[0] = t.x; a[1] = t.y; a[2] = t.z; a[3] = t.w;
            t = *reinterpret_cast<const float4*>(&Qs[kk][64 + ty * 4]);
            a[4] = t.x; a[5] = t.y; a[6] = t.z; a[7] = t.w;
            t = *reinterpret_cast<const float4*>(&Ks[kk][tx * 4]);
            bb2[0] = t.x; bb2[1] = t.y; bb2[2] = t.z; bb2[3] = t.w;
            t = *reinterpret_cast<const float4*>(&Ks[kk][64 + tx * 4]);
            bb2[4] = t.x; bb2[5] = t.y; bb2[6] = t.z; bb2[7] = t.w;
#pragma unroll
            for (int i = 0; i < 8; i++)
#pragma unroll
                for (int j = 0; j < 8; j++)
                    acc[i][j] = fmaf(a[i], bb2[j], acc[i][j]);
        }
        __syncthreads();
    }

#pragma unroll
    for (int i = 0; i < 8; i++) {
        int m = bm + ((i < 4) ? (ty * 4 + i) : (64 + ty * 4 + i - 4));
#pragma unroll
        for (int jj = 0; jj < 2; jj++) {
            int n = bn + ((jj == 0) ? (tx * 4) : (64 + tx * 4));
            const float* mk = mask + b * Sk + n;
            float4 o;
            o.x = acc[i][jj * 4 + 0] * scale + mk[0];
            o.y = acc[i][jj * 4 + 1] * scale + mk[1];
            o.z = acc[i][jj * 4 + 2] * scale + mk[2];
            o.w = acc[i][jj * 4 + 3] * scale + mk[3];
            *reinterpret_cast<float4*>(S + ((size_t)bh * Sq + m) * Sk + n) = o;
        }
    }
}

// ---------------------------------------------------------------------------
// context fp32: O[b,m,h,:] = sum_n P[bh,m,n] * V[b,n,h,:]
// 128x128 tile, 8x8 microtile. grid (1, Sq/128, BH). K = Sk.
// P transpose-loaded; V direct row-loaded ([n][d] == [K][N] like sgemm W).
// ---------------------------------------------------------------------------
__global__ __launch_bounds__(256, 2) void attn_ctx128(
    const float* __restrict__ P, const float* __restrict__ V,
    float* __restrict__ O, int Sq, int Sk)
{
    __shared__ float Ps[16][132];
    __shared__ float Vs[16][132];
    const int tid = threadIdx.x;
    const int tx = tid & 15, ty = tid >> 4;
    const int bh = blockIdx.z, b = bh >> 3, h = bh & 7;
    const int m0 = blockIdx.y * 128;

    const float* Pb = P + ((size_t)bh * Sq + m0) * Sk;
    const float* Vb = V + (size_t)(b * Sk) * HD + h * DD;

    float acc[8][8];
#pragma unroll
    for (int i = 0; i < 8; i++)
#pragma unroll
        for (int j = 0; j < 8; j++) acc[i][j] = 0.f;

    const int av = tid * 2;
    for (int n0 = 0; n0 < Sk; n0 += 16) {
#pragma unroll
        for (int u = 0; u < 2; u++) {
            int v = av + u;
            int row = v >> 2;
            int nq = (v & 3) << 2;
            float4 p4 = *reinterpret_cast<const float4*>(Pb + (size_t)row * Sk + n0 + nq);
            Ps[nq + 0][row] = p4.x; Ps[nq + 1][row] = p4.y;
            Ps[nq + 2][row] = p4.z; Ps[nq + 3][row] = p4.w;
            int vr = v >> 5;
            int dq = (v & 31) << 2;
            float4 v4 = *reinterpret_cast<const float4*>(
                Vb + (size_t)(n0 + vr) * HD + dq);
            *reinterpret_cast<float4*>(&Vs[vr][dq]) = v4;
        }
        __syncthreads();
#pragma unroll
        for (int kk = 0; kk < 16; kk++) {
            float a[8], bb2[8];
            float4 t;
            t = *reinterpret_cast<const float4*>(&Ps[kk][ty * 4]);
            a[0] = t.x; a[1] = t.y; a[2] = t.z; a[3] = t.w;
            t = *reinterpret_cast<const float4*>(&Ps[kk][64 + ty * 4]);
            a[4] = t.x; a[5] = t.y; a[6] = t.z; a[7] = t.w;
            t = *reinterpret_cast<const float4*>(&Vs[kk][tx * 4]);
            bb2[0] = t.x; bb2[1] = t.y; bb2[2] = t.z; bb2[3] = t.w;
            t = *reinterpret_cast<const float4*>(&Vs[kk][64 + tx * 4]);
            bb2[4] = t.x; bb2[5] = t.y; bb2[6] = t.z; bb2[7] = t.w;
#pragma unroll
            for (int i = 0; i < 8; i++)
#pragma unroll
                for (int j = 0; j < 8; j++)
                    acc[i][j] = fmaf(a[i], bb2[j], acc[i][j]);
        }
        __syncthreads();
    }

#pragma unroll
    for (int i = 0; i < 8; i++) {
        int m = m0 + ((i < 4) ? (ty * 4 + i) : (64 + ty * 4 + i - 4));
        float* orow = O + (size_t)(b * Sq + m) * HD + h * DD;
#pragma unroll
        for (int jj = 0; jj < 2; jj++) {
            int d = (jj == 0) ? (tx * 4) : (64 + tx * 4);
            float4 o = make_float4(acc[i][jj * 4 + 0], acc[i][jj * 4 + 1],
                                   acc[i][jj * 4 + 2], acc[i][jj * 4 + 3]);
            *reinterpret_cast<float4*>(orow + d) = o;
        }
    }
}

// ---------------------------------------------------------------------------
// warp-per-row softmax (unchanged)
// ---------------------------------------------------------------------------
__global__ __launch_bounds__(256) void softmax_rows(
    float* __restrict__ S, int rows, int n) {
    int warp = (blockIdx.x * blockDim.x + threadIdx.x) >> 5;
    int lane = threadIdx.x & 31;
    if (warp >= rows) return;
    float* row = S + (size_t)warp * n;

    float mx = -INFINITY;
    for (int i = lane; i < n; i += 32) mx = fmaxf(mx, row[i]);
#pragma unroll
    for (int o = 16; o; o >>= 1) mx = fmaxf(mx, __shfl_xor_sync(0xffffffffu, mx, o));

    float sum = 0.f;
    for (int i = lane; i < n; i += 32) {
        float e = __expf(row[i] - mx);
        row[i] = e;
        sum += e;
    }
#pragma unroll
    for (int o = 16; o; o >>= 1) sum += __shfl_xor_sync(0xffffffffu, sum, o);
    float inv = 1.f / sum;
    for (int i = lane; i < n; i += 32) row[i] *= inv;
}

// ---------------------------------------------------------------------------
extern "C" void kernel_launch(void* const* d_in, const int* in_sizes, int n_in,
                              void* d_out, int out_size) {
    const float* x1    = (const float*)d_in[0];
    const float* mask1 = (const float*)d_in[1];
    const float* x2    = (const float*)d_in[2];
    const float* mask2 = (const float*)d_in[3];
    const float* W1[3] = {(const float*)d_in[4], (const float*)d_in[6], (const float*)d_in[8]};
    const float* b1[3] = {(const float*)d_in[5], (const float*)d_in[7], (const float*)d_in[9]};
    const float* W2[3] = {(const float*)d_in[10], (const float*)d_in[12], (const float*)d_in[14]};
    const float* b2[3] = {(const float*)d_in[11], (const float*)d_in[13], (const float*)d_in[15]};
    float* out = (float*)d_out;

    float *q1, *k1, *v1, *q2, *k2, *v2, *p1, *p2;
    cudaGetSymbolAddress((void**)&q1, g_q1);
    cudaGetSymbolAddress((void**)&k1, g_k1);
    cudaGetSymbolAddress((void**)&v1, g_v1);
    cudaGetSymbolAddress((void**)&q2, g_q2);
    cudaGetSymbolAddress((void**)&k2, g_k2);
    cudaGetSymbolAddress((void**)&v2, g_v2);
    cudaGetSymbolAddress((void**)&p1, g_p1);
    cudaGetSymbolAddress((void**)&p2, g_p2);

    bf16 *x1h, *x1l, *x2h, *x2l, *w1h, *w1l, *w2h, *w2l;
    cudaGetSymbolAddress((void**)&x1h, g_x1h);
    cudaGetSymbolAddress((void**)&x1l, g_x1l);
    cudaGetSymbolAddress((void**)&x2h, g_x2h);
    cudaGetSymbolAddress((void**)&x2l, g_x2l);
    cudaGetSymbolAddress((void**)&w1h, g_w1h);
    cudaGetSymbolAddress((void**)&w1l, g_w1l);
    cudaGetSymbolAddress((void**)&w2h, g_w2h);
    cudaGetSymbolAddress((void**)&w2l, g_w2l);

    const float scale = 1.0f / sqrtf((float)DD);
    dim3 blk(256);

    // 1-2: activation splits
    {
        int n4 = 4096 * 1024 / 4;
        xsplit<<<n4 / 256, 256>>>((const float4*)x1, (uint2*)x1h, (uint2*)x1l, n4);
    }
    {
        int n4 = 8192 * 768 / 4;
        xsplit<<<n4 / 256, 256>>>((const float4*)x2, (uint2*)x2h, (uint2*)x2l, n4);
    }

    // 3: all weight splits in one launch
    {
        WS ws;
        for (int i = 0; i < 3; i++) {
            ws.W[i] = W1[i];
            ws.Wh[i] = w1h + (size_t)i * 1024 * 1024;
            ws.Wl[i] = w1l + (size_t)i * 1024 * 1024;
            ws.K[i] = 1024;
            ws.W[3 + i] = W2[i];
            ws.Wh[3 + i] = w2h + (size_t)i * 1024 * 768;
            ws.Wl[3 + i] = w2l + (size_t)i * 1024 * 768;
            ws.K[3 + i] = 768;
        }
        wsplit_all<<<dim3(32, 32, 6), dim3(32, 8)>>>(ws);
    }

    // 4-5: QKV projections (HMMA, 3-pass split)
    {
        G3 g;
        for (int i = 0; i < 3; i++) {
            g.Wh[i] = w1h + (size_t)i * 1024 * 1024;
            g.Wl[i] = w1l + (size_t)i * 1024 * 1024;
            g.bias[i] = b1[i];
        }
        g.out[0] = q1; g.out[1] = k1; g.out[2] = v1;
        hmma_gemm3<<<dim3(8, 32, 3), blk>>>(x1h, x1l, g, BB * SS1, 1024);
    }
    {
        G3 g;
        for (int i = 0; i < 3; i++) {
            g.Wh[i] = w2h + (size_t)i * 1024 * 768;
            g.Wl[i] = w2l + (size_t)i * 1024 * 768;
            g.bias[i] = b2[i];
        }
        g.out[0] = q2; g.out[1] = k2; g.out[2] = v2;
        hmma_gemm3<<<dim3(8, 64, 3), blk>>>(x2h, x2l, g, BB * SS2, 768);
    }

    // 6-8: attention 1 (text queries q2 over vision k1/v1) -> out[0:C1]
    attn_scores128<<<dim3(SS1 / 128, SS2 / 128, BB * HH), blk>>>(
        q2, k1, mask1, p1, SS2, SS1, scale);
    softmax_rows<<<(BB * HH * SS2) / 8, blk>>>(p1, BB * HH * SS2, SS1);
    attn_ctx128<<<dim3(1, SS2 / 128, BB * HH), blk>>>(p1, v1, out, SS2, SS1);

    // 9-11: attention 2 (vision queries q1 over text k2/v2) -> out[C1:]
    attn_scores128<<<dim3(SS2 / 128, SS1 / 128, BB * HH), blk>>>(
        q1, k2, mask2, p2, SS1, SS2, scale);
    softmax_rows<<<(BB * HH * SS1) / 8, blk>>>(p2, BB * HH * SS1, SS2);
    attn_ctx128<<<dim3(1, SS1 / 128, BB * HH), blk>>>(p2, v2, out + C1_ELEMS, SS1, SS2);
}

// round 8
// speedup vs baseline: 1.7933x; 1.1108x over previous
#include <cuda_runtime.h>
#include <cuda_bf16.h>
#include <cstdint>
#include <math.h>

// ===========================================================================
// BertBiAttention on GB300 (sm_103 ptxas target -> mma.sync HMMA everywhere)
//   B=16, S1=256, S2=512, V_HID=1024, T_HID=768, BI_HID=1024, H=8, D=128
// Round 8: attention GEMMs ported to the PROVEN hmma_gemm3 skeleton
//   (identical loader/ldsm/mma/epilogue structure; only pointers/strides
//   differ). V pre-transposed to [BH,D,S] so ctx needs no trans-ldmatrix.
//   All GEMMs: bf16 hi/lo split, 3-pass compensation, fp32 accum.
// ===========================================================================

#define BB   16
#define SS1  256
#define SS2  512
#define HH   8
#define DD   128
#define HD   1024
#define C1_ELEMS ((size_t)BB * SS2 * HD)

typedef __nv_bfloat16 bf16;

// ---------------- scratch ----------------
__device__ float g_q1[BB * SS1 * HD];
__device__ float g_k1[BB * SS1 * HD];
__device__ float g_v1[BB * SS1 * HD];
__device__ float g_q2[BB * SS2 * HD];
__device__ float g_k2[BB * SS2 * HD];
__device__ float g_v2[BB * SS2 * HD];
__device__ float g_p1[(size_t)BB * HH * SS2 * SS1];
__device__ float g_p2[(size_t)BB * HH * SS1 * SS2];

__device__ bf16 g_x1h[4096 * 1024];
__device__ bf16 g_x1l[4096 * 1024];
__device__ bf16 g_x2h[8192 * 768];
__device__ bf16 g_x2l[8192 * 768];
__device__ bf16 g_w1h[3][1024 * 1024];  // transposed [N][K]
__device__ bf16 g_w1l[3][1024 * 1024];
__device__ bf16 g_w2h[3][1024 * 768];
__device__ bf16 g_w2l[3][1024 * 768];

// bf16 splits of q/k (same [B,S,H,D] layout) and V transposed [B,H,D,S]
__device__ bf16 g_q1h[BB * SS1 * HD]; __device__ bf16 g_q1l[BB * SS1 * HD];
__device__ bf16 g_k1h[BB * SS1 * HD]; __device__ bf16 g_k1l[BB * SS1 * HD];
__device__ bf16 g_v1th[BB * HH * DD * SS1]; __device__ bf16 g_v1tl[BB * HH * DD * SS1];
__device__ bf16 g_q2h[BB * SS2 * HD]; __device__ bf16 g_q2l[BB * SS2 * HD];
__device__ bf16 g_k2h[BB * SS2 * HD]; __device__ bf16 g_k2l[BB * SS2 * HD];
__device__ bf16 g_v2th[BB * HH * DD * SS2]; __device__ bf16 g_v2tl[BB * HH * DD * SS2];

#define P_ELEMS ((size_t)BB * HH * SS2 * SS1)
__device__ bf16 g_p1h[P_ELEMS]; __device__ bf16 g_p1l[P_ELEMS];
__device__ bf16 g_p2h[P_ELEMS]; __device__ bf16 g_p2l[P_ELEMS];

// ---------------- helpers ----------------
__device__ __forceinline__ uint32_t smem_u32(const void* p) {
    uint32_t a;
    asm("{ .reg .u64 t; cvta.to.shared.u64 t, %1; cvt.u32.u64 %0, t; }"
        : "=r"(a) : "l"(p));
    return a;
}
__device__ __forceinline__ void cp16(uint32_t dst, const void* src) {
    asm volatile("cp.async.cg.shared.global [%0], [%1], 16;\n" :: "r"(dst), "l"(src));
}
__device__ __forceinline__ void ldsm_x4(uint32_t& r0, uint32_t& r1,
                                        uint32_t& r2, uint32_t& r3, uint32_t a) {
    asm volatile("ldmatrix.sync.aligned.m8n8.x4.shared.b16 {%0,%1,%2,%3}, [%4];"
                 : "=r"(r0), "=r"(r1), "=r"(r2), "=r"(r3) : "r"(a));
}
__device__ __forceinline__ void mma16816(float* c, uint32_t a0, uint32_t a1,
                                         uint32_t a2, uint32_t a3,
                                         uint32_t b0, uint32_t b1) {
    asm volatile(
        "mma.sync.aligned.m16n8k16.row.col.f32.bf16.bf16.f32 "
        "{%0,%1,%2,%3}, {%4,%5,%6,%7}, {%8,%9}, {%0,%1,%2,%3};"
        : "+f"(c[0]), "+f"(c[1]), "+f"(c[2]), "+f"(c[3])
        : "r"(a0), "r"(a1), "r"(a2), "r"(a3), "r"(b0), "r"(b1));
}
__device__ __forceinline__ uint32_t packbf(bf16 a, bf16 b) {
    __nv_bfloat162 t = __halves2bfloat162(a, b);
    return *reinterpret_cast<uint32_t*>(&t);
}

// ---------------- split/convert kernels ----------------
__global__ void xsplit(const float4* __restrict__ x,
                       uint2* __restrict__ h, uint2* __restrict__ l, int n4) {
    int i = blockIdx.x * blockDim.x + threadIdx.x;
    if (i >= n4) return;
    float4 v = x[i];
    bf16 h0 = __float2bfloat16(v.x), h1 = __float2bfloat16(v.y);
    bf16 h2 = __float2bfloat16(v.z), h3 = __float2bfloat16(v.w);
    float r0 = v.x - __bfloat162float(h0), r1 = v.y - __bfloat162float(h1);
    float r2 = v.z - __bfloat162float(h2), r3 = v.w - __bfloat162float(h3);
    uint2 hp, lp;
    hp.x = packbf(h0, h1); hp.y = packbf(h2, h3);
    lp.x = packbf(__float2bfloat16(r0), __float2bfloat16(r1));
    lp.y = packbf(__float2bfloat16(r2), __float2bfloat16(r3));
    h[i] = hp; l[i] = lp;
}

struct WS {
    const float* W[6];
    bf16* Wh[6];
    bf16* Wl[6];
    int K[6];
};

__global__ void wsplit_all(WS ws) {
    const int z = blockIdx.z;
    const int K = ws.K[z];
    const int N = 1024;
    const int k0 = blockIdx.y * 32, n0 = blockIdx.x * 32;
    if (k0 >= K) return;
    __shared__ float t[32][33];
    const float* W = ws.W[z];
    bf16* Wh = ws.Wh[z];
    bf16* Wl = ws.Wl[z];
    int tx = threadIdx.x, ty = threadIdx.y;
#pragma unroll
    for (int i = 0; i < 4; i++)
        t[ty + i * 8][tx] = W[(size_t)(k0 + ty + i * 8) * N + n0 + tx];
    __syncthreads();
#pragma unroll
    for (int i = 0; i < 4; i++) {
        float v = t[tx][ty + i * 8];
        bf16 h = __float2bfloat16(v);
        float lo = v - __bfloat162float(h);
        size_t o = (size_t)(n0 + ty + i * 8) * K + k0 + tx;
        Wh[o] = h;
        Wl[o] = __float2bfloat16(lo);
    }
}

// V [B,S,H,D] fp32 -> Vt [B,H,D,S] bf16 hi/lo.  grid (D/32, S/32, BH), block (32,8)
__global__ void vtrans(const float* __restrict__ V,
                       bf16* __restrict__ Vth, bf16* __restrict__ Vtl, int S) {
    __shared__ float t[32][33];
    const int bh = blockIdx.z, b = bh >> 3, h = bh & 7;
    const int d0 = blockIdx.x * 32, s0 = blockIdx.y * 32;
    const int tx = threadIdx.x, ty = threadIdx.y;
#pragma unroll
    for (int i = 0; i < 4; i++)
        t[ty + i * 8][tx] =
            V[(size_t)(b * S + s0 + ty + i * 8) * HD + h * DD + d0 + tx];
    __syncthreads();
#pragma unroll
    for (int i = 0; i < 4; i++) {
        float v = t[tx][ty + i * 8];
        bf16 hi = __float2bfloat16(v);
        float lo = v - __bfloat162float(hi);
        size_t o = ((size_t)bh * DD + d0 + ty + i * 8) * S + s0 + tx;
        Vth[o] = hi;
        Vtl[o] = __float2bfloat16(lo);
    }
}

// ---------------------------------------------------------------------------
// QKV HMMA GEMM (unchanged; proven)
// ---------------------------------------------------------------------------
struct G3 {
    const bf16* Wh[3];
    const bf16* Wl[3];
    const float* bias[3];
    float* out[3];
};

#define PADK 40

__global__ __launch_bounds__(256) void hmma_gemm3(
    const bf16* __restrict__ Ah, const bf16* __restrict__ Al,
    G3 g, int M, int K) {
    const int N = 1024;
    __shared__ __align__(128) bf16 As[2][128 * PADK];
    __shared__ __align__(128) bf16 Bs[2][128 * PADK];

    const int tid = threadIdx.x;
    const int wid = tid >> 5, lane = tid & 31;
    const int wm = wid >> 2, wn = wid & 3;
    const int z = blockIdx.z;
    const int bm = blockIdx.y * 128, bn = blockIdx.x * 128;
    const int nk = K / 32;
    const int C = 3 * nk;

    const bf16* Wh = g.Wh[z];
    const bf16* Wl = g.Wl[z];

    float acc[4][4][4];
#pragma unroll
    for (int i = 0; i < 4; i++)
#pragma unroll
        for (int j = 0; j < 4; j++)
#pragma unroll
            for (int r = 0; r < 4; r++) acc[i][j][r] = 0.f;

    const uint32_t asb = smem_u32(&As[0][0]);
    const uint32_t bsb = smem_u32(&Bs[0][0]);
    const uint32_t stageB = 128 * PADK * 2;

    const int r0 = tid >> 2, s0 = (tid & 3);
    const uint32_t a_lm = (uint32_t)((wm * 64 + (lane & 15)) * (PADK * 2) + (lane >> 4) * 16);
    const uint32_t b_lm = (uint32_t)((wn * 32 + (lane & 15)) * (PADK * 2) + (lane >> 4) * 16);

    auto load_stage = [&](int c, int buf) {
        const int p = c / nk, kc = c - p * nk;
        const bf16* Ap = (p < 2) ? Ah : Al;
        const bf16* Bp = (p == 1) ? Wl : Wh;
        const char* ab = (const char*)(Ap + (size_t)bm * K + kc * 32);
        const char* bb = (const char*)(Bp + (size_t)bn * K + kc * 32);
        const size_t rs = (size_t)K * 2;
        const uint32_t sa = asb + buf * stageB;
        const uint32_t sb2 = bsb + buf * stageB;
#pragma unroll
        for (int u = 0; u < 2; u++) {
            int row = r0 + u * 64;
            uint32_t off = (uint32_t)(row * (PADK * 2) + s0 * 16);
            cp16(sa + off, ab + (size_t)row * rs + s0 * 16);
            cp16(sb2 + off, bb + (size_t)row * rs + s0 * 16);
        }
        asm volatile("cp.async.commit_group;\n");
    };

    load_stage(0, 0);

    for (int c = 0; c < C; ++c) {
        if (c + 1 < C) {
            load_stage(c + 1, (c + 1) & 1);
            asm volatile("cp.async.wait_group 1;\n");
        } else {
            asm volatile("cp.async.wait_group 0;\n");
        }
        __syncthreads();

        const int buf = c & 1;
        const uint32_t sa = asb + buf * stageB + a_lm;
        const uint32_t sb2 = bsb + buf * stageB + b_lm;
#pragma unroll
        for (int kk = 0; kk < 2; kk++) {
            uint32_t a[4][4], bbf[2][4];
#pragma unroll
            for (int i = 0; i < 4; i++)
                ldsm_x4(a[i][0], a[i][1], a[i][2], a[i][3],
                        sa + i * 16 * (PADK * 2) + kk * 32);
#pragma unroll
            for (int j2 = 0; j2 < 2; j2++)
                ldsm_x4(bbf[j2][0], bbf[j2][1], bbf[j2][2], bbf[j2][3],
                        sb2 + j2 * 16 * (PADK * 2) + kk * 32);
#pragma unroll
            for (int i = 0; i < 4; i++)
#pragma unroll
                for (int j = 0; j < 4; j++) {
                    int j2 = j >> 1, jo = j & 1;
                    mma16816(acc[i][j], a[i][0], a[i][1], a[i][2], a[i][3],
                             bbf[j2][jo], bbf[j2][jo + 2]);
                }
        }
        __syncthreads();
    }

    float* outp = g.out[z];
    const float* bias = g.bias[z];
#pragma unroll
    for (int i = 0; i < 4; i++) {
#pragma unroll
        for (int j = 0; j < 4; j++) {
            int m = bm + wm * 64 + i * 16 + (lane >> 2);
            int n = bn + wn * 32 + j * 8 + (lane & 3) * 2;
            float b0 = __ldg(bias + n), b1 = __ldg(bias + n + 1);
            float2 v0 = make_float2(acc[i][j][0] + b0, acc[i][j][1] + b1);
            float2 v1 = make_float2(acc[i][j][2] + b0, acc[i][j][3] + b1);
            *reinterpret_cast<float2*>(outp + (size_t)m * N + n) = v0;
            *reinterpret_cast<float2*>(outp + (size_t)(m + 8) * N + n) = v1;
        }
    }
}

// ---------------------------------------------------------------------------
// scores HMMA: same skeleton; A=Q rows (stride HD), B=K rows (stride HD).
// S[bh][m][n] = scale*(Q.K) + mask. grid (Sk/128, Sq/128, BH). nk=4, C=12.
// ---------------------------------------------------------------------------
__global__ __launch_bounds__(256) void hmma_scores(
    const bf16* __restrict__ Qh, const bf16* __restrict__ Ql,
    const bf16* __restrict__ Kh, const bf16* __restrict__ Kl,
    const float* __restrict__ mask, float* __restrict__ Sout,
    int Sq, int Sk, float scale) {
    __shared__ __align__(128) bf16 As[2][128 * PADK];
    __shared__ __align__(128) bf16 Bs[2][128 * PADK];

    const int tid = threadIdx.x;
    const int wid = tid >> 5, lane = tid & 31;
    const int wm = wid >> 2, wn = wid & 3;
    const int bh = blockIdx.z, b = bh >> 3, h = bh & 7;
    const int bm = blockIdx.y * 128, bn = blockIdx.x * 128;
    const int nk = 4;
    const int C = 12;

    float acc[4][4][4];
#pragma unroll
    for (int i = 0; i < 4; i++)
#pragma unroll
        for (int j = 0; j < 4; j++)
#pragma unroll
            for (int r = 0; r < 4; r++) acc[i][j][r] = 0.f;

    const uint32_t asb = smem_u32(&As[0][0]);
    const uint32_t bsb = smem_u32(&Bs[0][0]);
    const uint32_t stageB = 128 * PADK * 2;

    const int r0 = tid >> 2, s0 = (tid & 3);
    const uint32_t a_lm = (uint32_t)((wm * 64 + (lane & 15)) * (PADK * 2) + (lane >> 4) * 16);
    const uint32_t b_lm = (uint32_t)((wn * 32 + (lane & 15)) * (PADK * 2) + (lane >> 4) * 16);

    auto load_stage = [&](int c, int buf) {
        const int p = c / nk, kc = c - p * nk;
        const bf16* Ap = (p < 2) ? Qh : Ql;
        const bf16* Bp = (p == 1) ? Kl : Kh;
        const char* ab = (const char*)(Ap + (size_t)(b * Sq + bm) * HD + h * DD + kc * 32);
        const char* bb = (const char*)(Bp + (size_t)(b * Sk + bn) * HD + h * DD + kc * 32);
        const size_t rs = (size_t)HD * 2;
        const uint32_t sa = asb + buf * stageB;
        const uint32_t sb2 = bsb + buf * stageB;
#pragma unroll
        for (int u = 0; u < 2; u++) {
            int row = r0 + u * 64;
            uint32_t off = (uint32_t)(row * (PADK * 2) + s0 * 16);
            cp16(sa + off, ab + (size_t)row * rs + s0 * 16);
            cp16(sb2 + off, bb + (size_t)row * rs + s0 * 16);
        }
        asm volatile("cp.async.commit_group;\n");
    };

    load_stage(0, 0);

    for (int c = 0; c < C; ++c) {
        if (c + 1 < C) {
            load_stage(c + 1, (c + 1) & 1);
            asm volatile("cp.async.wait_group 1;\n");
        } else {
            asm volatile("cp.async.wait_group 0;\n");
        }
        __syncthreads();

        const int buf = c & 1;
        const uint32_t sa = asb + buf * stageB + a_lm;
        const uint32_t sb2 = bsb + buf * stageB + b_lm;
#pragma unroll
        for (int kk = 0; kk < 2; kk++) {
            uint32_t a[4][4], bbf[2][4];
#pragma unroll
            for (int i = 0; i < 4; i++)
                ldsm_x4(a[i][0], a[i][1], a[i][2], a[i][3],
                        sa + i * 16 * (PADK * 2) + kk * 32);
#pragma unroll
            for (int j2 = 0; j2 < 2; j2++)
                ldsm_x4(bbf[j2][0], bbf[j2][1], bbf[j2][2], bbf[j2][3],
                        sb2 + j2 * 16 * (PADK * 2) + kk * 32);
#pragma unroll
            for (int i = 0; i < 4; i++)
#pragma unroll
                for (int j = 0; j < 4; j++) {
                    int j2 = j >> 1, jo = j & 1;
                    mma16816(acc[i][j], a[i][0], a[i][1], a[i][2], a[i][3],
                             bbf[j2][jo], bbf[j2][jo + 2]);
                }
        }
        __syncthreads();
    }

#pragma unroll
    for (int i = 0; i < 4; i++) {
#pragma unroll
        for (int j = 0; j < 4; j++) {
            int m = bm + wm * 64 + i * 16 + (lane >> 2);
            int n = bn + wn * 32 + j * 8 + (lane & 3) * 2;
            float mk0 = __ldg(mask + b * Sk + n);
            float mk1 = __ldg(mask + b * Sk + n + 1);
            float2 v0 = make_float2(acc[i][j][0] * scale + mk0,
                                    acc[i][j][1] * scale + mk1);
            float2 v1 = make_float2(acc[i][j][2] * scale + mk0,
                                    acc[i][j][3] * scale + mk1);
            *reinterpret_cast<float2*>(Sout + ((size_t)bh * Sq + m) * Sk + n) = v0;
            *reinterpret_cast<float2*>(Sout + ((size_t)bh * Sq + m + 8) * Sk + n) = v1;
        }
    }
}

// ---------------------------------------------------------------------------
// softmax + split to bf16 hi/lo.  warp per row; n in {256,512}.
// ---------------------------------------------------------------------------
__global__ __launch_bounds__(256) void softmax_split(
    const float* __restrict__ S, bf16* __restrict__ Ph, bf16* __restrict__ Pl,
    int rows, int n) {
    int row = (blockIdx.x * blockDim.x + threadIdx.x) >> 5;
    int lane = threadIdx.x & 31;
    if (row >= rows) return;
    const float2* r2 = reinterpret_cast<const float2*>(S + (size_t)row * n);
    const int np = n >> 6;

    float v[16];
    float mx = -INFINITY;
#pragma unroll
    for (int c = 0; c < 8; c++) {
        if (c >= np) break;
        float2 t = r2[lane + c * 32];
        v[2 * c] = t.x; v[2 * c + 1] = t.y;
        mx = fmaxf(mx, fmaxf(t.x, t.y));
    }
#pragma unroll
    for (int o = 16; o; o >>= 1) mx = fmaxf(mx, __shfl_xor_sync(0xffffffffu, mx, o));

    float sum = 0.f;
#pragma unroll
    for (int c = 0; c < 8; c++) {
        if (c >= np) break;
        float e0 = __expf(v[2 * c] - mx);
        float e1 = __expf(v[2 * c + 1] - mx);
        v[2 * c] = e0; v[2 * c + 1] = e1;
        sum += e0 + e1;
    }
#pragma unroll
    for (int o = 16; o; o >>= 1) sum += __shfl_xor_sync(0xffffffffu, sum, o);
    float inv = 1.f / sum;

    uint32_t* ph32 = reinterpret_cast<uint32_t*>(Ph + (size_t)row * n);
    uint32_t* pl32 = reinterpret_cast<uint32_t*>(Pl + (size_t)row * n);
#pragma unroll
    for (int c = 0; c < 8; c++) {
        if (c >= np) break;
        float p0 = v[2 * c] * inv, p1 = v[2 * c + 1] * inv;
        bf16 h0 = __float2bfloat16(p0), h1 = __float2bfloat16(p1);
        float l0 = p0 - __bfloat162float(h0), l1 = p1 - __bfloat162float(h1);
        ph32[lane + c * 32] = packbf(h0, h1);
        pl32[lane + c * 32] = packbf(__float2bfloat16(l0), __float2bfloat16(l1));
    }
}

// ---------------------------------------------------------------------------
// ctx HMMA: same skeleton; A=P (stride Sk), B=Vt [D][S] (stride Sk).
// O[b,m,h,:] = P @ V. grid (1, Sq/128, BH). nk=Sk/32, C=3*nk.
// ---------------------------------------------------------------------------
__global__ __launch_bounds__(256) void hmma_ctx(
    const bf16* __restrict__ Ph, const bf16* __restrict__ Pl,
    const bf16* __restrict__ Vth, const bf16* __restrict__ Vtl,
    float* __restrict__ O, int Sq, int Sk) {
    __shared__ __align__(128) bf16 As[2][128 * PADK];
    __shared__ __align__(128) bf16 Bs[2][128 * PADK];

    const int tid = threadIdx.x;
    const int wid = tid >> 5, lane = tid & 31;
    const int wm = wid >> 2, wn = wid & 3;
    const int bh = blockIdx.z, b = bh >> 3, h = bh & 7;
    const int bm = blockIdx.y * 128;
    const int nk = Sk / 32;
    const int C = 3 * nk;

    float acc[4][4][4];
#pragma unroll
    for (int i = 0; i < 4; i++)
#pragma unroll
        for (int j = 0; j < 4; j++)
#pragma unroll
            for (int r = 0; r < 4; r++) acc[i][j][r] = 0.f;

    const uint32_t asb = smem_u32(&As[0][0]);
    const uint32_t bsb = smem_u32(&Bs[0][0]);
    const uint32_t stageB = 128 * PADK * 2;

    const int r0 = tid >> 2, s0 = (tid & 3);
    const uint32_t a_lm = (uint32_t)((wm * 64 + (lane & 15)) * (PADK * 2) + (lane >> 4) * 16);
    const uint32_t b_lm = (uint32_t)((wn * 32 + (lane & 15)) * (PADK * 2) + (lane >> 4) * 16);

    auto load_stage = [&](int c, int buf) {
        const int p = c / nk, kc = c - p * nk;
        const bf16* Ap = (p < 2) ? Ph : Pl;
        const bf16* Bp = (p == 1) ? Vtl : Vth;
        const char* ab = (const char*)(Ap + ((size_t)bh * Sq + bm) * Sk + kc * 32);
        const char* bb = (const char*)(Bp + (size_t)bh * DD * Sk + kc * 32);
        const size_t rs = (size_t)Sk * 2;
        const uint32_t sa = asb + buf * stageB;
        const uint32_t sb2 = bsb + buf * stageB;
#pragma unroll
        for (int u = 0; u < 2; u++) {
            int row = r0 + u * 64;
            uint32_t off = (uint32_t)(row * (PADK * 2) + s0 * 16);
            cp16(sa + off, ab + (size_t)row * rs + s0 * 16);
            cp16(sb2 + off, bb + (size_t)row * rs + s0 * 16);
        }
        asm volatile("cp.async.commit_group;\n");
    };

    load_stage(0, 0);

    for (int c = 0; c < C; ++c) {
        if (c + 1 < C) {
            load_stage(c + 1, (c + 1) & 1);
            asm volatile("cp.async.wait_group 1;\n");
        } else {
            asm volatile("cp.async.wait_group 0;\n");
        }
        __syncthreads();

        const int buf = c & 1;
        const uint32_t sa = asb + buf * stageB + a_lm;
        const uint32_t sb2 = bsb + buf * stageB + b_lm;
#pragma unroll
        for (int kk = 0; kk < 2; kk++) {
            uint32_t a[4][4], bbf[2][4];
#pragma unroll
            for (int i = 0; i < 4; i++)
                ldsm_x4(a[i][0], a[i][1], a[i][2], a[i][3],
                        sa + i * 16 * (PADK * 2) + kk * 32);
#pragma unroll
            for (int j2 = 0; j2 < 2; j2++)
                ldsm_x4(bbf[j2][0], bbf[j2][1], bbf[j2][2], bbf[j2][3],
                        sb2 + j2 * 16 * (PADK * 2) + kk * 32);
#pragma unroll
            for (int i = 0; i < 4; i++)
#pragma unroll
                for (int j = 0; j < 4; j++) {
                    int j2 = j >> 1, jo = j & 1;
                    mma16816(acc[i][j], a[i][0], a[i][1], a[i][2], a[i][3],
                             bbf[j2][jo], bbf[j2][jo + 2]);
                }
        }
        __syncthreads();
    }

    // epilogue -> O[b, m, h, d] fp32
#pragma unroll
    for (int i = 0; i < 4; i++) {
#pragma unroll
        for (int j = 0; j < 4; j++) {
            int m = bm + wm * 64 + i * 16 + (lane >> 2);
            int d = wn * 32 + j * 8 + (lane & 3) * 2;
            float2 v0 = make_float2(acc[i][j][0], acc[i][j][1]);
            float2 v1 = make_float2(acc[i][j][2], acc[i][j][3]);
            *reinterpret_cast<float2*>(
                O + ((size_t)(b * Sq + m) * HH + h) * DD + d) = v0;
            *reinterpret_cast<float2*>(
                O + ((size_t)(b * Sq + m + 8) * HH + h) * DD + d) = v1;
        }
    }
}

// ---------------------------------------------------------------------------
extern "C" void kernel_launch(void* const* d_in, const int* in_sizes, int n_in,
                              void* d_out, int out_size) {
    const float* x1    = (const float*)d_in[0];
    const float* mask1 = (const float*)d_in[1];
    const float* x2    = (const float*)d_in[2];
    const float* mask2 = (const float*)d_in[3];
    const float* W1[3] = {(const float*)d_in[4], (const float*)d_in[6], (const float*)d_in[8]};
    const float* b1[3] = {(const float*)d_in[5], (const float*)d_in[7], (const float*)d_in[9]};
    const float* W2[3] = {(const float*)d_in[10], (const float*)d_in[12], (const float*)d_in[14]};
    const float* b2[3] = {(const float*)d_in[11], (const float*)d_in[13], (const float*)d_in[15]};
    float* out = (float*)d_out;

    float *q1, *k1, *v1, *q2, *k2, *v2, *p1, *p2;
    cudaGetSymbolAddress((void**)&q1, g_q1);
    cudaGetSymbolAddress((void**)&k1, g_k1);
    cudaGetSymbolAddress((void**)&v1, g_v1);
    cudaGetSymbolAddress((void**)&q2, g_q2);
    cudaGetSymbolAddress((void**)&k2, g_k2);
    cudaGetSymbolAddress((void**)&v2, g_v2);
    cudaGetSymbolAddress((void**)&p1, g_p1);
    cudaGetSymbolAddress((void**)&p2, g_p2);

    bf16 *x1h, *x1l, *x2h, *x2l, *w1h, *w1l, *w2h, *w2l;
    cudaGetSymbolAddress((void**)&x1h, g_x1h);
    cudaGetSymbolAddress((void**)&x1l, g_x1l);
    cudaGetSymbolAddress((void**)&x2h, g_x2h);
    cudaGetSymbolAddress((void**)&x2l, g_x2l);
    cudaGetSymbolAddress((void**)&w1h, g_w1h);
    cudaGetSymbolAddress((void**)&w1l, g_w1l);
    cudaGetSymbolAddress((void**)&w2h, g_w2h);
    cudaGetSymbolAddress((void**)&w2l, g_w2l);

    bf16 *q1h, *q1l, *k1h, *k1l, *v1th, *v1tl;
    bf16 *q2h, *q2l, *k2h, *k2l, *v2th, *v2tl;
    cudaGetSymbolAddress((void**)&q1h, g_q1h); cudaGetSymbolAddress((void**)&q1l, g_q1l);
    cudaGetSymbolAddress((void**)&k1h, g_k1h); cudaGetSymbolAddress((void**)&k1l, g_k1l);
    cudaGetSymbolAddress((void**)&v1th, g_v1th); cudaGetSymbolAddress((void**)&v1tl, g_v1tl);
    cudaGetSymbolAddress((void**)&q2h, g_q2h); cudaGetSymbolAddress((void**)&q2l, g_q2l);
    cudaGetSymbolAddress((void**)&k2h, g_k2h); cudaGetSymbolAddress((void**)&k2l, g_k2l);
    cudaGetSymbolAddress((void**)&v2th, g_v2th); cudaGetSymbolAddress((void**)&v2tl, g_v2tl);

    bf16 *p1h, *p1l, *p2h, *p2l;
    cudaGetSymbolAddress((void**)&p1h, g_p1h); cudaGetSymbolAddress((void**)&p1l, g_p1l);
    cudaGetSymbolAddress((void**)&p2h, g_p2h); cudaGetSymbolAddress((void**)&p2l, g_p2l);

    const float scale = 1.0f / sqrtf((float)DD);
    dim3 blk(256);

    // input splits
    {
        int n4 = 4096 * 1024 / 4;
        xsplit<<<n4 / 256, 256>>>((const float4*)x1, (uint2*)x1h, (uint2*)x1l, n4);
    }
    {
        int n4 = 8192 * 768 / 4;
        xsplit<<<n4 / 256, 256>>>((const float4*)x2, (uint2*)x2h, (uint2*)x2l, n4);
    }
    {
        WS ws;
        for (int i = 0; i < 3; i++) {
            ws.W[i] = W1[i];
            ws.Wh[i] = w1h + (size_t)i * 1024 * 1024;
            ws.Wl[i] = w1l + (size_t)i * 1024 * 1024;
            ws.K[i] = 1024;
            ws.W[3 + i] = W2[i];
            ws.Wh[3 + i] = w2h + (size_t)i * 1024 * 768;
            ws.Wl[3 + i] = w2l + (size_t)i * 1024 * 768;
            ws.K[3 + i] = 768;
        }
        wsplit_all<<<dim3(32, 32, 6), dim3(32, 8)>>>(ws);
    }

    // QKV projections (HMMA, 3-pass split) -> fp32 q/k/v
    {
        G3 g;
        for (int i = 0; i < 3; i++) {
            g.Wh[i] = w1h + (size_t)i * 1024 * 1024;
            g.Wl[i] = w1l + (size_t)i * 1024 * 1024;
            g.bias[i] = b1[i];
        }
        g.out[0] = q1; g.out[1] = k1; g.out[2] = v1;
        hmma_gemm3<<<dim3(8, 32, 3), blk>>>(x1h, x1l, g, BB * SS1, 1024);
    }
    {
        G3 g;
        for (int i = 0; i < 3; i++) {
            g.Wh[i] = w2h + (size_t)i * 1024 * 768;
            g.Wl[i] = w2l + (size_t)i * 1024 * 768;
            g.bias[i] = b2[i];
        }
        g.out[0] = q2; g.out[1] = k2; g.out[2] = v2;
        hmma_gemm3<<<dim3(8, 64, 3), blk>>>(x2h, x2l, g, BB * SS2, 768);
    }

    // q/k splits (coalesced) + V transposes
    {
        int n4 = BB * SS1 * HD / 4;
        xsplit<<<n4 / 256, 256>>>((const float4*)q1, (uint2*)q1h, (uint2*)q1l, n4);
        xsplit<<<n4 / 256, 256>>>((const float4*)k1, (uint2*)k1h, (uint2*)k1l, n4);
    }
    {
        int n4 = BB * SS2 * HD / 4;
        xsplit<<<n4 / 256, 256>>>((const float4*)q2, (uint2*)q2h, (uint2*)q2l, n4);
        xsplit<<<n4 / 256, 256>>>((const float4*)k2, (uint2*)k2h, (uint2*)k2l, n4);
    }
    vtrans<<<dim3(4, SS1 / 32, BB * HH), dim3(32, 8)>>>(v1, v1th, v1tl, SS1);
    vtrans<<<dim3(4, SS2 / 32, BB * HH), dim3(32, 8)>>>(v2, v2th, v2tl, SS2);

    // attention 1: q2 over (k1, v1) -> out[0:C1]
    hmma_scores<<<dim3(SS1 / 128, SS2 / 128, BB * HH), blk>>>(
        q2h, q2l, k1h, k1l, mask1, p1, SS2, SS1, scale);
    softmax_split<<<(BB * HH * SS2) / 8, blk>>>(p1, p1h, p1l, BB * HH * SS2, SS1);
    hmma_ctx<<<dim3(1, SS2 / 128, BB * HH), blk>>>(p1h, p1l, v1th, v1tl, out, SS2, SS1);

    // attention 2: q1 over (k2, v2) -> out[C1:]
    hmma_scores<<<dim3(SS2 / 128, SS1 / 128, BB * HH), blk>>>(
        q1h, q1l, k2h, k2l, mask2, p2, SS1, SS2, scale);
    softmax_split<<<(BB * HH * SS1) / 8, blk>>>(p2, p2h, p2l, BB * HH * SS1, SS2);
    hmma_ctx<<<dim3(1, SS1 / 128, BB * HH), blk>>>(p2h, p2l, v2th, v2tl, out + C1_ELEMS, SS1, SS2);
}

// round 9
// speedup vs baseline: 1.9170x; 1.0689x over previous
#include <cuda_runtime.h>
#include <cuda_bf16.h>
#include <cstdint>
#include <math.h>

// ===========================================================================
// BertBiAttention on GB300 (sm_103 ptxas target -> mma.sync HMMA everywhere)
//   B=16, S1=256, S2=512, V_HID=1024, T_HID=768, BI_HID=1024, H=8, D=128
// Round 9: 4-stage cp.async ring + single barrier/iter in all HMMA kernels
//   (wait_group 2 -> sync -> compute(c) -> load(c+3) -> commit).
//   Numerics unchanged: bf16 hi/lo split, 3-pass compensation, fp32 accum.
// ===========================================================================

#define BB   16
#define SS1  256
#define SS2  512
#define HH   8
#define DD   128
#define HD   1024
#define C1_ELEMS ((size_t)BB * SS2 * HD)

typedef __nv_bfloat16 bf16;

#define PADK 40
#define NSTAGE 4
#define TILEB (128 * PADK * 2)          // 10240 bytes per tile
#define SMEM_DYN (2 * NSTAGE * TILEB)   // 81920 bytes

// ---------------- scratch ----------------
__device__ float g_q1[BB * SS1 * HD];
__device__ float g_k1[BB * SS1 * HD];
__device__ float g_v1[BB * SS1 * HD];
__device__ float g_q2[BB * SS2 * HD];
__device__ float g_k2[BB * SS2 * HD];
__device__ float g_v2[BB * SS2 * HD];
__device__ float g_p1[(size_t)BB * HH * SS2 * SS1];
__device__ float g_p2[(size_t)BB * HH * SS1 * SS2];

__device__ bf16 g_x1h[4096 * 1024];
__device__ bf16 g_x1l[4096 * 1024];
__device__ bf16 g_x2h[8192 * 768];
__device__ bf16 g_x2l[8192 * 768];
__device__ bf16 g_w1h[3][1024 * 1024];
__device__ bf16 g_w1l[3][1024 * 1024];
__device__ bf16 g_w2h[3][1024 * 768];
__device__ bf16 g_w2l[3][1024 * 768];

__device__ bf16 g_q1h[BB * SS1 * HD]; __device__ bf16 g_q1l[BB * SS1 * HD];
__device__ bf16 g_k1h[BB * SS1 * HD]; __device__ bf16 g_k1l[BB * SS1 * HD];
__device__ bf16 g_v1th[BB * HH * DD * SS1]; __device__ bf16 g_v1tl[BB * HH * DD * SS1];
__device__ bf16 g_q2h[BB * SS2 * HD]; __device__ bf16 g_q2l[BB * SS2 * HD];
__device__ bf16 g_k2h[BB * SS2 * HD]; __device__ bf16 g_k2l[BB * SS2 * HD];
__device__ bf16 g_v2th[BB * HH * DD * SS2]; __device__ bf16 g_v2tl[BB * HH * DD * SS2];

#define P_ELEMS ((size_t)BB * HH * SS2 * SS1)
__device__ bf16 g_p1h[P_ELEMS]; __device__ bf16 g_p1l[P_ELEMS];
__device__ bf16 g_p2h[P_ELEMS]; __device__ bf16 g_p2l[P_ELEMS];

// ---------------- helpers ----------------
__device__ __forceinline__ uint32_t smem_u32(const void* p) {
    uint32_t a;
    asm("{ .reg .u64 t; cvta.to.shared.u64 t, %1; cvt.u32.u64 %0, t; }"
        : "=r"(a) : "l"(p));
    return a;
}
__device__ __forceinline__ void cp16(uint32_t dst, const void* src) {
    asm volatile("cp.async.cg.shared.global [%0], [%1], 16;\n" :: "r"(dst), "l"(src));
}
__device__ __forceinline__ void ldsm_x4(uint32_t& r0, uint32_t& r1,
                                        uint32_t& r2, uint32_t& r3, uint32_t a) {
    asm volatile("ldmatrix.sync.aligned.m8n8.x4.shared.b16 {%0,%1,%2,%3}, [%4];"
                 : "=r"(r0), "=r"(r1), "=r"(r2), "=r"(r3) : "r"(a));
}
__device__ __forceinline__ void mma16816(float* c, uint32_t a0, uint32_t a1,
                                         uint32_t a2, uint32_t a3,
                                         uint32_t b0, uint32_t b1) {
    asm volatile(
        "mma.sync.aligned.m16n8k16.row.col.f32.bf16.bf16.f32 "
        "{%0,%1,%2,%3}, {%4,%5,%6,%7}, {%8,%9}, {%0,%1,%2,%3};"
        : "+f"(c[0]), "+f"(c[1]), "+f"(c[2]), "+f"(c[3])
        : "r"(a0), "r"(a1), "r"(a2), "r"(a3), "r"(b0), "r"(b1));
}
__device__ __forceinline__ uint32_t packbf(bf16 a, bf16 b) {
    __nv_bfloat162 t = __halves2bfloat162(a, b);
    return *reinterpret_cast<uint32_t*>(&t);
}

// ---------------- split/convert kernels ----------------
__global__ void xsplit(const float4* __restrict__ x,
                       uint2* __restrict__ h, uint2* __restrict__ l, int n4) {
    int i = blockIdx.x * blockDim.x + threadIdx.x;
    if (i >= n4) return;
    float4 v = x[i];
    bf16 h0 = __float2bfloat16(v.x), h1 = __float2bfloat16(v.y);
    bf16 h2 = __float2bfloat16(v.z), h3 = __float2bfloat16(v.w);
    float r0 = v.x - __bfloat162float(h0), r1 = v.y - __bfloat162float(h1);
    float r2 = v.z - __bfloat162float(h2), r3 = v.w - __bfloat162float(h3);
    uint2 hp, lp;
    hp.x = packbf(h0, h1); hp.y = packbf(h2, h3);
    lp.x = packbf(__float2bfloat16(r0), __float2bfloat16(r1));
    lp.y = packbf(__float2bfloat16(r2), __float2bfloat16(r3));
    h[i] = hp; l[i] = lp;
}

struct WS {
    const float* W[6];
    bf16* Wh[6];
    bf16* Wl[6];
    int K[6];
};

__global__ void wsplit_all(WS ws) {
    const int z = blockIdx.z;
    const int K = ws.K[z];
    const int N = 1024;
    const int k0 = blockIdx.y * 32, n0 = blockIdx.x * 32;
    if (k0 >= K) return;
    __shared__ float t[32][33];
    const float* W = ws.W[z];
    bf16* Wh = ws.Wh[z];
    bf16* Wl = ws.Wl[z];
    int tx = threadIdx.x, ty = threadIdx.y;
#pragma unroll
    for (int i = 0; i < 4; i++)
        t[ty + i * 8][tx] = W[(size_t)(k0 + ty + i * 8) * N + n0 + tx];
    __syncthreads();
#pragma unroll
    for (int i = 0; i < 4; i++) {
        float v = t[tx][ty + i * 8];
        bf16 h = __float2bfloat16(v);
        float lo = v - __bfloat162float(h);
        size_t o = (size_t)(n0 + ty + i * 8) * K + k0 + tx;
        Wh[o] = h;
        Wl[o] = __float2bfloat16(lo);
    }
}

__global__ void vtrans(const float* __restrict__ V,
                       bf16* __restrict__ Vth, bf16* __restrict__ Vtl, int S) {
    __shared__ float t[32][33];
    const int bh = blockIdx.z, b = bh >> 3, h = bh & 7;
    const int d0 = blockIdx.x * 32, s0 = blockIdx.y * 32;
    const int tx = threadIdx.x, ty = threadIdx.y;
#pragma unroll
    for (int i = 0; i < 4; i++)
        t[ty + i * 8][tx] =
            V[(size_t)(b * S + s0 + ty + i * 8) * HD + h * DD + d0 + tx];
    __syncthreads();
#pragma unroll
    for (int i = 0; i < 4; i++) {
        float v = t[tx][ty + i * 8];
        bf16 hi = __float2bfloat16(v);
        float lo = v - __bfloat162float(hi);
        size_t o = ((size_t)bh * DD + d0 + ty + i * 8) * S + s0 + tx;
        Vth[o] = hi;
        Vtl[o] = __float2bfloat16(lo);
    }
}

// ===========================================================================
// 4-stage pipelined mainloop (shared pattern):
//   prologue: load stages 0..2
//   iter c:   wait_group 2; sync; compute(c); load(c+3); commit
// ===========================================================================

#define MAINLOOP(LOADBODY)                                                     \
    /* prologue */                                                             \
    for (int s = 0; s < NSTAGE - 1; ++s) {                                     \
        if (s < C) { const int c_ = s; const int stg_ = s; LOADBODY }          \
        asm volatile("cp.async.commit_group;\n");                              \
    }                                                                          \
    for (int c = 0; c < C; ++c) {                                              \
        asm volatile("cp.async.wait_group %0;\n" :: "n"(NSTAGE - 2));          \
        __syncthreads();                                                       \
        const int buf = c & (NSTAGE - 1);                                      \
        const uint32_t sa = asb + buf * TILEB + a_lm;                          \
        const uint32_t sb2 = bsb + buf * TILEB + b_lm;                         \
        _Pragma("unroll")                                                      \
        for (int kk = 0; kk < 2; kk++) {                                       \
            uint32_t a[4][4], bbf[2][4];                                       \
            _Pragma("unroll")                                                  \
            for (int i = 0; i < 4; i++)                                        \
                ldsm_x4(a[i][0], a[i][1], a[i][2], a[i][3],                    \
                        sa + i * 16 * (PADK * 2) + kk * 32);                   \
            _Pragma("unroll")                                                  \
            for (int j2 = 0; j2 < 2; j2++)                                     \
                ldsm_x4(bbf[j2][0], bbf[j2][1], bbf[j2][2], bbf[j2][3],        \
                        sb2 + j2 * 16 * (PADK * 2) + kk * 32);                 \
            _Pragma("unroll")                                                  \
            for (int i = 0; i < 4; i++)                                        \
                _Pragma("unroll")                                              \
                for (int j = 0; j < 4; j++) {                                  \
                    int j2 = j >> 1, jo = j & 1;                               \
                    mma16816(acc[i][j], a[i][0], a[i][1], a[i][2], a[i][3],    \
                             bbf[j2][jo], bbf[j2][jo + 2]);                    \
                }                                                              \
        }                                                                      \
        if (c + NSTAGE - 1 < C) {                                              \
            const int c_ = c + NSTAGE - 1;                                     \
            const int stg_ = c_ & (NSTAGE - 1);                                \
            LOADBODY                                                           \
        }                                                                      \
        asm volatile("cp.async.commit_group;\n");                              \
    }

// ---------------------------------------------------------------------------
// QKV HMMA GEMM
// ---------------------------------------------------------------------------
struct G3 {
    const bf16* Wh[3];
    const bf16* Wl[3];
    const float* bias[3];
    float* out[3];
};

__global__ __launch_bounds__(256) void hmma_gemm3(
    const bf16* __restrict__ Ah, const bf16* __restrict__ Al,
    G3 g, int M, int K) {
    const int N = 1024;
    extern __shared__ __align__(128) char smem[];
    const uint32_t asb = smem_u32(smem);
    const uint32_t bsb = asb + NSTAGE * TILEB;

    const int tid = threadIdx.x;
    const int wid = tid >> 5, lane = tid & 31;
    const int wm = wid >> 2, wn = wid & 3;
    const int z = blockIdx.z;
    const int bm = blockIdx.y * 128, bn = blockIdx.x * 128;
    const int nk = K / 32;
    const int C = 3 * nk;

    const bf16* Wh = g.Wh[z];
    const bf16* Wl = g.Wl[z];

    float acc[4][4][4];
#pragma unroll
    for (int i = 0; i < 4; i++)
#pragma unroll
        for (int j = 0; j < 4; j++)
#pragma unroll
            for (int r = 0; r < 4; r++) acc[i][j][r] = 0.f;

    const int r0 = tid >> 2, s0 = (tid & 3);
    const uint32_t a_lm = (uint32_t)((wm * 64 + (lane & 15)) * (PADK * 2) + (lane >> 4) * 16);
    const uint32_t b_lm = (uint32_t)((wn * 32 + (lane & 15)) * (PADK * 2) + (lane >> 4) * 16);

#define QKV_LOAD {                                                             \
        const int p = c_ / nk, kc = c_ - p * nk;                               \
        const bf16* Ap = (p < 2) ? Ah : Al;                                    \
        const bf16* Bp = (p == 1) ? Wl : Wh;                                   \
        const char* ab = (const char*)(Ap + (size_t)bm * K + kc * 32);         \
        const char* bb = (const char*)(Bp + (size_t)bn * K + kc * 32);         \
        const size_t rs = (size_t)K * 2;                                       \
        const uint32_t sa_ = asb + stg_ * TILEB;                               \
        const uint32_t sb_ = bsb + stg_ * TILEB;                               \
        _Pragma("unroll")                                                      \
        for (int u = 0; u < 2; u++) {                                          \
            int row = r0 + u * 64;                                             \
            uint32_t off = (uint32_t)(row * (PADK * 2) + s0 * 16);             \
            cp16(sa_ + off, ab + (size_t)row * rs + s0 * 16);                  \
            cp16(sb_ + off, bb + (size_t)row * rs + s0 * 16);                  \
        }                                                                      \
    }

    MAINLOOP(QKV_LOAD)

    float* outp = g.out[z];
    const float* bias = g.bias[z];
#pragma unroll
    for (int i = 0; i < 4; i++) {
#pragma unroll
        for (int j = 0; j < 4; j++) {
            int m = bm + wm * 64 + i * 16 + (lane >> 2);
            int n = bn + wn * 32 + j * 8 + (lane & 3) * 2;
            float b0 = __ldg(bias + n), b1 = __ldg(bias + n + 1);
            float2 v0 = make_float2(acc[i][j][0] + b0, acc[i][j][1] + b1);
            float2 v1 = make_float2(acc[i][j][2] + b0, acc[i][j][3] + b1);
            *reinterpret_cast<float2*>(outp + (size_t)m * N + n) = v0;
            *reinterpret_cast<float2*>(outp + (size_t)(m + 8) * N + n) = v1;
        }
    }
}

// ---------------------------------------------------------------------------
// scores HMMA
// ---------------------------------------------------------------------------
__global__ __launch_bounds__(256) void hmma_scores(
    const bf16* __restrict__ Qh, const bf16* __restrict__ Ql,
    const bf16* __restrict__ Kh, const bf16* __restrict__ Kl,
    const float* __restrict__ mask, float* __restrict__ Sout,
    int Sq, int Sk, float scale) {
    extern __shared__ __align__(128) char smem[];
    const uint32_t asb = smem_u32(smem);
    const uint32_t bsb = asb + NSTAGE * TILEB;

    const int tid = threadIdx.x;
    const int wid = tid >> 5, lane = tid & 31;
    const int wm = wid >> 2, wn = wid & 3;
    const int bh = blockIdx.z, b = bh >> 3, h = bh & 7;
    const int bm = blockIdx.y * 128, bn = blockIdx.x * 128;
    const int nk = 4;
    const int C = 12;

    float acc[4][4][4];
#pragma unroll
    for (int i = 0; i < 4; i++)
#pragma unroll
        for (int j = 0; j < 4; j++)
#pragma unroll
            for (int r = 0; r < 4; r++) acc[i][j][r] = 0.f;

    const int r0 = tid >> 2, s0 = (tid & 3);
    const uint32_t a_lm = (uint32_t)((wm * 64 + (lane & 15)) * (PADK * 2) + (lane >> 4) * 16);
    const uint32_t b_lm = (uint32_t)((wn * 32 + (lane & 15)) * (PADK * 2) + (lane >> 4) * 16);

#define SC_LOAD {                                                              \
        const int p = c_ / nk, kc = c_ - p * nk;                               \
        const bf16* Ap = (p < 2) ? Qh : Ql;                                    \
        const bf16* Bp = (p == 1) ? Kl : Kh;                                   \
        const char* ab = (const char*)(Ap + (size_t)(b * Sq + bm) * HD + h * DD + kc * 32); \
        const char* bb = (const char*)(Bp + (size_t)(b * Sk + bn) * HD + h * DD + kc * 32); \
        const size_t rs = (size_t)HD * 2;                                      \
        const uint32_t sa_ = asb + stg_ * TILEB;                               \
        const uint32_t sb_ = bsb + stg_ * TILEB;                               \
        _Pragma("unroll")                                                      \
        for (int u = 0; u < 2; u++) {                                          \
            int row = r0 + u * 64;                                             \
            uint32_t off = (uint32_t)(row * (PADK * 2) + s0 * 16);             \
            cp16(sa_ + off, ab + (size_t)row * rs + s0 * 16);                  \
            cp16(sb_ + off, bb + (size_t)row * rs + s0 * 16);                  \
        }                                                                      \
    }

    MAINLOOP(SC_LOAD)

#pragma unroll
    for (int i = 0; i < 4; i++) {
#pragma unroll
        for (int j = 0; j < 4; j++) {
            int m = bm + wm * 64 + i * 16 + (lane >> 2);
            int n = bn + wn * 32 + j * 8 + (lane & 3) * 2;
            float mk0 = __ldg(mask + b * Sk + n);
            float mk1 = __ldg(mask + b * Sk + n + 1);
            float2 v0 = make_float2(acc[i][j][0] * scale + mk0,
                                    acc[i][j][1] * scale + mk1);
            float2 v1 = make_float2(acc[i][j][2] * scale + mk0,
                                    acc[i][j][3] * scale + mk1);
            *reinterpret_cast<float2*>(Sout + ((size_t)bh * Sq + m) * Sk + n) = v0;
            *reinterpret_cast<float2*>(Sout + ((size_t)bh * Sq + m + 8) * Sk + n) = v1;
        }
    }
}

// ---------------------------------------------------------------------------
// softmax + split
// ---------------------------------------------------------------------------
__global__ __launch_bounds__(256) void softmax_split(
    const float* __restrict__ S, bf16* __restrict__ Ph, bf16* __restrict__ Pl,
    int rows, int n) {
    int row = (blockIdx.x * blockDim.x + threadIdx.x) >> 5;
    int lane = threadIdx.x & 31;
    if (row >= rows) return;
    const float2* r2 = reinterpret_cast<const float2*>(S + (size_t)row * n);
    const int np = n >> 6;

    float v[16];
    float mx = -INFINITY;
#pragma unroll
    for (int c = 0; c < 8; c++) {
        if (c >= np) break;
        float2 t = r2[lane + c * 32];
        v[2 * c] = t.x; v[2 * c + 1] = t.y;
        mx = fmaxf(mx, fmaxf(t.x, t.y));
    }
#pragma unroll
    for (int o = 16; o; o >>= 1) mx = fmaxf(mx, __shfl_xor_sync(0xffffffffu, mx, o));

    float sum = 0.f;
#pragma unroll
    for (int c = 0; c < 8; c++) {
        if (c >= np) break;
        float e0 = __expf(v[2 * c] - mx);
        float e1 = __expf(v[2 * c + 1] - mx);
        v[2 * c] = e0; v[2 * c + 1] = e1;
        sum += e0 + e1;
    }
#pragma unroll
    for (int o = 16; o; o >>= 1) sum += __shfl_xor_sync(0xffffffffu, sum, o);
    float inv = 1.f / sum;

    uint32_t* ph32 = reinterpret_cast<uint32_t*>(Ph + (size_t)row * n);
    uint32_t* pl32 = reinterpret_cast<uint32_t*>(Pl + (size_t)row * n);
#pragma unroll
    for (int c = 0; c < 8; c++) {
        if (c >= np) break;
        float p0 = v[2 * c] * inv, p1 = v[2 * c + 1] * inv;
        bf16 h0 = __float2bfloat16(p0), h1 = __float2bfloat16(p1);
        float l0 = p0 - __bfloat162float(h0), l1 = p1 - __bfloat162float(h1);
        ph32[lane + c * 32] = packbf(h0, h1);
        pl32[lane + c * 32] = packbf(__float2bfloat16(l0), __float2bfloat16(l1));
    }
}

// ---------------------------------------------------------------------------
// ctx HMMA
// ---------------------------------------------------------------------------
__global__ __launch_bounds__(256) void hmma_ctx(
    const bf16* __restrict__ Ph, const bf16* __restrict__ Pl,
    const bf16* __restrict__ Vth, const bf16* __restrict__ Vtl,
    float* __restrict__ O, int Sq, int Sk) {
    extern __shared__ __align__(128) char smem[];
    const uint32_t asb = smem_u32(smem);
    const uint32_t bsb = asb + NSTAGE * TILEB;

    const int tid = threadIdx.x;
    const int wid = tid >> 5, lane = tid & 31;
    const int wm = wid >> 2, wn = wid & 3;
    const int bh = blockIdx.z, b = bh >> 3, h = bh & 7;
    const int bm = blockIdx.y * 128;
    const int nk = Sk / 32;
    const int C = 3 * nk;

    float acc[4][4][4];
#pragma unroll
    for (int i = 0; i < 4; i++)
#pragma unroll
        for (int j = 0; j < 4; j++)
#pragma unroll
            for (int r = 0; r < 4; r++) acc[i][j][r] = 0.f;

    const int r0 = tid >> 2, s0 = (tid & 3);
    const uint32_t a_lm = (uint32_t)((wm * 64 + (lane & 15)) * (PADK * 2) + (lane >> 4) * 16);
    const uint32_t b_lm = (uint32_t)((wn * 32 + (lane & 15)) * (PADK * 2) + (lane >> 4) * 16);

#define CTX_LOAD {                                                             \
        const int p = c_ / nk, kc = c_ - p * nk;                               \
        const bf16* Ap = (p < 2) ? Ph : Pl;                                    \
        const bf16* Bp = (p == 1) ? Vtl : Vth;                                 \
        const char* ab = (const char*)(Ap + ((size_t)bh * Sq + bm) * Sk + kc * 32); \
        const char* bb = (const char*)(Bp + (size_t)bh * DD * Sk + kc * 32);   \
        const size_t rs = (size_t)Sk * 2;                                      \
        const uint32_t sa_ = asb + stg_ * TILEB;                               \
        const uint32_t sb_ = bsb + stg_ * TILEB;                               \
        _Pragma("unroll")                                                      \
        for (int u = 0; u < 2; u++) {                                          \
            int row = r0 + u * 64;                                             \
            uint32_t off = (uint32_t)(row * (PADK * 2) + s0 * 16);             \
            cp16(sa_ + off, ab + (size_t)row * rs + s0 * 16);                  \
            cp16(sb_ + off, bb + (size_t)row * rs + s0 * 16);                  \
        }                                                                      \
    }

    MAINLOOP(CTX_LOAD)

#pragma unroll
    for (int i = 0; i < 4; i++) {
#pragma unroll
        for (int j = 0; j < 4; j++) {
            int m = bm + wm * 64 + i * 16 + (lane >> 2);
            int d = wn * 32 + j * 8 + (lane & 3) * 2;
            float2 v0 = make_float2(acc[i][j][0], acc[i][j][1]);
            float2 v1 = make_float2(acc[i][j][2], acc[i][j][3]);
            *reinterpret_cast<float2*>(
                O + ((size_t)(b * Sq + m) * HH + h) * DD + d) = v0;
            *reinterpret_cast<float2*>(
                O + ((size_t)(b * Sq + m + 8) * HH + h) * DD + d) = v1;
        }
    }
}

// ---------------------------------------------------------------------------
extern "C" void kernel_launch(void* const* d_in, const int* in_sizes, int n_in,
                              void* d_out, int out_size) {
    const float* x1    = (const float*)d_in[0];
    const float* mask1 = (const float*)d_in[1];
    const float* x2    = (const float*)d_in[2];
    const float* mask2 = (const float*)d_in[3];
    const float* W1[3] = {(const float*)d_in[4], (const float*)d_in[6], (const float*)d_in[8]};
    const float* b1[3] = {(const float*)d_in[5], (const float*)d_in[7], (const float*)d_in[9]};
    const float* W2[3] = {(const float*)d_in[10], (const float*)d_in[12], (const float*)d_in[14]};
    const float* b2[3] = {(const float*)d_in[11], (const float*)d_in[13], (const float*)d_in[15]};
    float* out = (float*)d_out;

    float *q1, *k1, *v1, *q2, *k2, *v2, *p1, *p2;
    cudaGetSymbolAddress((void**)&q1, g_q1);
    cudaGetSymbolAddress((void**)&k1, g_k1);
    cudaGetSymbolAddress((void**)&v1, g_v1);
    cudaGetSymbolAddress((void**)&q2, g_q2);
    cudaGetSymbolAddress((void**)&k2, g_k2);
    cudaGetSymbolAddress((void**)&v2, g_v2);
    cudaGetSymbolAddress((void**)&p1, g_p1);
    cudaGetSymbolAddress((void**)&p2, g_p2);

    bf16 *x1h, *x1l, *x2h, *x2l, *w1h, *w1l, *w2h, *w2l;
    cudaGetSymbolAddress((void**)&x1h, g_x1h);
    cudaGetSymbolAddress((void**)&x1l, g_x1l);
    cudaGetSymbolAddress((void**)&x2h, g_x2h);
    cudaGetSymbolAddress((void**)&x2l, g_x2l);
    cudaGetSymbolAddress((void**)&w1h, g_w1h);
    cudaGetSymbolAddress((void**)&w1l, g_w1l);
    cudaGetSymbolAddress((void**)&w2h, g_w2h);
    cudaGetSymbolAddress((void**)&w2l, g_w2l);

    bf16 *q1h, *q1l, *k1h, *k1l, *v1th, *v1tl;
    bf16 *q2h, *q2l, *k2h, *k2l, *v2th, *v2tl;
    cudaGetSymbolAddress((void**)&q1h, g_q1h); cudaGetSymbolAddress((void**)&q1l, g_q1l);
    cudaGetSymbolAddress((void**)&k1h, g_k1h); cudaGetSymbolAddress((void**)&k1l, g_k1l);
    cudaGetSymbolAddress((void**)&v1th, g_v1th); cudaGetSymbolAddress((void**)&v1tl, g_v1tl);
    cudaGetSymbolAddress((void**)&q2h, g_q2h); cudaGetSymbolAddress((void**)&q2l, g_q2l);
    cudaGetSymbolAddress((void**)&k2h, g_k2h); cudaGetSymbolAddress((void**)&k2l, g_k2l);
    cudaGetSymbolAddress((void**)&v2th, g_v2th); cudaGetSymbolAddress((void**)&v2tl, g_v2tl);

    bf16 *p1h, *p1l, *p2h, *p2l;
    cudaGetSymbolAddress((void**)&p1h, g_p1h); cudaGetSymbolAddress((void**)&p1l, g_p1l);
    cudaGetSymbolAddress((void**)&p2h, g_p2h); cudaGetSymbolAddress((void**)&p2l, g_p2l);

    // raise dynamic smem limits (no-op after first call; not a guard, not an alloc)
    cudaFuncSetAttribute(hmma_gemm3, cudaFuncAttributeMaxDynamicSharedMemorySize, SMEM_DYN);
    cudaFuncSetAttribute(hmma_scores, cudaFuncAttributeMaxDynamicSharedMemorySize, SMEM_DYN);
    cudaFuncSetAttribute(hmma_ctx, cudaFuncAttributeMaxDynamicSharedMemorySize, SMEM_DYN);

    const float scale = 1.0f / sqrtf((float)DD);
    dim3 blk(256);

    // input splits
    {
        int n4 = 4096 * 1024 / 4;
        xsplit<<<n4 / 256, 256>>>((const float4*)x1, (uint2*)x1h, (uint2*)x1l, n4);
    }
    {
        int n4 = 8192 * 768 / 4;
        xsplit<<<n4 / 256, 256>>>((const float4*)x2, (uint2*)x2h, (uint2*)x2l, n4);
    }
    {
        WS ws;
        for (int i = 0; i < 3; i++) {
            ws.W[i] = W1[i];
            ws.Wh[i] = w1h + (size_t)i * 1024 * 1024;
            ws.Wl[i] = w1l + (size_t)i * 1024 * 1024;
            ws.K[i] = 1024;
            ws.W[3 + i] = W2[i];
            ws.Wh[3 + i] = w2h + (size_t)i * 1024 * 768;
            ws.Wl[3 + i] = w2l + (size_t)i * 1024 * 768;
            ws.K[3 + i] = 768;
        }
        wsplit_all<<<dim3(32, 32, 6), dim3(32, 8)>>>(ws);
    }

    // QKV projections
    {
        G3 g;
        for (int i = 0; i < 3; i++) {
            g.Wh[i] = w1h + (size_t)i * 1024 * 1024;
            g.Wl[i] = w1l + (size_t)i * 1024 * 1024;
            g.bias[i] = b1[i];
        }
        g.out[0] = q1; g.out[1] = k1; g.out[2] = v1;
        hmma_gemm3<<<dim3(8, 32, 3), blk, SMEM_DYN>>>(x1h, x1l, g, BB * SS1, 1024);
    }
    {
        G3 g;
        for (int i = 0; i < 3; i++) {
            g.Wh[i] = w2h + (size_t)i * 1024 * 768;
            g.Wl[i] = w2l + (size_t)i * 1024 * 768;
            g.bias[i] = b2[i];
        }
        g.out[0] = q2; g.out[1] = k2; g.out[2] = v2;
        hmma_gemm3<<<dim3(8, 64, 3), blk, SMEM_DYN>>>(x2h, x2l, g, BB * SS2, 768);
    }

    // q/k splits + V transposes
    {
        int n4 = BB * SS1 * HD / 4;
        xsplit<<<n4 / 256, 256>>>((const float4*)q1, (uint2*)q1h, (uint2*)q1l, n4);
        xsplit<<<n4 / 256, 256>>>((const float4*)k1, (uint2*)k1h, (uint2*)k1l, n4);
    }
    {
        int n4 = BB * SS2 * HD / 4;
        xsplit<<<n4 / 256, 256>>>((const float4*)q2, (uint2*)q2h, (uint2*)q2l, n4);
        xsplit<<<n4 / 256, 256>>>((const float4*)k2, (uint2*)k2h, (uint2*)k2l, n4);
    }
    vtrans<<<dim3(4, SS1 / 32, BB * HH), dim3(32, 8)>>>(v1, v1th, v1tl, SS1);
    vtrans<<<dim3(4, SS2 / 32, BB * HH), dim3(32, 8)>>>(v2, v2th, v2tl, SS2);

    // attention 1: q2 over (k1, v1) -> out[0:C1]
    hmma_scores<<<dim3(SS1 / 128, SS2 / 128, BB * HH), blk, SMEM_DYN>>>(
        q2h, q2l, k1h, k1l, mask1, p1, SS2, SS1, scale);
    softmax_split<<<(BB * HH * SS2) / 8, blk>>>(p1, p1h, p1l, BB * HH * SS2, SS1);
    hmma_ctx<<<dim3(1, SS2 / 128, BB * HH), blk, SMEM_DYN>>>(p1h, p1l, v1th, v1tl, out, SS2, SS1);

    // attention 2: q1 over (k2, v2) -> out[C1:]
    hmma_scores<<<dim3(SS2 / 128, SS1 / 128, BB * HH), blk, SMEM_DYN>>>(
        q1h, q1l, k2h, k2l, mask2, p2, SS1, SS2, scale);
    softmax_split<<<(BB * HH * SS1) / 8, blk>>>(p2, p2h, p2l, BB * HH * SS1, SS2);
    hmma_ctx<<<dim3(1, SS1 / 128, BB * HH), blk, SMEM_DYN>>>(p2h, p2l, v2th, v2tl, out + C1_ELEMS, SS1, SS2);
}

// round 10
// speedup vs baseline: 2.5250x; 1.3172x over previous
#include <cuda_runtime.h>
#include <cuda_bf16.h>
#include <cuda_fp16.h>
#include <cstdint>
#include <math.h>

// ===========================================================================
// BertBiAttention on GB300 (sm_103 ptxas target -> mma.sync HMMA everywhere)
//   B=16, S1=256, S2=512, V_HID=1024, T_HID=768, BI_HID=1024, H=8, D=128
// Round 10: fp16 2-pass split compensation (A = Ah+Al fp16, B single fp16)
//   replaces bf16 3-pass -> 33% fewer MMAs/loads in every GEMM.
//   4-stage cp.async ring mainloop unchanged. fp32 accum throughout.
// ===========================================================================

#define BB   16
#define SS1  256
#define SS2  512
#define HH   8
#define DD   128
#define HD   1024
#define C1_ELEMS ((size_t)BB * SS2 * HD)

typedef __half hf;

#define PADK 40
#define NSTAGE 4
#define TILEB (128 * PADK * 2)          // 10240 bytes per tile
#define SMEM_DYN (2 * NSTAGE * TILEB)   // 81920 bytes

// ---------------- scratch ----------------
__device__ float g_q1[BB * SS1 * HD];
__device__ float g_k1[BB * SS1 * HD];
__device__ float g_v1[BB * SS1 * HD];
__device__ float g_q2[BB * SS2 * HD];
__device__ float g_k2[BB * SS2 * HD];
__device__ float g_v2[BB * SS2 * HD];
__device__ float g_p1[(size_t)BB * HH * SS2 * SS1];
__device__ float g_p2[(size_t)BB * HH * SS1 * SS2];

__device__ hf g_x1h[4096 * 1024];
__device__ hf g_x1l[4096 * 1024];
__device__ hf g_x2h[8192 * 768];
__device__ hf g_x2l[8192 * 768];
__device__ hf g_w1h[3][1024 * 1024];   // transposed [N][K], single fp16
__device__ hf g_w2h[3][1024 * 768];

__device__ hf g_q1h[BB * SS1 * HD]; __device__ hf g_q1l[BB * SS1 * HD];
__device__ hf g_k1h[BB * SS1 * HD];
__device__ hf g_v1th[BB * HH * DD * SS1];
__device__ hf g_q2h[BB * SS2 * HD]; __device__ hf g_q2l[BB * SS2 * HD];
__device__ hf g_k2h[BB * SS2 * HD];
__device__ hf g_v2th[BB * HH * DD * SS2];

#define P_ELEMS ((size_t)BB * HH * SS2 * SS1)
__device__ hf g_p1h[P_ELEMS]; __device__ hf g_p1l[P_ELEMS];
__device__ hf g_p2h[P_ELEMS]; __device__ hf g_p2l[P_ELEMS];

// ---------------- helpers ----------------
__device__ __forceinline__ uint32_t smem_u32(const void* p) {
    uint32_t a;
    asm("{ .reg .u64 t; cvta.to.shared.u64 t, %1; cvt.u32.u64 %0, t; }"
        : "=r"(a) : "l"(p));
    return a;
}
__device__ __forceinline__ void cp16(uint32_t dst, const void* src) {
    asm volatile("cp.async.cg.shared.global [%0], [%1], 16;\n" :: "r"(dst), "l"(src));
}
__device__ __forceinline__ void ldsm_x4(uint32_t& r0, uint32_t& r1,
                                        uint32_t& r2, uint32_t& r3, uint32_t a) {
    asm volatile("ldmatrix.sync.aligned.m8n8.x4.shared.b16 {%0,%1,%2,%3}, [%4];"
                 : "=r"(r0), "=r"(r1), "=r"(r2), "=r"(r3) : "r"(a));
}
__device__ __forceinline__ void mma16816(float* c, uint32_t a0, uint32_t a1,
                                         uint32_t a2, uint32_t a3,
                                         uint32_t b0, uint32_t b1) {
    asm volatile(
        "mma.sync.aligned.m16n8k16.row.col.f32.f16.f16.f32 "
        "{%0,%1,%2,%3}, {%4,%5,%6,%7}, {%8,%9}, {%0,%1,%2,%3};"
        : "+f"(c[0]), "+f"(c[1]), "+f"(c[2]), "+f"(c[3])
        : "r"(a0), "r"(a1), "r"(a2), "r"(a3), "r"(b0), "r"(b1));
}
__device__ __forceinline__ uint32_t packhf(hf a, hf b) {
    __half2 t = __halves2half2(a, b);
    return *reinterpret_cast<uint32_t*>(&t);
}

// ---------------- split/convert kernels ----------------
// split into fp16 hi + fp16 residual
__global__ void xsplit(const float4* __restrict__ x,
                       uint2* __restrict__ h, uint2* __restrict__ l, int n4) {
    int i = blockIdx.x * blockDim.x + threadIdx.x;
    if (i >= n4) return;
    float4 v = x[i];
    hf h0 = __float2half(v.x), h1 = __float2half(v.y);
    hf h2 = __float2half(v.z), h3 = __float2half(v.w);
    float r0 = v.x - __half2float(h0), r1 = v.y - __half2float(h1);
    float r2 = v.z - __half2float(h2), r3 = v.w - __half2float(h3);
    uint2 hp, lp;
    hp.x = packhf(h0, h1); hp.y = packhf(h2, h3);
    lp.x = packhf(__float2half(r0), __float2half(r1));
    lp.y = packhf(__float2half(r2), __float2half(r3));
    h[i] = hp; l[i] = lp;
}

// single fp16 convert (no residual) for B-side operands
__global__ void xcvt(const float4* __restrict__ x, uint2* __restrict__ h, int n4) {
    int i = blockIdx.x * blockDim.x + threadIdx.x;
    if (i >= n4) return;
    float4 v = x[i];
    uint2 hp;
    hp.x = packhf(__float2half(v.x), __float2half(v.y));
    hp.y = packhf(__float2half(v.z), __float2half(v.w));
    h[i] = hp;
}

struct WS {
    const float* W[6];
    hf* Wh[6];
    int K[6];
};

__global__ void wsplit_all(WS ws) {
    const int z = blockIdx.z;
    const int K = ws.K[z];
    const int N = 1024;
    const int k0 = blockIdx.y * 32, n0 = blockIdx.x * 32;
    if (k0 >= K) return;
    __shared__ float t[32][33];
    const float* W = ws.W[z];
    hf* Wh = ws.Wh[z];
    int tx = threadIdx.x, ty = threadIdx.y;
#pragma unroll
    for (int i = 0; i < 4; i++)
        t[ty + i * 8][tx] = W[(size_t)(k0 + ty + i * 8) * N + n0 + tx];
    __syncthreads();
#pragma unroll
    for (int i = 0; i < 4; i++) {
        float v = t[tx][ty + i * 8];
        size_t o = (size_t)(n0 + ty + i * 8) * K + k0 + tx;
        Wh[o] = __float2half(v);
    }
}

__global__ void vtrans(const float* __restrict__ V,
                       hf* __restrict__ Vth, int S) {
    __shared__ float t[32][33];
    const int bh = blockIdx.z, b = bh >> 3, h = bh & 7;
    const int d0 = blockIdx.x * 32, s0 = blockIdx.y * 32;
    const int tx = threadIdx.x, ty = threadIdx.y;
#pragma unroll
    for (int i = 0; i < 4; i++)
        t[ty + i * 8][tx] =
            V[(size_t)(b * S + s0 + ty + i * 8) * HD + h * DD + d0 + tx];
    __syncthreads();
#pragma unroll
    for (int i = 0; i < 4; i++) {
        float v = t[tx][ty + i * 8];
        size_t o = ((size_t)bh * DD + d0 + ty + i * 8) * S + s0 + tx;
        Vth[o] = __float2half(v);
    }
}

// ===========================================================================
// 4-stage pipelined mainloop (unchanged pattern):
//   prologue: load stages 0..2
//   iter c:   wait_group 2; sync; compute(c); load(c+3); commit
// ===========================================================================

#define MAINLOOP(LOADBODY)                                                     \
    for (int s = 0; s < NSTAGE - 1; ++s) {                                     \
        if (s < C) { const int c_ = s; const int stg_ = s; LOADBODY }          \
        asm volatile("cp.async.commit_group;\n");                              \
    }                                                                          \
    for (int c = 0; c < C; ++c) {                                              \
        asm volatile("cp.async.wait_group %0;\n" :: "n"(NSTAGE - 2));          \
        __syncthreads();                                                       \
        const int buf = c & (NSTAGE - 1);                                      \
        const uint32_t sa = asb + buf * TILEB + a_lm;                          \
        const uint32_t sb2 = bsb + buf * TILEB + b_lm;                         \
        _Pragma("unroll")                                                      \
        for (int kk = 0; kk < 2; kk++) {                                       \
            uint32_t a[4][4], bbf[2][4];                                       \
            _Pragma("unroll")                                                  \
            for (int i = 0; i < 4; i++)                                        \
                ldsm_x4(a[i][0], a[i][1], a[i][2], a[i][3],                    \
                        sa + i * 16 * (PADK * 2) + kk * 32);                   \
            _Pragma("unroll")                                                  \
            for (int j2 = 0; j2 < 2; j2++)                                     \
                ldsm_x4(bbf[j2][0], bbf[j2][1], bbf[j2][2], bbf[j2][3],        \
                        sb2 + j2 * 16 * (PADK * 2) + kk * 32);                 \
            _Pragma("unroll")                                                  \
            for (int i = 0; i < 4; i++)                                        \
                _Pragma("unroll")                                              \
                for (int j = 0; j < 4; j++) {                                  \
                    int j2 = j >> 1, jo = j & 1;                               \
                    mma16816(acc[i][j], a[i][0], a[i][1], a[i][2], a[i][3],    \
                             bbf[j2][jo], bbf[j2][jo + 2]);                    \
                }                                                              \
        }                                                                      \
        if (c + NSTAGE - 1 < C) {                                              \
            const int c_ = c + NSTAGE - 1;                                     \
            const int stg_ = c_ & (NSTAGE - 1);                                \
            LOADBODY                                                           \
        }                                                                      \
        asm volatile("cp.async.commit_group;\n");                              \
    }

// ---------------------------------------------------------------------------
// QKV HMMA GEMM: 2-pass (Ah.W + Al.W)
// ---------------------------------------------------------------------------
struct G3 {
    const hf* Wh[3];
    const float* bias[3];
    float* out[3];
};

__global__ __launch_bounds__(256) void hmma_gemm3(
    const hf* __restrict__ Ah, const hf* __restrict__ Al,
    G3 g, int M, int K) {
    const int N = 1024;
    extern __shared__ __align__(128) char smem[];
    const uint32_t asb = smem_u32(smem);
    const uint32_t bsb = asb + NSTAGE * TILEB;

    const int tid = threadIdx.x;
    const int wid = tid >> 5, lane = tid & 31;
    const int wm = wid >> 2, wn = wid & 3;
    const int z = blockIdx.z;
    const int bm = blockIdx.y * 128, bn = blockIdx.x * 128;
    const int nk = K / 32;
    const int C = 2 * nk;

    const hf* Wh = g.Wh[z];

    float acc[4][4][4];
#pragma unroll
    for (int i = 0; i < 4; i++)
#pragma unroll
        for (int j = 0; j < 4; j++)
#pragma unroll
            for (int r = 0; r < 4; r++) acc[i][j][r] = 0.f;

    const int r0 = tid >> 2, s0 = (tid & 3);
    const uint32_t a_lm = (uint32_t)((wm * 64 + (lane & 15)) * (PADK * 2) + (lane >> 4) * 16);
    const uint32_t b_lm = (uint32_t)((wn * 32 + (lane & 15)) * (PADK * 2) + (lane >> 4) * 16);

#define QKV_LOAD {                                                             \
        const int p = c_ / nk, kc = c_ - p * nk;                               \
        const hf* Ap = (p == 0) ? Ah : Al;                                     \
        const char* ab = (const char*)(Ap + (size_t)bm * K + kc * 32);         \
        const char* bb = (const char*)(Wh + (size_t)bn * K + kc * 32);         \
        const size_t rs = (size_t)K * 2;                                       \
        const uint32_t sa_ = asb + stg_ * TILEB;                               \
        const uint32_t sb_ = bsb + stg_ * TILEB;                               \
        _Pragma("unroll")                                                      \
        for (int u = 0; u < 2; u++) {                                          \
            int row = r0 + u * 64;                                             \
            uint32_t off = (uint32_t)(row * (PADK * 2) + s0 * 16);             \
            cp16(sa_ + off, ab + (size_t)row * rs + s0 * 16);                  \
            cp16(sb_ + off, bb + (size_t)row * rs + s0 * 16);                  \
        }                                                                      \
    }

    MAINLOOP(QKV_LOAD)

    float* outp = g.out[z];
    const float* bias = g.bias[z];
#pragma unroll
    for (int i = 0; i < 4; i++) {
#pragma unroll
        for (int j = 0; j < 4; j++) {
            int m = bm + wm * 64 + i * 16 + (lane >> 2);
            int n = bn + wn * 32 + j * 8 + (lane & 3) * 2;
            float b0 = __ldg(bias + n), b1 = __ldg(bias + n + 1);
            float2 v0 = make_float2(acc[i][j][0] + b0, acc[i][j][1] + b1);
            float2 v1 = make_float2(acc[i][j][2] + b0, acc[i][j][3] + b1);
            *reinterpret_cast<float2*>(outp + (size_t)m * N + n) = v0;
            *reinterpret_cast<float2*>(outp + (size_t)(m + 8) * N + n) = v1;
        }
    }
}

// ---------------------------------------------------------------------------
// scores HMMA: 2-pass (Qh.K + Ql.K)
// ---------------------------------------------------------------------------
__global__ __launch_bounds__(256) void hmma_scores(
    const hf* __restrict__ Qh, const hf* __restrict__ Ql,
    const hf* __restrict__ Kh,
    const float* __restrict__ mask, float* __restrict__ Sout,
    int Sq, int Sk, float scale) {
    extern __shared__ __align__(128) char smem[];
    const uint32_t asb = smem_u32(smem);
    const uint32_t bsb = asb + NSTAGE * TILEB;

    const int tid = threadIdx.x;
    const int wid = tid >> 5, lane = tid & 31;
    const int wm = wid >> 2, wn = wid & 3;
    const int bh = blockIdx.z, b = bh >> 3, h = bh & 7;
    const int bm = blockIdx.y * 128, bn = blockIdx.x * 128;
    const int nk = 4;
    const int C = 8;

    float acc[4][4][4];
#pragma unroll
    for (int i = 0; i < 4; i++)
#pragma unroll
        for (int j = 0; j < 4; j++)
#pragma unroll
            for (int r = 0; r < 4; r++) acc[i][j][r] = 0.f;

    const int r0 = tid >> 2, s0 = (tid & 3);
    const uint32_t a_lm = (uint32_t)((wm * 64 + (lane & 15)) * (PADK * 2) + (lane >> 4) * 16);
    const uint32_t b_lm = (uint32_t)((wn * 32 + (lane & 15)) * (PADK * 2) + (lane >> 4) * 16);

#define SC_LOAD {                                                              \
        const int p = c_ / nk, kc = c_ - p * nk;                               \
        const hf* Ap = (p == 0) ? Qh : Ql;                                     \
        const char* ab = (const char*)(Ap + (size_t)(b * Sq + bm) * HD + h * DD + kc * 32); \
        const char* bb = (const char*)(Kh + (size_t)(b * Sk + bn) * HD + h * DD + kc * 32); \
        const size_t rs = (size_t)HD * 2;                                      \
        const uint32_t sa_ = asb + stg_ * TILEB;                               \
        const uint32_t sb_ = bsb + stg_ * TILEB;                               \
        _Pragma("unroll")                                                      \
        for (int u = 0; u < 2; u++) {                                          \
            int row = r0 + u * 64;                                             \
            uint32_t off = (uint32_t)(row * (PADK * 2) + s0 * 16);             \
            cp16(sa_ + off, ab + (size_t)row * rs + s0 * 16);                  \
            cp16(sb_ + off, bb + (size_t)row * rs + s0 * 16);                  \
        }                                                                      \
    }

    MAINLOOP(SC_LOAD)

#pragma unroll
    for (int i = 0; i < 4; i++) {
#pragma unroll
        for (int j = 0; j < 4; j++) {
            int m = bm + wm * 64 + i * 16 + (lane >> 2);
            int n = bn + wn * 32 + j * 8 + (lane & 3) * 2;
            float mk0 = __ldg(mask + b * Sk + n);
            float mk1 = __ldg(mask + b * Sk + n + 1);
            float2 v0 = make_float2(acc[i][j][0] * scale + mk0,
                                    acc[i][j][1] * scale + mk1);
            float2 v1 = make_float2(acc[i][j][2] * scale + mk0,
                                    acc[i][j][3] * scale + mk1);
            *reinterpret_cast<float2*>(Sout + ((size_t)bh * Sq + m) * Sk + n) = v0;
            *reinterpret_cast<float2*>(Sout + ((size_t)bh * Sq + m + 8) * Sk + n) = v1;
        }
    }
}

// ---------------------------------------------------------------------------
// softmax + split to fp16 hi/lo
// ---------------------------------------------------------------------------
__global__ __launch_bounds__(256) void softmax_split(
    const float* __restrict__ S, hf* __restrict__ Ph, hf* __restrict__ Pl,
    int rows, int n) {
    int row = (blockIdx.x * blockDim.x + threadIdx.x) >> 5;
    int lane = threadIdx.x & 31;
    if (row >= rows) return;
    const float2* r2 = reinterpret_cast<const float2*>(S + (size_t)row * n);
    const int np = n >> 6;

    float v[16];
    float mx = -INFINITY;
#pragma unroll
    for (int c = 0; c < 8; c++) {
        if (c >= np) break;
        float2 t = r2[lane + c * 32];
        v[2 * c] = t.x; v[2 * c + 1] = t.y;
        mx = fmaxf(mx, fmaxf(t.x, t.y));
    }
#pragma unroll
    for (int o = 16; o; o >>= 1) mx = fmaxf(mx, __shfl_xor_sync(0xffffffffu, mx, o));

    float sum = 0.f;
#pragma unroll
    for (int c = 0; c < 8; c++) {
        if (c >= np) break;
        float e0 = __expf(v[2 * c] - mx);
        float e1 = __expf(v[2 * c + 1] - mx);
        v[2 * c] = e0; v[2 * c + 1] = e1;
        sum += e0 + e1;
    }
#pragma unroll
    for (int o = 16; o; o >>= 1) sum += __shfl_xor_sync(0xffffffffu, sum, o);
    float inv = 1.f / sum;

    uint32_t* ph32 = reinterpret_cast<uint32_t*>(Ph + (size_t)row * n);
    uint32_t* pl32 = reinterpret_cast<uint32_t*>(Pl + (size_t)row * n);
#pragma unroll
    for (int c = 0; c < 8; c++) {
        if (c >= np) break;
        float p0 = v[2 * c] * inv, p1 = v[2 * c + 1] * inv;
        hf h0 = __float2half(p0), h1 = __float2half(p1);
        float l0 = p0 - __half2float(h0), l1 = p1 - __half2float(h1);
        ph32[lane + c * 32] = packhf(h0, h1);
        pl32[lane + c * 32] = packhf(__float2half(l0), __float2half(l1));
    }
}

// ---------------------------------------------------------------------------
// ctx HMMA: 2-pass (Ph.V + Pl.V)
// ---------------------------------------------------------------------------
__global__ __launch_bounds__(256) void hmma_ctx(
    const hf* __restrict__ Ph, const hf* __restrict__ Pl,
    const hf* __restrict__ Vth,
    float* __restrict__ O, int Sq, int Sk) {
    extern __shared__ __align__(128) char smem[];
    const uint32_t asb = smem_u32(smem);
    const uint32_t bsb = asb + NSTAGE * TILEB;

    const int tid = threadIdx.x;
    const int wid = tid >> 5, lane = tid & 31;
    const int wm = wid >> 2, wn = wid & 3;
    const int bh = blockIdx.z, b = bh >> 3, h = bh & 7;
    const int bm = blockIdx.y * 128;
    const int nk = Sk / 32;
    const int C = 2 * nk;

    float acc[4][4][4];
#pragma unroll
    for (int i = 0; i < 4; i++)
#pragma unroll
        for (int j = 0; j < 4; j++)
#pragma unroll
            for (int r = 0; r < 4; r++) acc[i][j][r] = 0.f;

    const int r0 = tid >> 2, s0 = (tid & 3);
    const uint32_t a_lm = (uint32_t)((wm * 64 + (lane & 15)) * (PADK * 2) + (lane >> 4) * 16);
    const uint32_t b_lm = (uint32_t)((wn * 32 + (lane & 15)) * (PADK * 2) + (lane >> 4) * 16);

#define CTX_LOAD {                                                             \
        const int p = c_ / nk, kc = c_ - p * nk;                               \
        const hf* Ap = (p == 0) ? Ph : Pl;                                     \
        const char* ab = (const char*)(Ap + ((size_t)bh * Sq + bm) * Sk + kc * 32); \
        const char* bb = (const char*)(Vth + (size_t)bh * DD * Sk + kc * 32);  \
        const size_t rs = (size_t)Sk * 2;                                      \
        const uint32_t sa_ = asb + stg_ * TILEB;                               \
        const uint32_t sb_ = bsb + stg_ * TILEB;                               \
        _Pragma("unroll")                                                      \
        for (int u = 0; u < 2; u++) {                                          \
            int row = r0 + u * 64;                                             \
            uint32_t off = (uint32_t)(row * (PADK * 2) + s0 * 16);             \
            cp16(sa_ + off, ab + (size_t)row * rs + s0 * 16);                  \
            cp16(sb_ + off, bb + (size_t)row * rs + s0 * 16);                  \
        }                                                                      \
    }

    MAINLOOP(CTX_LOAD)

#pragma unroll
    for (int i = 0; i < 4; i++) {
#pragma unroll
        for (int j = 0; j < 4; j++) {
            int m = bm + wm * 64 + i * 16 + (lane >> 2);
            int d = wn * 32 + j * 8 + (lane & 3) * 2;
            float2 v0 = make_float2(acc[i][j][0], acc[i][j][1]);
            float2 v1 = make_float2(acc[i][j][2], acc[i][j][3]);
            *reinterpret_cast<float2*>(
                O + ((size_t)(b * Sq + m) * HH + h) * DD + d) = v0;
            *reinterpret_cast<float2*>(
                O + ((size_t)(b * Sq + m + 8) * HH + h) * DD + d) = v1;
        }
    }
}

// ---------------------------------------------------------------------------
extern "C" void kernel_launch(void* const* d_in, const int* in_sizes, int n_in,
                              void* d_out, int out_size) {
    const float* x1    = (const float*)d_in[0];
    const float* mask1 = (const float*)d_in[1];
    const float* x2    = (const float*)d_in[2];
    const float* mask2 = (const float*)d_in[3];
    const float* W1[3] = {(const float*)d_in[4], (const float*)d_in[6], (const float*)d_in[8]};
    const float* b1[3] = {(const float*)d_in[5], (const float*)d_in[7], (const float*)d_in[9]};
    const float* W2[3] = {(const float*)d_in[10], (const float*)d_in[12], (const float*)d_in[14]};
    const float* b2[3] = {(const float*)d_in[11], (const float*)d_in[13], (const float*)d_in[15]};
    float* out = (float*)d_out;

    float *q1, *k1, *v1, *q2, *k2, *v2, *p1, *p2;
    cudaGetSymbolAddress((void**)&q1, g_q1);
    cudaGetSymbolAddress((void**)&k1, g_k1);
    cudaGetSymbolAddress((void**)&v1, g_v1);
    cudaGetSymbolAddress((void**)&q2, g_q2);
    cudaGetSymbolAddress((void**)&k2, g_k2);
    cudaGetSymbolAddress((void**)&v2, g_v2);
    cudaGetSymbolAddress((void**)&p1, g_p1);
    cudaGetSymbolAddress((void**)&p2, g_p2);

    hf *x1h, *x1l, *x2h, *x2l, *w1h, *w2h;
    cudaGetSymbolAddress((void**)&x1h, g_x1h);
    cudaGetSymbolAddress((void**)&x1l, g_x1l);
    cudaGetSymbolAddress((void**)&x2h, g_x2h);
    cudaGetSymbolAddress((void**)&x2l, g_x2l);
    cudaGetSymbolAddress((void**)&w1h, g_w1h);
    cudaGetSymbolAddress((void**)&w2h, g_w2h);

    hf *q1h, *q1l, *k1h, *v1th, *q2h, *q2l, *k2h, *v2th;
    cudaGetSymbolAddress((void**)&q1h, g_q1h); cudaGetSymbolAddress((void**)&q1l, g_q1l);
    cudaGetSymbolAddress((void**)&k1h, g_k1h);
    cudaGetSymbolAddress((void**)&v1th, g_v1th);
    cudaGetSymbolAddress((void**)&q2h, g_q2h); cudaGetSymbolAddress((void**)&q2l, g_q2l);
    cudaGetSymbolAddress((void**)&k2h, g_k2h);
    cudaGetSymbolAddress((void**)&v2th, g_v2th);

    hf *p1h, *p1l, *p2h, *p2l;
    cudaGetSymbolAddress((void**)&p1h, g_p1h); cudaGetSymbolAddress((void**)&p1l, g_p1l);
    cudaGetSymbolAddress((void**)&p2h, g_p2h); cudaGetSymbolAddress((void**)&p2l, g_p2l);

    cudaFuncSetAttribute(hmma_gemm3, cudaFuncAttributeMaxDynamicSharedMemorySize, SMEM_DYN);
    cudaFuncSetAttribute(hmma_scores, cudaFuncAttributeMaxDynamicSharedMemorySize, SMEM_DYN);
    cudaFuncSetAttribute(hmma_ctx, cudaFuncAttributeMaxDynamicSharedMemorySize, SMEM_DYN);

    const float scale = 1.0f / sqrtf((float)DD);
    dim3 blk(256);

    // input splits
    {
        int n4 = 4096 * 1024 / 4;
        xsplit<<<n4 / 256, 256>>>((const float4*)x1, (uint2*)x1h, (uint2*)x1l, n4);
    }
    {
        int n4 = 8192 * 768 / 4;
        xsplit<<<n4 / 256, 256>>>((const float4*)x2, (uint2*)x2h, (uint2*)x2l, n4);
    }
    {
        WS ws;
        for (int i = 0; i < 3; i++) {
            ws.W[i] = W1[i];
            ws.Wh[i] = w1h + (size_t)i * 1024 * 1024;
            ws.K[i] = 1024;
            ws.W[3 + i] = W2[i];
            ws.Wh[3 + i] = w2h + (size_t)i * 1024 * 768;
            ws.K[3 + i] = 768;
        }
        wsplit_all<<<dim3(32, 32, 6), dim3(32, 8)>>>(ws);
    }

    // QKV projections (2-pass fp16)
    {
        G3 g;
        for (int i = 0; i < 3; i++) {
            g.Wh[i] = w1h + (size_t)i * 1024 * 1024;
            g.bias[i] = b1[i];
        }
        g.out[0] = q1; g.out[1] = k1; g.out[2] = v1;
        hmma_gemm3<<<dim3(8, 32, 3), blk, SMEM_DYN>>>(x1h, x1l, g, BB * SS1, 1024);
    }
    {
        G3 g;
        for (int i = 0; i < 3; i++) {
            g.Wh[i] = w2h + (size_t)i * 1024 * 768;
            g.bias[i] = b2[i];
        }
        g.out[0] = q2; g.out[1] = k2; g.out[2] = v2;
        hmma_gemm3<<<dim3(8, 64, 3), blk, SMEM_DYN>>>(x2h, x2l, g, BB * SS2, 768);
    }

    // q split (A-side), k single convert (B-side), V transposes (B-side)
    {
        int n4 = BB * SS1 * HD / 4;
        xsplit<<<n4 / 256, 256>>>((const float4*)q1, (uint2*)q1h, (uint2*)q1l, n4);
        xcvt<<<n4 / 256, 256>>>((const float4*)k1, (uint2*)k1h, n4);
    }
    {
        int n4 = BB * SS2 * HD / 4;
        xsplit<<<n4 / 256, 256>>>((const float4*)q2, (uint2*)q2h, (uint2*)q2l, n4);
        xcvt<<<n4 / 256, 256>>>((const float4*)k2, (uint2*)k2h, n4);
    }
    vtrans<<<dim3(4, SS1 / 32, BB * HH), dim3(32, 8)>>>(v1, v1th, SS1);
    vtrans<<<dim3(4, SS2 / 32, BB * HH), dim3(32, 8)>>>(v2, v2th, SS2);

    // attention 1: q2 over (k1, v1) -> out[0:C1]
    hmma_scores<<<dim3(SS1 / 128, SS2 / 128, BB * HH), blk, SMEM_DYN>>>(
        q2h, q2l, k1h, mask1, p1, SS2, SS1, scale);
    softmax_split<<<(BB * HH * SS2) / 8, blk>>>(p1, p1h, p1l, BB * HH * SS2, SS1);
    hmma_ctx<<<dim3(1, SS2 / 128, BB * HH), blk, SMEM_DYN>>>(p1h, p1l, v1th, out, SS2, SS1);

    // attention 2: q1 over (k2, v2) -> out[C1:]
    hmma_scores<<<dim3(SS2 / 128, SS1 / 128, BB * HH), blk, SMEM_DYN>>>(
        q1h, q1l, k2h, mask2, p2, SS1, SS2, scale);
    softmax_split<<<(BB * HH * SS1) / 8, blk>>>(p2, p2h, p2l, BB * HH * SS1, SS2);
    hmma_ctx<<<dim3(1, SS1 / 128, BB * HH), blk, SMEM_DYN>>>(p2h, p2l, v2th, out + C1_ELEMS, SS1, SS2);
}

// round 11
// speedup vs baseline: 4.1394x; 1.6393x over previous
#include <cuda_runtime.h>
#include <cuda_fp16.h>
#include <cstdint>
#include <math.h>

// ===========================================================================
// BertBiAttention on GB300 (sm_103 ptxas target -> mma.sync HMMA everywhere)
//   B=16, S1=256, S2=512, V_HID=1024, T_HID=768, BI_HID=1024, H=8, D=128
// Round 11: single-pass fp16 in every GEMM (no residual compensation).
//   Predicted rel_err ~5e-4 (< 1e-3 gate). 4-stage cp.async ring unchanged.
//   fp32 accumulate throughout.
// ===========================================================================

#define BB   16
#define SS1  256
#define SS2  512
#define HH   8
#define DD   128
#define HD   1024
#define C1_ELEMS ((size_t)BB * SS2 * HD)

typedef __half hf;

#define PADK 40
#define NSTAGE 4
#define TILEB (128 * PADK * 2)          // 10240 bytes per tile
#define SMEM_DYN (2 * NSTAGE * TILEB)   // 81920 bytes

// ---------------- scratch ----------------
__device__ float g_q1[BB * SS1 * HD];
__device__ float g_k1[BB * SS1 * HD];
__device__ float g_v1[BB * SS1 * HD];
__device__ float g_q2[BB * SS2 * HD];
__device__ float g_k2[BB * SS2 * HD];
__device__ float g_v2[BB * SS2 * HD];
__device__ float g_p1[(size_t)BB * HH * SS2 * SS1];
__device__ float g_p2[(size_t)BB * HH * SS1 * SS2];

__device__ hf g_x1h[4096 * 1024];
__device__ hf g_x2h[8192 * 768];
__device__ hf g_w1h[3][1024 * 1024];   // transposed [N][K]
__device__ hf g_w2h[3][1024 * 768];

__device__ hf g_q1h[BB * SS1 * HD];
__device__ hf g_k1h[BB * SS1 * HD];
__device__ hf g_v1th[BB * HH * DD * SS1];
__device__ hf g_q2h[BB * SS2 * HD];
__device__ hf g_k2h[BB * SS2 * HD];
__device__ hf g_v2th[BB * HH * DD * SS2];

#define P_ELEMS ((size_t)BB * HH * SS2 * SS1)
__device__ hf g_p1h[P_ELEMS];
__device__ hf g_p2h[P_ELEMS];

// ---------------- helpers ----------------
__device__ __forceinline__ uint32_t smem_u32(const void* p) {
    uint32_t a;
    asm("{ .reg .u64 t; cvta.to.shared.u64 t, %1; cvt.u32.u64 %0, t; }"
        : "=r"(a) : "l"(p));
    return a;
}
__device__ __forceinline__ void cp16(uint32_t dst, const void* src) {
    asm volatile("cp.async.cg.shared.global [%0], [%1], 16;\n" :: "r"(dst), "l"(src));
}
__device__ __forceinline__ void ldsm_x4(uint32_t& r0, uint32_t& r1,
                                        uint32_t& r2, uint32_t& r3, uint32_t a) {
    asm volatile("ldmatrix.sync.aligned.m8n8.x4.shared.b16 {%0,%1,%2,%3}, [%4];"
                 : "=r"(r0), "=r"(r1), "=r"(r2), "=r"(r3) : "r"(a));
}
__device__ __forceinline__ void mma16816(float* c, uint32_t a0, uint32_t a1,
                                         uint32_t a2, uint32_t a3,
                                         uint32_t b0, uint32_t b1) {
    asm volatile(
        "mma.sync.aligned.m16n8k16.row.col.f32.f16.f16.f32 "
        "{%0,%1,%2,%3}, {%4,%5,%6,%7}, {%8,%9}, {%0,%1,%2,%3};"
        : "+f"(c[0]), "+f"(c[1]), "+f"(c[2]), "+f"(c[3])
        : "r"(a0), "r"(a1), "r"(a2), "r"(a3), "r"(b0), "r"(b1));
}
__device__ __forceinline__ uint32_t packhf(hf a, hf b) {
    __half2 t = __halves2half2(a, b);
    return *reinterpret_cast<uint32_t*>(&t);
}

// ---------------- convert kernels ----------------
__global__ void xcvt(const float4* __restrict__ x, uint2* __restrict__ h, int n4) {
    int i = blockIdx.x * blockDim.x + threadIdx.x;
    if (i >= n4) return;
    float4 v = x[i];
    uint2 hp;
    hp.x = packhf(__float2half(v.x), __float2half(v.y));
    hp.y = packhf(__float2half(v.z), __float2half(v.w));
    h[i] = hp;
}

struct WS {
    const float* W[6];
    hf* Wh[6];
    int K[6];
};

__global__ void wsplit_all(WS ws) {
    const int z = blockIdx.z;
    const int K = ws.K[z];
    const int N = 1024;
    const int k0 = blockIdx.y * 32, n0 = blockIdx.x * 32;
    if (k0 >= K) return;
    __shared__ float t[32][33];
    const float* W = ws.W[z];
    hf* Wh = ws.Wh[z];
    int tx = threadIdx.x, ty = threadIdx.y;
#pragma unroll
    for (int i = 0; i < 4; i++)
        t[ty + i * 8][tx] = W[(size_t)(k0 + ty + i * 8) * N + n0 + tx];
    __syncthreads();
#pragma unroll
    for (int i = 0; i < 4; i++) {
        float v = t[tx][ty + i * 8];
        size_t o = (size_t)(n0 + ty + i * 8) * K + k0 + tx;
        Wh[o] = __float2half(v);
    }
}

__global__ void vtrans(const float* __restrict__ V,
                       hf* __restrict__ Vth, int S) {
    __shared__ float t[32][33];
    const int bh = blockIdx.z, b = bh >> 3, h = bh & 7;
    const int d0 = blockIdx.x * 32, s0 = blockIdx.y * 32;
    const int tx = threadIdx.x, ty = threadIdx.y;
#pragma unroll
    for (int i = 0; i < 4; i++)
        t[ty + i * 8][tx] =
            V[(size_t)(b * S + s0 + ty + i * 8) * HD + h * DD + d0 + tx];
    __syncthreads();
#pragma unroll
    for (int i = 0; i < 4; i++) {
        float v = t[tx][ty + i * 8];
        size_t o = ((size_t)bh * DD + d0 + ty + i * 8) * S + s0 + tx;
        Vth[o] = __float2half(v);
    }
}

// ===========================================================================
// 4-stage pipelined mainloop:
//   prologue: load stages 0..2; iter c: wait 2; sync; compute(c); load(c+3)
// ===========================================================================

#define MAINLOOP(LOADBODY)                                                     \
    for (int s = 0; s < NSTAGE - 1; ++s) {                                     \
        if (s < C) { const int c_ = s; const int stg_ = s; LOADBODY }          \
        asm volatile("cp.async.commit_group;\n");                              \
    }                                                                          \
    for (int c = 0; c < C; ++c) {                                              \
        asm volatile("cp.async.wait_group %0;\n" :: "n"(NSTAGE - 2));          \
        __syncthreads();                                                       \
        const int buf = c & (NSTAGE - 1);                                      \
        const uint32_t sa = asb + buf * TILEB + a_lm;                          \
        const uint32_t sb2 = bsb + buf * TILEB + b_lm;                         \
        _Pragma("unroll")                                                      \
        for (int kk = 0; kk < 2; kk++) {                                       \
            uint32_t a[4][4], bbf[2][4];                                       \
            _Pragma("unroll")                                                  \
            for (int i = 0; i < 4; i++)                                        \
                ldsm_x4(a[i][0], a[i][1], a[i][2], a[i][3],                    \
                        sa + i * 16 * (PADK * 2) + kk * 32);                   \
            _Pragma("unroll")                                                  \
            for (int j2 = 0; j2 < 2; j2++)                                     \
                ldsm_x4(bbf[j2][0], bbf[j2][1], bbf[j2][2], bbf[j2][3],        \
                        sb2 + j2 * 16 * (PADK * 2) + kk * 32);                 \
            _Pragma("unroll")                                                  \
            for (int i = 0; i < 4; i++)                                        \
                _Pragma("unroll")                                              \
                for (int j = 0; j < 4; j++) {                                  \
                    int j2 = j >> 1, jo = j & 1;                               \
                    mma16816(acc[i][j], a[i][0], a[i][1], a[i][2], a[i][3],    \
                             bbf[j2][jo], bbf[j2][jo + 2]);                    \
                }                                                              \
        }                                                                      \
        if (c + NSTAGE - 1 < C) {                                              \
            const int c_ = c + NSTAGE - 1;                                     \
            const int stg_ = c_ & (NSTAGE - 1);                                \
            LOADBODY                                                           \
        }                                                                      \
        asm volatile("cp.async.commit_group;\n");                              \
    }

// ---------------------------------------------------------------------------
// QKV HMMA GEMM: single pass A.W
// ---------------------------------------------------------------------------
struct G3 {
    const hf* Wh[3];
    const float* bias[3];
    float* out[3];
};

__global__ __launch_bounds__(256) void hmma_gemm3(
    const hf* __restrict__ Ah, G3 g, int M, int K) {
    const int N = 1024;
    extern __shared__ __align__(128) char smem[];
    const uint32_t asb = smem_u32(smem);
    const uint32_t bsb = asb + NSTAGE * TILEB;

    const int tid = threadIdx.x;
    const int wid = tid >> 5, lane = tid & 31;
    const int wm = wid >> 2, wn = wid & 3;
    const int z = blockIdx.z;
    const int bm = blockIdx.y * 128, bn = blockIdx.x * 128;
    const int C = K / 32;

    const hf* Wh = g.Wh[z];

    float acc[4][4][4];
#pragma unroll
    for (int i = 0; i < 4; i++)
#pragma unroll
        for (int j = 0; j < 4; j++)
#pragma unroll
            for (int r = 0; r < 4; r++) acc[i][j][r] = 0.f;

    const int r0 = tid >> 2, s0 = (tid & 3);
    const uint32_t a_lm = (uint32_t)((wm * 64 + (lane & 15)) * (PADK * 2) + (lane >> 4) * 16);
    const uint32_t b_lm = (uint32_t)((wn * 32 + (lane & 15)) * (PADK * 2) + (lane >> 4) * 16);

#define QKV_LOAD {                                                             \
        const int kc = c_;                                                     \
        const char* ab = (const char*)(Ah + (size_t)bm * K + kc * 32);         \
        const char* bb = (const char*)(Wh + (size_t)bn * K + kc * 32);         \
        const size_t rs = (size_t)K * 2;                                       \
        const uint32_t sa_ = asb + stg_ * TILEB;                               \
        const uint32_t sb_ = bsb + stg_ * TILEB;                               \
        _Pragma("unroll")                                                      \
        for (int u = 0; u < 2; u++) {                                          \
            int row = r0 + u * 64;                                             \
            uint32_t off = (uint32_t)(row * (PADK * 2) + s0 * 16);             \
            cp16(sa_ + off, ab + (size_t)row * rs + s0 * 16);                  \
            cp16(sb_ + off, bb + (size_t)row * rs + s0 * 16);                  \
        }                                                                      \
    }

    MAINLOOP(QKV_LOAD)

    float* outp = g.out[z];
    const float* bias = g.bias[z];
#pragma unroll
    for (int i = 0; i < 4; i++) {
#pragma unroll
        for (int j = 0; j < 4; j++) {
            int m = bm + wm * 64 + i * 16 + (lane >> 2);
            int n = bn + wn * 32 + j * 8 + (lane & 3) * 2;
            float b0 = __ldg(bias + n), b1 = __ldg(bias + n + 1);
            float2 v0 = make_float2(acc[i][j][0] + b0, acc[i][j][1] + b1);
            float2 v1 = make_float2(acc[i][j][2] + b0, acc[i][j][3] + b1);
            *reinterpret_cast<float2*>(outp + (size_t)m * N + n) = v0;
            *reinterpret_cast<float2*>(outp + (size_t)(m + 8) * N + n) = v1;
        }
    }
}

// ---------------------------------------------------------------------------
// scores HMMA: single pass Q.K
// ---------------------------------------------------------------------------
__global__ __launch_bounds__(256) void hmma_scores(
    const hf* __restrict__ Qh, const hf* __restrict__ Kh,
    const float* __restrict__ mask, float* __restrict__ Sout,
    int Sq, int Sk, float scale) {
    extern __shared__ __align__(128) char smem[];
    const uint32_t asb = smem_u32(smem);
    const uint32_t bsb = asb + NSTAGE * TILEB;

    const int tid = threadIdx.x;
    const int wid = tid >> 5, lane = tid & 31;
    const int wm = wid >> 2, wn = wid & 3;
    const int bh = blockIdx.z, b = bh >> 3, h = bh & 7;
    const int bm = blockIdx.y * 128, bn = blockIdx.x * 128;
    const int C = 4;

    float acc[4][4][4];
#pragma unroll
    for (int i = 0; i < 4; i++)
#pragma unroll
        for (int j = 0; j < 4; j++)
#pragma unroll
            for (int r = 0; r < 4; r++) acc[i][j][r] = 0.f;

    const int r0 = tid >> 2, s0 = (tid & 3);
    const uint32_t a_lm = (uint32_t)((wm * 64 + (lane & 15)) * (PADK * 2) + (lane >> 4) * 16);
    const uint32_t b_lm = (uint32_t)((wn * 32 + (lane & 15)) * (PADK * 2) + (lane >> 4) * 16);

#define SC_LOAD {                                                              \
        const int kc = c_;                                                     \
        const char* ab = (const char*)(Qh + (size_t)(b * Sq + bm) * HD + h * DD + kc * 32); \
        const char* bb = (const char*)(Kh + (size_t)(b * Sk + bn) * HD + h * DD + kc * 32); \
        const size_t rs = (size_t)HD * 2;                                      \
        const uint32_t sa_ = asb + stg_ * TILEB;                               \
        const uint32_t sb_ = bsb + stg_ * TILEB;                               \
        _Pragma("unroll")                                                      \
        for (int u = 0; u < 2; u++) {                                          \
            int row = r0 + u * 64;                                             \
            uint32_t off = (uint32_t)(row * (PADK * 2) + s0 * 16);             \
            cp16(sa_ + off, ab + (size_t)row * rs + s0 * 16);                  \
            cp16(sb_ + off, bb + (size_t)row * rs + s0 * 16);                  \
        }                                                                      \
    }

    MAINLOOP(SC_LOAD)

#pragma unroll
    for (int i = 0; i < 4; i++) {
#pragma unroll
        for (int j = 0; j < 4; j++) {
            int m = bm + wm * 64 + i * 16 + (lane >> 2);
            int n = bn + wn * 32 + j * 8 + (lane & 3) * 2;
            float mk0 = __ldg(mask + b * Sk + n);
            float mk1 = __ldg(mask + b * Sk + n + 1);
            float2 v0 = make_float2(acc[i][j][0] * scale + mk0,
                                    acc[i][j][1] * scale + mk1);
            float2 v1 = make_float2(acc[i][j][2] * scale + mk0,
                                    acc[i][j][3] * scale + mk1);
            *reinterpret_cast<float2*>(Sout + ((size_t)bh * Sq + m) * Sk + n) = v0;
            *reinterpret_cast<float2*>(Sout + ((size_t)bh * Sq + m + 8) * Sk + n) = v1;
        }
    }
}

// ---------------------------------------------------------------------------
// softmax -> fp16 P
// ---------------------------------------------------------------------------
__global__ __launch_bounds__(256) void softmax_h(
    const float* __restrict__ S, hf* __restrict__ Ph, int rows, int n) {
    int row = (blockIdx.x * blockDim.x + threadIdx.x) >> 5;
    int lane = threadIdx.x & 31;
    if (row >= rows) return;
    const float2* r2 = reinterpret_cast<const float2*>(S + (size_t)row * n);
    const int np = n >> 6;

    float v[16];
    float mx = -INFINITY;
#pragma unroll
    for (int c = 0; c < 8; c++) {
        if (c >= np) break;
        float2 t = r2[lane + c * 32];
        v[2 * c] = t.x; v[2 * c + 1] = t.y;
        mx = fmaxf(mx, fmaxf(t.x, t.y));
    }
#pragma unroll
    for (int o = 16; o; o >>= 1) mx = fmaxf(mx, __shfl_xor_sync(0xffffffffu, mx, o));

    float sum = 0.f;
#pragma unroll
    for (int c = 0; c < 8; c++) {
        if (c >= np) break;
        float e0 = __expf(v[2 * c] - mx);
        float e1 = __expf(v[2 * c + 1] - mx);
        v[2 * c] = e0; v[2 * c + 1] = e1;
        sum += e0 + e1;
    }
#pragma unroll
    for (int o = 16; o; o >>= 1) sum += __shfl_xor_sync(0xffffffffu, sum, o);
    float inv = 1.f / sum;

    uint32_t* ph32 = reinterpret_cast<uint32_t*>(Ph + (size_t)row * n);
#pragma unroll
    for (int c = 0; c < 8; c++) {
        if (c >= np) break;
        float p0 = v[2 * c] * inv, p1 = v[2 * c + 1] * inv;
        ph32[lane + c * 32] = packhf(__float2half(p0), __float2half(p1));
    }
}

// ---------------------------------------------------------------------------
// ctx HMMA: single pass P.V
// ---------------------------------------------------------------------------
__global__ __launch_bounds__(256) void hmma_ctx(
    const hf* __restrict__ Ph, const hf* __restrict__ Vth,
    float* __restrict__ O, int Sq, int Sk) {
    extern __shared__ __align__(128) char smem[];
    const uint32_t asb = smem_u32(smem);
    const uint32_t bsb = asb + NSTAGE * TILEB;

    const int tid = threadIdx.x;
    const int wid = tid >> 5, lane = tid & 31;
    const int wm = wid >> 2, wn = wid & 3;
    const int bh = blockIdx.z, b = bh >> 3, h = bh & 7;
    const int bm = blockIdx.y * 128;
    const int C = Sk / 32;

    float acc[4][4][4];
#pragma unroll
    for (int i = 0; i < 4; i++)
#pragma unroll
        for (int j = 0; j < 4; j++)
#pragma unroll
            for (int r = 0; r < 4; r++) acc[i][j][r] = 0.f;

    const int r0 = tid >> 2, s0 = (tid & 3);
    const uint32_t a_lm = (uint32_t)((wm * 64 + (lane & 15)) * (PADK * 2) + (lane >> 4) * 16);
    const uint32_t b_lm = (uint32_t)((wn * 32 + (lane & 15)) * (PADK * 2) + (lane >> 4) * 16);

#define CTX_LOAD {                                                             \
        const int kc = c_;                                                     \
        const char* ab = (const char*)(Ph + ((size_t)bh * Sq + bm) * Sk + kc * 32); \
        const char* bb = (const char*)(Vth + (size_t)bh * DD * Sk + kc * 32);  \
        const size_t rs = (size_t)Sk * 2;                                      \
        const uint32_t sa_ = asb + stg_ * TILEB;                               \
        const uint32_t sb_ = bsb + stg_ * TILEB;                               \
        _Pragma("unroll")                                                      \
        for (int u = 0; u < 2; u++) {                                          \
            int row = r0 + u * 64;                                             \
            uint32_t off = (uint32_t)(row * (PADK * 2) + s0 * 16);             \
            cp16(sa_ + off, ab + (size_t)row * rs + s0 * 16);                  \
            cp16(sb_ + off, bb + (size_t)row * rs + s0 * 16);                  \
        }                                                                      \
    }

    MAINLOOP(CTX_LOAD)

#pragma unroll
    for (int i = 0; i < 4; i++) {
#pragma unroll
        for (int j = 0; j < 4; j++) {
            int m = bm + wm * 64 + i * 16 + (lane >> 2);
            int d = wn * 32 + j * 8 + (lane & 3) * 2;
            float2 v0 = make_float2(acc[i][j][0], acc[i][j][1]);
            float2 v1 = make_float2(acc[i][j][2], acc[i][j][3]);
            *reinterpret_cast<float2*>(
                O + ((size_t)(b * Sq + m) * HH + h) * DD + d) = v0;
            *reinterpret_cast<float2*>(
                O + ((size_t)(b * Sq + m + 8) * HH + h) * DD + d) = v1;
        }
    }
}

// ---------------------------------------------------------------------------
extern "C" void kernel_launch(void* const* d_in, const int* in_sizes, int n_in,
                              void* d_out, int out_size) {
    const float* x1    = (const float*)d_in[0];
    const float* mask1 = (const float*)d_in[1];
    const float* x2    = (const float*)d_in[2];
    const float* mask2 = (const float*)d_in[3];
    const float* W1[3] = {(const float*)d_in[4], (const float*)d_in[6], (const float*)d_in[8]};
    const float* b1[3] = {(const float*)d_in[5], (const float*)d_in[7], (const float*)d_in[9]};
    const float* W2[3] = {(const float*)d_in[10], (const float*)d_in[12], (const float*)d_in[14]};
    const float* b2[3] = {(const float*)d_in[11], (const float*)d_in[13], (const float*)d_in[15]};
    float* out = (float*)d_out;

    float *q1, *k1, *v1, *q2, *k2, *v2, *p1, *p2;
    cudaGetSymbolAddress((void**)&q1, g_q1);
    cudaGetSymbolAddress((void**)&k1, g_k1);
    cudaGetSymbolAddress((void**)&v1, g_v1);
    cudaGetSymbolAddress((void**)&q2, g_q2);
    cudaGetSymbolAddress((void**)&k2, g_k2);
    cudaGetSymbolAddress((void**)&v2, g_v2);
    cudaGetSymbolAddress((void**)&p1, g_p1);
    cudaGetSymbolAddress((void**)&p2, g_p2);

    hf *x1h, *x2h, *w1h, *w2h;
    cudaGetSymbolAddress((void**)&x1h, g_x1h);
    cudaGetSymbolAddress((void**)&x2h, g_x2h);
    cudaGetSymbolAddress((void**)&w1h, g_w1h);
    cudaGetSymbolAddress((void**)&w2h, g_w2h);

    hf *q1h, *k1h, *v1th, *q2h, *k2h, *v2th;
    cudaGetSymbolAddress((void**)&q1h, g_q1h);
    cudaGetSymbolAddress((void**)&k1h, g_k1h);
    cudaGetSymbolAddress((void**)&v1th, g_v1th);
    cudaGetSymbolAddress((void**)&q2h, g_q2h);
    cudaGetSymbolAddress((void**)&k2h, g_k2h);
    cudaGetSymbolAddress((void**)&v2th, g_v2th);

    hf *p1h, *p2h;
    cudaGetSymbolAddress((void**)&p1h, g_p1h);
    cudaGetSymbolAddress((void**)&p2h, g_p2h);

    cudaFuncSetAttribute(hmma_gemm3, cudaFuncAttributeMaxDynamicSharedMemorySize, SMEM_DYN);
    cudaFuncSetAttribute(hmma_scores, cudaFuncAttributeMaxDynamicSharedMemorySize, SMEM_DYN);
    cudaFuncSetAttribute(hmma_ctx, cudaFuncAttributeMaxDynamicSharedMemorySize, SMEM_DYN);

    const float scale = 1.0f / sqrtf((float)DD);
    dim3 blk(256);

    // input converts
    {
        int n4 = 4096 * 1024 / 4;
        xcvt<<<n4 / 256, 256>>>((const float4*)x1, (uint2*)x1h, n4);
    }
    {
        int n4 = 8192 * 768 / 4;
        xcvt<<<n4 / 256, 256>>>((const float4*)x2, (uint2*)x2h, n4);
    }
    {
        WS ws;
        for (int i = 0; i < 3; i++) {
            ws.W[i] = W1[i];
            ws.Wh[i] = w1h + (size_t)i * 1024 * 1024;
            ws.K[i] = 1024;
            ws.W[3 + i] = W2[i];
            ws.Wh[3 + i] = w2h + (size_t)i * 1024 * 768;
            ws.K[3 + i] = 768;
        }
        wsplit_all<<<dim3(32, 32, 6), dim3(32, 8)>>>(ws);
    }

    // QKV projections (single-pass fp16)
    {
        G3 g;
        for (int i = 0; i < 3; i++) {
            g.Wh[i] = w1h + (size_t)i * 1024 * 1024;
            g.bias[i] = b1[i];
        }
        g.out[0] = q1; g.out[1] = k1; g.out[2] = v1;
        hmma_gemm3<<<dim3(8, 32, 3), blk, SMEM_DYN>>>(x1h, g, BB * SS1, 1024);
    }
    {
        G3 g;
        for (int i = 0; i < 3; i++) {
            g.Wh[i] = w2h + (size_t)i * 1024 * 768;
            g.bias[i] = b2[i];
        }
        g.out[0] = q2; g.out[1] = k2; g.out[2] = v2;
        hmma_gemm3<<<dim3(8, 64, 3), blk, SMEM_DYN>>>(x2h, g, BB * SS2, 768);
    }

    // q/k converts + V transposes
    {
        int n4 = BB * SS1 * HD / 4;
        xcvt<<<n4 / 256, 256>>>((const float4*)q1, (uint2*)q1h, n4);
        xcvt<<<n4 / 256, 256>>>((const float4*)k1, (uint2*)k1h, n4);
    }
    {
        int n4 = BB * SS2 * HD / 4;
        xcvt<<<n4 / 256, 256>>>((const float4*)q2, (uint2*)q2h, n4);
        xcvt<<<n4 / 256, 256>>>((const float4*)k2, (uint2*)k2h, n4);
    }
    vtrans<<<dim3(4, SS1 / 32, BB * HH), dim3(32, 8)>>>(v1, v1th, SS1);
    vtrans<<<dim3(4, SS2 / 32, BB * HH), dim3(32, 8)>>>(v2, v2th, SS2);

    // attention 1: q2 over (k1, v1) -> out[0:C1]
    hmma_scores<<<dim3(SS1 / 128, SS2 / 128, BB * HH), blk, SMEM_DYN>>>(
        q2h, k1h, mask1, p1, SS2, SS1, scale);
    softmax_h<<<(BB * HH * SS2) / 8, blk>>>(p1, p1h, BB * HH * SS2, SS1);
    hmma_ctx<<<dim3(1, SS2 / 128, BB * HH), blk, SMEM_DYN>>>(p1h, v1th, out, SS2, SS1);

    // attention 2: q1 over (k2, v2) -> out[C1:]
    hmma_scores<<<dim3(SS2 / 128, SS1 / 128, BB * HH), blk, SMEM_DYN>>>(
        q1h, k2h, mask2, p2, SS1, SS2, scale);
    softmax_h<<<(BB * HH * SS1) / 8, blk>>>(p2, p2h, BB * HH * SS1, SS2);
    hmma_ctx<<<dim3(1, SS1 / 128, BB * HH), blk, SMEM_DYN>>>(p2h, v2th, out + C1_ELEMS, SS1, SS2);
}

// round 13
// speedup vs baseline: 4.3226x; 1.0443x over previous
#include <cuda_runtime.h>
#include <cuda_fp16.h>
#include <cstdint>
#include <math.h>

// ===========================================================================
// BertBiAttention on GB300 (sm_103 ptxas target -> mma.sync HMMA everywhere)
//   B=16, S1=256, S2=512, V_HID=1024, T_HID=768, BI_HID=1024, H=8, D=128
// Round 13 (= R12 re-bench after infra failure): fp16 single-pass GEMMs with
//   - QKV epilogue writing fp16 q/k/v directly (no fp32 staging, no xcvt)
//   - both QKV streams in ONE launch
//   - merged scores / softmax / vtrans / ctx launches (z-partitioned)
//   17 launches -> 8; ~130 MB staging traffic removed.
// ===========================================================================

#define BB   16
#define SS1  256
#define SS2  512
#define HH   8
#define DD   128
#define HD   1024
#define C1_ELEMS ((size_t)BB * SS2 * HD)

typedef __half hf;

#define PADK 40
#define NSTAGE 4
#define TILEB (128 * PADK * 2)          // 10240 bytes per tile
#define SMEM_DYN (2 * NSTAGE * TILEB)   // 81920 bytes

// ---------------- scratch ----------------
__device__ hf g_x1h[4096 * 1024];
__device__ hf g_x2h[8192 * 768];
__device__ hf g_w1h[3][1024 * 1024];   // transposed [N][K]
__device__ hf g_w2h[3][1024 * 768];

__device__ hf g_q1h[BB * SS1 * HD];
__device__ hf g_k1h[BB * SS1 * HD];
__device__ hf g_v1h[BB * SS1 * HD];
__device__ hf g_v1th[BB * HH * DD * SS1];
__device__ hf g_q2h[BB * SS2 * HD];
__device__ hf g_k2h[BB * SS2 * HD];
__device__ hf g_v2h[BB * SS2 * HD];
__device__ hf g_v2th[BB * HH * DD * SS2];

#define P_ELEMS ((size_t)BB * HH * SS2 * SS1)
__device__ float g_p1[P_ELEMS];
__device__ float g_p2[P_ELEMS];
__device__ hf g_p1h[P_ELEMS];
__device__ hf g_p2h[P_ELEMS];

// ---------------- helpers ----------------
__device__ __forceinline__ uint32_t smem_u32(const void* p) {
    uint32_t a;
    asm("{ .reg .u64 t; cvta.to.shared.u64 t, %1; cvt.u32.u64 %0, t; }"
        : "=r"(a) : "l"(p));
    return a;
}
__device__ __forceinline__ void cp16(uint32_t dst, const void* src) {
    asm volatile("cp.async.cg.shared.global [%0], [%1], 16;\n" :: "r"(dst), "l"(src));
}
__device__ __forceinline__ void ldsm_x4(uint32_t& r0, uint32_t& r1,
                                        uint32_t& r2, uint32_t& r3, uint32_t a) {
    asm volatile("ldmatrix.sync.aligned.m8n8.x4.shared.b16 {%0,%1,%2,%3}, [%4];"
                 : "=r"(r0), "=r"(r1), "=r"(r2), "=r"(r3) : "r"(a));
}
__device__ __forceinline__ void mma16816(float* c, uint32_t a0, uint32_t a1,
                                         uint32_t a2, uint32_t a3,
                                         uint32_t b0, uint32_t b1) {
    asm volatile(
        "mma.sync.aligned.m16n8k16.row.col.f32.f16.f16.f32 "
        "{%0,%1,%2,%3}, {%4,%5,%6,%7}, {%8,%9}, {%0,%1,%2,%3};"
        : "+f"(c[0]), "+f"(c[1]), "+f"(c[2]), "+f"(c[3])
        : "r"(a0), "r"(a1), "r"(a2), "r"(a3), "r"(b0), "r"(b1));
}
__device__ __forceinline__ uint32_t packhf(hf a, hf b) {
    __half2 t = __halves2half2(a, b);
    return *reinterpret_cast<uint32_t*>(&t);
}

// ---------------- convert kernels ----------------
__global__ void xcvt(const float4* __restrict__ x, uint2* __restrict__ h, int n4) {
    int i = blockIdx.x * blockDim.x + threadIdx.x;
    if (i >= n4) return;
    float4 v = x[i];
    uint2 hp;
    hp.x = packhf(__float2half(v.x), __float2half(v.y));
    hp.y = packhf(__float2half(v.z), __float2half(v.w));
    h[i] = hp;
}

struct WS {
    const float* W[6];
    hf* Wh[6];
    int K[6];
};

__global__ void wsplit_all(WS ws) {
    const int z = blockIdx.z;
    const int K = ws.K[z];
    const int N = 1024;
    const int k0 = blockIdx.y * 32, n0 = blockIdx.x * 32;
    if (k0 >= K) return;
    __shared__ float t[32][33];
    const float* W = ws.W[z];
    hf* Wh = ws.Wh[z];
    int tx = threadIdx.x, ty = threadIdx.y;
#pragma unroll
    for (int i = 0; i < 4; i++)
        t[ty + i * 8][tx] = W[(size_t)(k0 + ty + i * 8) * N + n0 + tx];
    __syncthreads();
#pragma unroll
    for (int i = 0; i < 4; i++) {
        float v = t[tx][ty + i * 8];
        size_t o = (size_t)(n0 + ty + i * 8) * K + k0 + tx;
        Wh[o] = __float2half(v);
    }
}

// merged V transpose: half [B,S,H,D] -> half [B,H,D,S], both streams
struct VTP {
    const hf* V[2];
    hf* Vt[2];
    int S[2];
};

__global__ void vtrans_all(VTP p) {
    const int part = blockIdx.z >> 7;
    const int bh = blockIdx.z & 127, b = bh >> 3, h = bh & 7;
    const int S = p.S[part];
    const int s0 = blockIdx.y * 32;
    if (s0 >= S) return;
    const int d0 = blockIdx.x * 32;
    __shared__ float t[32][33];
    const hf* V = p.V[part];
    hf* Vt = p.Vt[part];
    const int tx = threadIdx.x, ty = threadIdx.y;
#pragma unroll
    for (int i = 0; i < 4; i++)
        t[ty + i * 8][tx] = __half2float(
            V[(size_t)(b * S + s0 + ty + i * 8) * HD + h * DD + d0 + tx]);
    __syncthreads();
#pragma unroll
    for (int i = 0; i < 4; i++) {
        size_t o = ((size_t)bh * DD + d0 + ty + i * 8) * S + s0 + tx;
        Vt[o] = __float2half(t[tx][ty + i * 8]);
    }
}

// ===========================================================================
// 4-stage pipelined mainloop
// ===========================================================================

#define MAINLOOP(LOADBODY)                                                     \
    for (int s = 0; s < NSTAGE - 1; ++s) {                                     \
        if (s < C) { const int c_ = s; const int stg_ = s; LOADBODY }          \
        asm volatile("cp.async.commit_group;\n");                              \
    }                                                                          \
    for (int c = 0; c < C; ++c) {                                              \
        asm volatile("cp.async.wait_group %0;\n" :: "n"(NSTAGE - 2));          \
        __syncthreads();                                                       \
        const int buf = c & (NSTAGE - 1);                                      \
        const uint32_t sa = asb + buf * TILEB + a_lm;                          \
        const uint32_t sb2 = bsb + buf * TILEB + b_lm;                         \
        _Pragma("unroll")                                                      \
        for (int kk = 0; kk < 2; kk++) {                                       \
            uint32_t a[4][4], bbf[2][4];                                       \
            _Pragma("unroll")                                                  \
            for (int i = 0; i < 4; i++)                                        \
                ldsm_x4(a[i][0], a[i][1], a[i][2], a[i][3],                    \
                        sa + i * 16 * (PADK * 2) + kk * 32);                   \
            _Pragma("unroll")                                                  \
            for (int j2 = 0; j2 < 2; j2++)                                     \
                ldsm_x4(bbf[j2][0], bbf[j2][1], bbf[j2][2], bbf[j2][3],        \
                        sb2 + j2 * 16 * (PADK * 2) + kk * 32);                 \
            _Pragma("unroll")                                                  \
            for (int i = 0; i < 4; i++)                                        \
                _Pragma("unroll")                                              \
                for (int j = 0; j < 4; j++) {                                  \
                    int j2 = j >> 1, jo = j & 1;                               \
                    mma16816(acc[i][j], a[i][0], a[i][1], a[i][2], a[i][3],    \
                             bbf[j2][jo], bbf[j2][jo + 2]);                    \
                }                                                              \
        }                                                                      \
        if (c + NSTAGE - 1 < C) {                                              \
            const int c_ = c + NSTAGE - 1;                                     \
            const int stg_ = c_ & (NSTAGE - 1);                                \
            LOADBODY                                                           \
        }                                                                      \
        asm volatile("cp.async.commit_group;\n");                              \
    }

// ---------------------------------------------------------------------------
// QKV HMMA GEMM: BOTH streams, one launch. z in [0,6): z<3 stream1, else 2.
// Epilogue writes fp16 directly (bias add in fp32).
// ---------------------------------------------------------------------------
struct G6 {
    const hf* A[6];
    const hf* Wh[6];
    const float* bias[6];
    hf* out[6];
    int K[6];
    int M[6];
};

__global__ __launch_bounds__(256) void hmma_qkv_all(G6 g) {
    const int N = 1024;
    extern __shared__ __align__(128) char smem[];
    const uint32_t asb = smem_u32(smem);
    const uint32_t bsb = asb + NSTAGE * TILEB;

    const int z = blockIdx.z;
    const int bm = blockIdx.y * 128;
    if (bm >= g.M[z]) return;
    const int bn = blockIdx.x * 128;
    const int K = g.K[z];
    const int C = K / 32;

    const int tid = threadIdx.x;
    const int wid = tid >> 5, lane = tid & 31;
    const int wm = wid >> 2, wn = wid & 3;
    const hf* Ah = g.A[z];
    const hf* Wh = g.Wh[z];

    float acc[4][4][4];
#pragma unroll
    for (int i = 0; i < 4; i++)
#pragma unroll
        for (int j = 0; j < 4; j++)
#pragma unroll
            for (int r = 0; r < 4; r++) acc[i][j][r] = 0.f;

    const int r0 = tid >> 2, s0 = (tid & 3);
    const uint32_t a_lm = (uint32_t)((wm * 64 + (lane & 15)) * (PADK * 2) + (lane >> 4) * 16);
    const uint32_t b_lm = (uint32_t)((wn * 32 + (lane & 15)) * (PADK * 2) + (lane >> 4) * 16);

#define QKV_LOAD {                                                             \
        const int kc = c_;                                                     \
        const char* ab = (const char*)(Ah + (size_t)bm * K + kc * 32);         \
        const char* bb = (const char*)(Wh + (size_t)bn * K + kc * 32);         \
        const size_t rs = (size_t)K * 2;                                       \
        const uint32_t sa_ = asb + stg_ * TILEB;                               \
        const uint32_t sb_ = bsb + stg_ * TILEB;                               \
        _Pragma("unroll")                                                      \
        for (int u = 0; u < 2; u++) {                                          \
            int row = r0 + u * 64;                                             \
            uint32_t off = (uint32_t)(row * (PADK * 2) + s0 * 16);             \
            cp16(sa_ + off, ab + (size_t)row * rs + s0 * 16);                  \
            cp16(sb_ + off, bb + (size_t)row * rs + s0 * 16);                  \
        }                                                                      \
    }

    MAINLOOP(QKV_LOAD)

    hf* outp = g.out[z];
    const float* bias = g.bias[z];
#pragma unroll
    for (int i = 0; i < 4; i++) {
#pragma unroll
        for (int j = 0; j < 4; j++) {
            int m = bm + wm * 64 + i * 16 + (lane >> 2);
            int n = bn + wn * 32 + j * 8 + (lane & 3) * 2;
            float b0 = __ldg(bias + n), b1 = __ldg(bias + n + 1);
            *reinterpret_cast<uint32_t*>(outp + (size_t)m * N + n) =
                packhf(__float2half(acc[i][j][0] + b0), __float2half(acc[i][j][1] + b1));
            *reinterpret_cast<uint32_t*>(outp + (size_t)(m + 8) * N + n) =
                packhf(__float2half(acc[i][j][2] + b0), __float2half(acc[i][j][3] + b1));
        }
    }
}

// ---------------------------------------------------------------------------
// scores HMMA: both attention directions, one launch.
// ---------------------------------------------------------------------------
struct SCP {
    const hf* Qh[2];
    const hf* Kh[2];
    const float* mask[2];
    float* Sout[2];
    int Sq[2], Sk[2];
};

__global__ __launch_bounds__(256) void hmma_scores_all(SCP p, float scale) {
    extern __shared__ __align__(128) char smem[];
    const uint32_t asb = smem_u32(smem);
    const uint32_t bsb = asb + NSTAGE * TILEB;

    const int part = blockIdx.z >> 7;
    const int bh = blockIdx.z & 127, b = bh >> 3, h = bh & 7;
    const int Sq = p.Sq[part], Sk = p.Sk[part];
    const int bm = blockIdx.y * 128;
    if (bm >= Sq) return;
    const int bn = blockIdx.x * 128;
    if (bn >= Sk) return;
    const int C = 4;

    const int tid = threadIdx.x;
    const int wid = tid >> 5, lane = tid & 31;
    const int wm = wid >> 2, wn = wid & 3;
    const hf* Qh = p.Qh[part];
    const hf* Kh = p.Kh[part];

    float acc[4][4][4];
#pragma unroll
    for (int i = 0; i < 4; i++)
#pragma unroll
        for (int j = 0; j < 4; j++)
#pragma unroll
            for (int r = 0; r < 4; r++) acc[i][j][r] = 0.f;

    const int r0 = tid >> 2, s0 = (tid & 3);
    const uint32_t a_lm = (uint32_t)((wm * 64 + (lane & 15)) * (PADK * 2) + (lane >> 4) * 16);
    const uint32_t b_lm = (uint32_t)((wn * 32 + (lane & 15)) * (PADK * 2) + (lane >> 4) * 16);

#define SC_LOAD {                                                              \
        const int kc = c_;                                                     \
        const char* ab = (const char*)(Qh + (size_t)(b * Sq + bm) * HD + h * DD + kc * 32); \
        const char* bb = (const char*)(Kh + (size_t)(b * Sk + bn) * HD + h * DD + kc * 32); \
        const size_t rs = (size_t)HD * 2;                                      \
        const uint32_t sa_ = asb + stg_ * TILEB;                               \
        const uint32_t sb_ = bsb + stg_ * TILEB;                               \
        _Pragma("unroll")                                                      \
        for (int u = 0; u < 2; u++) {                                          \
            int row = r0 + u * 64;                                             \
            uint32_t off = (uint32_t)(row * (PADK * 2) + s0 * 16);             \
            cp16(sa_ + off, ab + (size_t)row * rs + s0 * 16);                  \
            cp16(sb_ + off, bb + (size_t)row * rs + s0 * 16);                  \
        }                                                                      \
    }

    MAINLOOP(SC_LOAD)

    float* Sout = p.Sout[part];
    const float* mask = p.mask[part];
#pragma unroll
    for (int i = 0; i < 4; i++) {
#pragma unroll
        for (int j = 0; j < 4; j++) {
            int m = bm + wm * 64 + i * 16 + (lane >> 2);
            int n = bn + wn * 32 + j * 8 + (lane & 3) * 2;
            float mk0 = __ldg(mask + b * Sk + n);
            float mk1 = __ldg(mask + b * Sk + n + 1);
            float2 v0 = make_float2(acc[i][j][0] * scale + mk0,
                                    acc[i][j][1] * scale + mk1);
            float2 v1 = make_float2(acc[i][j][2] * scale + mk0,
                                    acc[i][j][3] * scale + mk1);
            *reinterpret_cast<float2*>(Sout + ((size_t)bh * Sq + m) * Sk + n) = v0;
            *reinterpret_cast<float2*>(Sout + ((size_t)bh * Sq + m + 8) * Sk + n) = v1;
        }
    }
}

// ---------------------------------------------------------------------------
// softmax -> fp16 P, both parts in one launch
// ---------------------------------------------------------------------------
struct SMP {
    const float* S[2];
    hf* Ph[2];
    int rows0;   // rows in part 0
    int n[2];
};

__global__ __launch_bounds__(256) void softmax_all(SMP p, int rows_total) {
    int rg = (blockIdx.x * blockDim.x + threadIdx.x) >> 5;
    int lane = threadIdx.x & 31;
    if (rg >= rows_total) return;
    int part = (rg < p.rows0) ? 0 : 1;
    int row = (part == 0) ? rg : rg - p.rows0;
    const int n = p.n[part];
    const float2* r2 = reinterpret_cast<const float2*>(p.S[part] + (size_t)row * n);
    const int np = n >> 6;

    float v[16];
    float mx = -INFINITY;
#pragma unroll
    for (int c = 0; c < 8; c++) {
        if (c >= np) break;
        float2 t = r2[lane + c * 32];
        v[2 * c] = t.x; v[2 * c + 1] = t.y;
        mx = fmaxf(mx, fmaxf(t.x, t.y));
    }
#pragma unroll
    for (int o = 16; o; o >>= 1) mx = fmaxf(mx, __shfl_xor_sync(0xffffffffu, mx, o));

    float sum = 0.f;
#pragma unroll
    for (int c = 0; c < 8; c++) {
        if (c >= np) break;
        float e0 = __expf(v[2 * c] - mx);
        float e1 = __expf(v[2 * c + 1] - mx);
        v[2 * c] = e0; v[2 * c + 1] = e1;
        sum += e0 + e1;
    }
#pragma unroll
    for (int o = 16; o; o >>= 1) sum += __shfl_xor_sync(0xffffffffu, sum, o);
    float inv = 1.f / sum;

    uint32_t* ph32 = reinterpret_cast<uint32_t*>(p.Ph[part] + (size_t)row * n);
#pragma unroll
    for (int c = 0; c < 8; c++) {
        if (c >= np) break;
        ph32[lane + c * 32] = packhf(__float2half(v[2 * c] * inv),
                                     __float2half(v[2 * c + 1] * inv));
    }
}

// ---------------------------------------------------------------------------
// ctx HMMA: both directions, one launch
// ---------------------------------------------------------------------------
struct CXP {
    const hf* Ph[2];
    const hf* Vth[2];
    float* O[2];
    int Sq[2], Sk[2];
};

__global__ __launch_bounds__(256) void hmma_ctx_all(CXP p) {
    extern __shared__ __align__(128) char smem[];
    const uint32_t asb = smem_u32(smem);
    const uint32_t bsb = asb + NSTAGE * TILEB;

    const int part = blockIdx.z >> 7;
    const int bh = blockIdx.z & 127, b = bh >> 3, h = bh & 7;
    const int Sq = p.Sq[part], Sk = p.Sk[part];
    const int bm = blockIdx.y * 128;
    if (bm >= Sq) return;
    const int C = Sk / 32;

    const int tid = threadIdx.x;
    const int wid = tid >> 5, lane = tid & 31;
    const int wm = wid >> 2, wn = wid & 3;
    const hf* Ph = p.Ph[part];
    const hf* Vth = p.Vth[part];

    float acc[4][4][4];
#pragma unroll
    for (int i = 0; i < 4; i++)
#pragma unroll
        for (int j = 0; j < 4; j++)
#pragma unroll
            for (int r = 0; r < 4; r++) acc[i][j][r] = 0.f;

    const int r0 = tid >> 2, s0 = (tid & 3);
    const uint32_t a_lm = (uint32_t)((wm * 64 + (lane & 15)) * (PADK * 2) + (lane >> 4) * 16);
    const uint32_t b_lm = (uint32_t)((wn * 32 + (lane & 15)) * (PADK * 2) + (lane >> 4) * 16);

#define CTX_LOAD {                                                             \
        const int kc = c_;                                                     \
        const char* ab = (const char*)(Ph + ((size_t)bh * Sq + bm) * Sk + kc * 32); \
        const char* bb = (const char*)(Vth + (size_t)bh * DD * Sk + kc * 32);  \
        const size_t rs = (size_t)Sk * 2;                                      \
        const uint32_t sa_ = asb + stg_ * TILEB;                               \
        const uint32_t sb_ = bsb + stg_ * TILEB;                               \
        _Pragma("unroll")                                                      \
        for (int u = 0; u < 2; u++) {                                          \
            int row = r0 + u * 64;                                             \
            uint32_t off = (uint32_t)(row * (PADK * 2) + s0 * 16);             \
            cp16(sa_ + off, ab + (size_t)row * rs + s0 * 16);                  \
            cp16(sb_ + off, bb + (size_t)row * rs + s0 * 16);                  \
        }                                                                      \
    }

    MAINLOOP(CTX_LOAD)

    float* O = p.O[part];
#pragma unroll
    for (int i = 0; i < 4; i++) {
#pragma unroll
        for (int j = 0; j < 4; j++) {
            int m = bm + wm * 64 + i * 16 + (lane >> 2);
            int d = wn * 32 + j * 8 + (lane & 3) * 2;
            float2 v0 = make_float2(acc[i][j][0], acc[i][j][1]);
            float2 v1 = make_float2(acc[i][j][2], acc[i][j][3]);
            *reinterpret_cast<float2*>(
                O + ((size_t)(b * Sq + m) * HH + h) * DD + d) = v0;
            *reinterpret_cast<float2*>(
                O + ((size_t)(b * Sq + m + 8) * HH + h) * DD + d) = v1;
        }
    }
}

// ---------------------------------------------------------------------------
extern "C" void kernel_launch(void* const* d_in, const int* in_sizes, int n_in,
                              void* d_out, int out_size) {
    const float* x1    = (const float*)d_in[0];
    const float* mask1 = (const float*)d_in[1];
    const float* x2    = (const float*)d_in[2];
    const float* mask2 = (const float*)d_in[3];
    const float* W1[3] = {(const float*)d_in[4], (const float*)d_in[6], (const float*)d_in[8]};
    const float* b1[3] = {(const float*)d_in[5], (const float*)d_in[7], (const float*)d_in[9]};
    const float* W2[3] = {(const float*)d_in[10], (const float*)d_in[12], (const float*)d_in[14]};
    const float* b2[3] = {(const float*)d_in[11], (const float*)d_in[13], (const float*)d_in[15]};
    float* out = (float*)d_out;

    hf *x1h, *x2h, *w1h, *w2h;
    cudaGetSymbolAddress((void**)&x1h, g_x1h);
    cudaGetSymbolAddress((void**)&x2h, g_x2h);
    cudaGetSymbolAddress((void**)&w1h, g_w1h);
    cudaGetSymbolAddress((void**)&w2h, g_w2h);

    hf *q1h, *k1h, *v1h, *v1th, *q2h, *k2h, *v2h, *v2th;
    cudaGetSymbolAddress((void**)&q1h, g_q1h);
    cudaGetSymbolAddress((void**)&k1h, g_k1h);
    cudaGetSymbolAddress((void**)&v1h, g_v1h);
    cudaGetSymbolAddress((void**)&v1th, g_v1th);
    cudaGetSymbolAddress((void**)&q2h, g_q2h);
    cudaGetSymbolAddress((void**)&k2h, g_k2h);
    cudaGetSymbolAddress((void**)&v2h, g_v2h);
    cudaGetSymbolAddress((void**)&v2th, g_v2th);

    float *p1, *p2;
    hf *p1h, *p2h;
    cudaGetSymbolAddress((void**)&p1, g_p1);
    cudaGetSymbolAddress((void**)&p2, g_p2);
    cudaGetSymbolAddress((void**)&p1h, g_p1h);
    cudaGetSymbolAddress((void**)&p2h, g_p2h);

    cudaFuncSetAttribute(hmma_qkv_all, cudaFuncAttributeMaxDynamicSharedMemorySize, SMEM_DYN);
    cudaFuncSetAttribute(hmma_scores_all, cudaFuncAttributeMaxDynamicSharedMemorySize, SMEM_DYN);
    cudaFuncSetAttribute(hmma_ctx_all, cudaFuncAttributeMaxDynamicSharedMemorySize, SMEM_DYN);

    const float scale = 1.0f / sqrtf((float)DD);
    dim3 blk(256);

    // 1-2: input converts
    {
        int n4 = 4096 * 1024 / 4;
        xcvt<<<n4 / 256, 256>>>((const float4*)x1, (uint2*)x1h, n4);
    }
    {
        int n4 = 8192 * 768 / 4;
        xcvt<<<n4 / 256, 256>>>((const float4*)x2, (uint2*)x2h, n4);
    }
    // 3: weight converts (transposed)
    {
        WS ws;
        for (int i = 0; i < 3; i++) {
            ws.W[i] = W1[i];
            ws.Wh[i] = w1h + (size_t)i * 1024 * 1024;
            ws.K[i] = 1024;
            ws.W[3 + i] = W2[i];
            ws.Wh[3 + i] = w2h + (size_t)i * 1024 * 768;
            ws.K[3 + i] = 768;
        }
        wsplit_all<<<dim3(32, 32, 6), dim3(32, 8)>>>(ws);
    }

    // 4: all 6 QKV GEMMs, one launch, fp16 epilogue
    {
        G6 g;
        for (int i = 0; i < 3; i++) {
            g.A[i] = x1h;
            g.Wh[i] = w1h + (size_t)i * 1024 * 1024;
            g.bias[i] = b1[i];
            g.K[i] = 1024;
            g.M[i] = BB * SS1;
            g.A[3 + i] = x2h;
            g.Wh[3 + i] = w2h + (size_t)i * 1024 * 768;
            g.bias[3 + i] = b2[i];
            g.K[3 + i] = 768;
            g.M[3 + i] = BB * SS2;
        }
        g.out[0] = q1h; g.out[1] = k1h; g.out[2] = v1h;
        g.out[3] = q2h; g.out[4] = k2h; g.out[5] = v2h;
        hmma_qkv_all<<<dim3(8, 64, 6), blk, SMEM_DYN>>>(g);
    }

    // 5: merged V transposes
    {
        VTP p;
        p.V[0] = v1h; p.Vt[0] = v1th; p.S[0] = SS1;
        p.V[1] = v2h; p.Vt[1] = v2th; p.S[1] = SS2;
        vtrans_all<<<dim3(4, 16, 256), dim3(32, 8)>>>(p);
    }

    // 6: merged scores (both directions)
    {
        SCP p;
        p.Qh[0] = q2h; p.Kh[0] = k1h; p.mask[0] = mask1; p.Sout[0] = p1;
        p.Sq[0] = SS2; p.Sk[0] = SS1;
        p.Qh[1] = q1h; p.Kh[1] = k2h; p.mask[1] = mask2; p.Sout[1] = p2;
        p.Sq[1] = SS1; p.Sk[1] = SS2;
        hmma_scores_all<<<dim3(4, 4, 256), blk, SMEM_DYN>>>(p, scale);
    }

    // 7: merged softmax
    {
        SMP p;
        p.S[0] = p1; p.Ph[0] = p1h; p.n[0] = SS1;
        p.S[1] = p2; p.Ph[1] = p2h; p.n[1] = SS2;
        p.rows0 = BB * HH * SS2;
        int rows_total = BB * HH * SS2 + BB * HH * SS1;
        softmax_all<<<(rows_total + 7) / 8, blk>>>(p, rows_total);
    }

    // 8: merged context (both directions)
    {
        CXP p;
        p.Ph[0] = p1h; p.Vth[0] = v1th; p.O[0] = out;
        p.Sq[0] = SS2; p.Sk[0] = SS1;
        p.Ph[1] = p2h; p.Vth[1] = v2th; p.O[1] = out + C1_ELEMS;
        p.Sq[1] = SS1; p.Sk[1] = SS2;
        hmma_ctx_all<<<dim3(1, 4, 256), blk, SMEM_DYN>>>(p);
    }
}